// round 3
// baseline (speedup 1.0000x reference)
#include <cuda_runtime.h>
#include <math.h>

// ---------------------------------------------------------------------------
// Problem constants
// ---------------------------------------------------------------------------
#define SEQ    16
#define DIN    2048
#define DOUT   1128
#define NT     560          // C(16,3)
#define NSUP   5
#define NSEQ   6            // 5 support + 1 query
#define NROWS  96           // 6 seqs * 16 frames
#define NCOL   6768         // 2 (K,V) * 3 parts * 1128
#define KV_OFF 3384         // column offset of V part inside Y
#define LN_EPS 1e-5f

// ---------------------------------------------------------------------------
// Scratch (device globals -- no allocation allowed)
// ---------------------------------------------------------------------------
__device__ float g_X[NROWS * DIN];          // frames + positional encoding
__device__ float g_Y[NROWS * NCOL];         // per-frame projections (K parts | V parts)
__device__ float g_K[NSEQ * NT * DOUT];     // layernormed keys per tuple
__device__ float g_V[NSEQ * NT * DOUT];     // values per tuple
__device__ int   g_tup[NT * 3];             // tuple -> frame indices

// ---------------------------------------------------------------------------
// Kernel 0: build tuple table (combinations of 16 choose 3, lexicographic)
// ---------------------------------------------------------------------------
__global__ void init_tup_kernel() {
    if (threadIdx.x == 0) {
        int idx = 0;
        for (int i = 0; i < SEQ; i++)
            for (int j = i + 1; j < SEQ; j++)
                for (int k = j + 1; k < SEQ; k++) {
                    g_tup[idx * 3 + 0] = i;
                    g_tup[idx * 3 + 1] = j;
                    g_tup[idx * 3 + 2] = k;
                    idx++;
                }
    }
}

__global__ void zero_out_kernel(float* out) {
    if (threadIdx.x < NSUP) out[threadIdx.x] = 0.0f;
}

// ---------------------------------------------------------------------------
// Kernel 1: X = input + positional encoding.  One block per frame-row.
// rows 0..79 = support (n*16+f), rows 80..95 = query frames.
// ---------------------------------------------------------------------------
__global__ void build_x_kernel(const float* __restrict__ sup,
                               const float* __restrict__ qry) {
    int r   = blockIdx.x;
    int tid = threadIdx.x;
    int f   = (r < 80) ? (r & 15) : (r - 80);
    const float* src = (r < 80) ? (sup + r * DIN) : (qry + (r - 80) * DIN);
    const float cexp = -logf(10000.0f) / (float)DIN;
    for (int j = tid; j < DIN / 2; j += blockDim.x) {
        float div = expf((float)(2 * j) * cexp);
        float ang = (float)f * div;
        g_X[r * DIN + 2 * j]     = src[2 * j]     + 0.1f * sinf(ang);
        g_X[r * DIN + 2 * j + 1] = src[2 * j + 1] + 0.1f * cosf(ang);
    }
}

// ---------------------------------------------------------------------------
// Kernel 2: Y[96, 6768] = X[96, 2048] @ W^T
//   column cg < 3384 :  p = cg/1128, r = cg%1128 -> wk[r, p*2048 + k]
//   column cg >= 3384:  same with wv
// Block: computes all 96 rows x 64 columns.  256 threads, micro-tile 6x4.
// ---------------------------------------------------------------------------
#define PB_BK 64
__global__ void __launch_bounds__(256) proj_kernel(const float* __restrict__ wk,
                                                   const float* __restrict__ wv) {
    __shared__ float Xs[PB_BK][NROWS + 1];  // [kk][row], pad for banks
    __shared__ float Ws[PB_BK][64 + 1];     // [kk][col], pad for banks

    int tid  = threadIdx.x;
    int tx   = tid & 15;        // col group 0..15 (4 cols each)
    int ty   = tid >> 4;        // row group 0..15 (6 rows each)
    int col0 = blockIdx.x * 64;

    float acc[6][4];
#pragma unroll
    for (int i = 0; i < 6; i++)
#pragma unroll
        for (int j = 0; j < 4; j++) acc[i][j] = 0.0f;

    for (int k0 = 0; k0 < DIN; k0 += PB_BK) {
        // load X tile: 96*64 elements
#pragma unroll
        for (int l = 0; l < 24; l++) {
            int idx = tid + l * 256;
            int row = idx >> 6;
            int kk  = idx & 63;
            Xs[kk][row] = g_X[row * DIN + k0 + kk];
        }
        // load W tile: 64*64 elements
#pragma unroll
        for (int l = 0; l < 16; l++) {
            int idx = tid + l * 256;
            int cl  = idx >> 6;
            int kk  = idx & 63;
            int cg  = col0 + cl;
            float v = 0.0f;
            if (cg < NCOL) {
                const float* wp;
                int p, r;
                if (cg < KV_OFF) { p = cg / DOUT; r = cg - p * DOUT; wp = wk; }
                else             { int q = cg - KV_OFF; p = q / DOUT; r = q - p * DOUT; wp = wv; }
                v = wp[r * (3 * DIN) + p * DIN + k0 + kk];
            }
            Ws[kk][cl] = v;
        }
        __syncthreads();

#pragma unroll 4
        for (int kk = 0; kk < PB_BK; kk++) {
            float a[6], b[4];
#pragma unroll
            for (int i = 0; i < 6; i++) a[i] = Xs[kk][ty * 6 + i];
#pragma unroll
            for (int j = 0; j < 4; j++) b[j] = Ws[kk][tx * 4 + j];
#pragma unroll
            for (int i = 0; i < 6; i++)
#pragma unroll
                for (int j = 0; j < 4; j++) acc[i][j] += a[i] * b[j];
        }
        __syncthreads();
    }

#pragma unroll
    for (int i = 0; i < 6; i++) {
        int row = ty * 6 + i;
#pragma unroll
        for (int j = 0; j < 4; j++) {
            int cg = col0 + tx * 4 + j;
            if (cg < NCOL) g_Y[row * NCOL + cg] = acc[i][j];
        }
    }
}

// ---------------------------------------------------------------------------
// Kernel 3: assemble per-tuple K (layernorm) and V.
// grid (560, 6), 256 threads; each thread owns d = tid + 256*k, k<5.
// ---------------------------------------------------------------------------
__global__ void __launch_bounds__(256) assemble_kernel(const float* __restrict__ bk,
                                                       const float* __restrict__ bv,
                                                       const float* __restrict__ gamma,
                                                       const float* __restrict__ beta) {
    int t   = blockIdx.x;
    int n   = blockIdx.y;
    int tid = threadIdx.x;
    int lane = tid & 31, warp = tid >> 5;

    int i0 = g_tup[t * 3 + 0];
    int i1 = g_tup[t * 3 + 1];
    int i2 = g_tup[t * 3 + 2];
    const float* y0 = g_Y + (n * SEQ + i0) * NCOL;
    const float* y1 = g_Y + (n * SEQ + i1) * NCOL;
    const float* y2 = g_Y + (n * SEQ + i2) * NCOL;

    float kr[5];
    float s1 = 0.0f, s2 = 0.0f;
#pragma unroll
    for (int k = 0; k < 5; k++) {
        int d = tid + k * 256;
        if (k < 4 || tid < (DOUT - 1024)) {
            float v = y0[d] + y1[DOUT + d] + y2[2 * DOUT + d] + bk[d];
            kr[k] = v; s1 += v; s2 += v * v;
            float vv = y0[KV_OFF + d] + y1[KV_OFF + DOUT + d] + y2[KV_OFF + 2 * DOUT + d] + bv[d];
            g_V[(n * NT + t) * DOUT + d] = vv;
        } else kr[k] = 0.0f;
    }
    // block reduce (sum, sumsq)
    __shared__ float r1[8], r2[8];
    __shared__ float mu_s, rs_s;
#pragma unroll
    for (int o = 16; o; o >>= 1) {
        s1 += __shfl_xor_sync(0xffffffffu, s1, o);
        s2 += __shfl_xor_sync(0xffffffffu, s2, o);
    }
    if (lane == 0) { r1[warp] = s1; r2[warp] = s2; }
    __syncthreads();
    if (tid == 0) {
        float a = 0.0f, b = 0.0f;
        for (int w = 0; w < 8; w++) { a += r1[w]; b += r2[w]; }
        float mu = a / (float)DOUT;
        float var = b / (float)DOUT - mu * mu;
        mu_s = mu;
        rs_s = rsqrtf(var + LN_EPS);
    }
    __syncthreads();
    float mu = mu_s, rs = rs_s;
#pragma unroll
    for (int k = 0; k < 5; k++) {
        int d = tid + k * 256;
        if (k < 4 || tid < (DOUT - 1024))
            g_K[(n * NT + t) * DOUT + d] = (kr[k] - mu) * rs * gamma[d] + beta[d];
    }
}

// ---------------------------------------------------------------------------
// Kernel 4: attention + distance.
// grid (70, 5): block = (8 query tuples) x (class c).
// Phase 1: scores[8][560] = Kq_tile . Kc^T / sqrt(1128)
// Phase 2: row softmax
// Phase 3: proto = attn @ Vc, squared distance vs q_vs, atomic accumulate
// ---------------------------------------------------------------------------
#define TB 8
#define SKQ_STRIDE 1152                     // 1128 padded to 36*32
#define ATTN_SMEM ((TB * SKQ_STRIDE + TB * NT + 32) * 4)

__global__ void __launch_bounds__(256) attn_kernel(const int* __restrict__ labels,
                                                   float* __restrict__ out) {
    extern __shared__ float sm[];
    float* sKq  = sm;                       // TB * SKQ_STRIDE
    float* sS   = sm + TB * SKQ_STRIDE;     // TB * NT (scores -> attn)
    float* sRed = sS + TB * NT;             // 32

    int tid  = threadIdx.x;
    int lane = tid & 31, warp = tid >> 5;
    int c    = blockIdx.y;
    int t0   = blockIdx.x * TB;
    int lab  = labels[c];
    if (lab < 0)     lab = 0;               // defensive clamp (OOB-safe)
    if (lab >= NSUP) lab = NSUP - 1;

    const float* Kc = g_K + (size_t)lab * NT * DOUT;
    const float* Vc = g_V + (size_t)lab * NT * DOUT;
    const float* Kq = g_K + (size_t)NSUP * NT * DOUT;
    const float* Vq = g_V + (size_t)NSUP * NT * DOUT;

    // load 8 query-key rows into smem (zero-padded tail so padded reads are safe)
    for (int idx = tid; idx < TB * SKQ_STRIDE; idx += 256) {
        int t = idx / SKQ_STRIDE;
        int d = idx - t * SKQ_STRIDE;
        sKq[idx] = (d < DOUT) ? Kq[(t0 + t) * DOUT + d] : 0.0f;
    }
    __syncthreads();

    // ---- Phase 1: scores ----
    const float scale = rsqrtf((float)DOUT);
    for (int ch = warp; ch < NT / 4; ch += 8) {
        int s0 = ch * 4;
        float acc[TB][4];
#pragma unroll
        for (int t = 0; t < TB; t++)
#pragma unroll
            for (int j = 0; j < 4; j++) acc[t][j] = 0.0f;

#pragma unroll 4
        for (int dj = 0; dj < 36; dj++) {
            int d = lane + dj * 32;
            bool ok = d < DOUT;
            float kc0 = ok ? Kc[(s0 + 0) * DOUT + d] : 0.0f;
            float kc1 = ok ? Kc[(s0 + 1) * DOUT + d] : 0.0f;
            float kc2 = ok ? Kc[(s0 + 2) * DOUT + d] : 0.0f;
            float kc3 = ok ? Kc[(s0 + 3) * DOUT + d] : 0.0f;
#pragma unroll
            for (int t = 0; t < TB; t++) {
                float kq = sKq[t * SKQ_STRIDE + d];   // padded region is 0
                acc[t][0] += kq * kc0;
                acc[t][1] += kq * kc1;
                acc[t][2] += kq * kc2;
                acc[t][3] += kq * kc3;
            }
        }
#pragma unroll
        for (int t = 0; t < TB; t++)
#pragma unroll
            for (int j = 0; j < 4; j++) {
                float v = acc[t][j];
#pragma unroll
                for (int o = 16; o; o >>= 1) v += __shfl_xor_sync(0xffffffffu, v, o);
                if (lane == 0) sS[t * NT + s0 + j] = v * scale;
            }
    }
    __syncthreads();

    // ---- Phase 2: softmax over s (one warp per t-row) ----
    {
        int t = warp;   // 8 warps == TB rows
        float* row = sS + t * NT;
        float m = -1e30f;
        for (int s = lane; s < NT; s += 32) m = fmaxf(m, row[s]);
#pragma unroll
        for (int o = 16; o; o >>= 1) m = fmaxf(m, __shfl_xor_sync(0xffffffffu, m, o));
        float sum = 0.0f;
        for (int s = lane; s < NT; s += 32) {
            float e = expf(row[s] - m);
            row[s] = e;
            sum += e;
        }
#pragma unroll
        for (int o = 16; o; o >>= 1) sum += __shfl_xor_sync(0xffffffffu, sum, o);
        float inv = 1.0f / sum;
        for (int s = lane; s < NT; s += 32) row[s] *= inv;
    }
    __syncthreads();

    // ---- Phase 3: proto + distance ----
    float p[TB][5];
#pragma unroll
    for (int t = 0; t < TB; t++)
#pragma unroll
        for (int k = 0; k < 5; k++) p[t][k] = 0.0f;

    for (int s = 0; s < NT; s++) {
        float a[TB];
#pragma unroll
        for (int t = 0; t < TB; t++) a[t] = sS[t * NT + s];
#pragma unroll
        for (int k = 0; k < 5; k++) {
            int d = tid + k * 256;
            if (k < 4 || tid < (DOUT - 1024)) {
                float v = Vc[s * DOUT + d];
#pragma unroll
                for (int t = 0; t < TB; t++) p[t][k] += a[t] * v;
            }
        }
    }

    float loc = 0.0f;
#pragma unroll
    for (int t = 0; t < TB; t++) {
        int tg = t0 + t;
#pragma unroll
        for (int k = 0; k < 5; k++) {
            int d = tid + k * 256;
            if (k < 4 || tid < (DOUT - 1024)) {
                float qv = Vq[tg * DOUT + d];
                float df = qv - p[t][k];
                loc += df * df;
            }
        }
    }
#pragma unroll
    for (int o = 16; o; o >>= 1) loc += __shfl_xor_sync(0xffffffffu, loc, o);
    if (lane == 0) sRed[warp] = loc;
    __syncthreads();
    if (tid == 0) {
        float tot = 0.0f;
        for (int w = 0; w < 8; w++) tot += sRed[w];
        atomicAdd(out + c, -tot / (float)NT);
    }
}

// ---------------------------------------------------------------------------
// Launch
// ---------------------------------------------------------------------------
extern "C" void kernel_launch(void* const* d_in, const int* in_sizes, int n_in,
                              void* d_out, int out_size) {
    const float* sup   = (const float*)d_in[0];
    const float* qry   = (const float*)d_in[1];
    const int*   lab   = (const int*)d_in[2];     // JAX x64-disabled: int32
    const float* wk    = (const float*)d_in[3];
    const float* bk    = (const float*)d_in[4];
    const float* wv    = (const float*)d_in[5];
    const float* bv    = (const float*)d_in[6];
    const float* gamma = (const float*)d_in[7];
    const float* beta  = (const float*)d_in[8];
    float* out = (float*)d_out;

    cudaFuncSetAttribute((const void*)attn_kernel,
                         cudaFuncAttributeMaxDynamicSharedMemorySize, ATTN_SMEM);

    init_tup_kernel<<<1, 32>>>();
    build_x_kernel<<<NROWS, 256>>>(sup, qry);
    zero_out_kernel<<<1, 32>>>(out);
    proj_kernel<<<(NCOL + 63) / 64, 256>>>(wk, wv);
    assemble_kernel<<<dim3(NT, NSEQ), 256>>>(bk, bv, gamma, beta);
    attn_kernel<<<dim3(NT / TB, NSUP), 256, ATTN_SMEM>>>(lab, out);
}

// round 4
// speedup vs baseline: 1.9281x; 1.9281x over previous
#include <cuda_runtime.h>
#include <math.h>
#include <stdint.h>

// ---------------------------------------------------------------------------
// Problem constants
// ---------------------------------------------------------------------------
#define SEQ    16
#define DIN    2048
#define DOUT   1128
#define NT     560          // C(16,3)
#define NSUP   5
#define NSEQ   6            // 5 support + 1 query
#define NROWS  96           // 6 seqs * 16 frames
#define NCOL   6768         // 2 (K,V) * 3 parts * 1128
#define KV_OFF 3384
#define LN_EPS 1e-5f

// ---------------------------------------------------------------------------
// Scratch (device globals -- no allocation allowed)
// ---------------------------------------------------------------------------
__device__ float g_X[NROWS * DIN];            // frames + positional encoding
__device__ float g_Y[NROWS * NCOL];           // per-frame projections
__device__ float g_K[NSEQ * NT * DOUT];       // layernormed keys per tuple
__device__ float g_V[NSEQ * NT * DOUT];       // values per tuple
__device__ float g_S[NSUP * NT * NT];         // scores -> attn weights
__device__ int   g_tup[NT * 3];

// ---------------------------------------------------------------------------
// tf32 mma helpers
// ---------------------------------------------------------------------------
__device__ __forceinline__ uint32_t f2tf32(float x) {
    uint32_t r;
    asm("cvt.rna.tf32.f32 %0, %1;" : "=r"(r) : "f"(x));
    return r;
}

__device__ __forceinline__ void mma_tf32(float* c, const uint32_t* a, const uint32_t* b) {
    asm volatile(
        "mma.sync.aligned.m16n8k8.row.col.f32.tf32.tf32.f32 "
        "{%0,%1,%2,%3}, {%4,%5,%6,%7}, {%8,%9}, {%0,%1,%2,%3};\n"
        : "+f"(c[0]), "+f"(c[1]), "+f"(c[2]), "+f"(c[3])
        : "r"(a[0]), "r"(a[1]), "r"(a[2]), "r"(a[3]), "r"(b[0]), "r"(b[1]));
}

// ---------------------------------------------------------------------------
// Kernel 0: tuple table + output zero
// ---------------------------------------------------------------------------
__global__ void init_tup_kernel() {
    if (threadIdx.x == 0) {
        int idx = 0;
        for (int i = 0; i < SEQ; i++)
            for (int j = i + 1; j < SEQ; j++)
                for (int k = j + 1; k < SEQ; k++) {
                    g_tup[idx * 3 + 0] = i;
                    g_tup[idx * 3 + 1] = j;
                    g_tup[idx * 3 + 2] = k;
                    idx++;
                }
    }
}

__global__ void zero_out_kernel(float* out) {
    if (threadIdx.x < NSUP) out[threadIdx.x] = 0.0f;
}

// ---------------------------------------------------------------------------
// Kernel 1: X = input + positional encoding
// ---------------------------------------------------------------------------
__global__ void build_x_kernel(const float* __restrict__ sup,
                               const float* __restrict__ qry) {
    int r   = blockIdx.x;
    int tid = threadIdx.x;
    int f   = (r < 80) ? (r & 15) : (r - 80);
    const float* src = (r < 80) ? (sup + r * DIN) : (qry + (r - 80) * DIN);
    const float cexp = -logf(10000.0f) / (float)DIN;
    for (int j = tid; j < DIN / 2; j += blockDim.x) {
        float div = expf((float)(2 * j) * cexp);
        float ang = (float)f * div;
        g_X[r * DIN + 2 * j]     = src[2 * j]     + 0.1f * sinf(ang);
        g_X[r * DIN + 2 * j + 1] = src[2 * j + 1] + 0.1f * cosf(ang);
    }
}

// ---------------------------------------------------------------------------
// Kernel 2 (tf32 MMA): Y[96, 6768] = X[96,2048] @ W^T
// Block tile M=96 x N=32, 192 threads (6 warps, each m16 n32). grid 212.
// ---------------------------------------------------------------------------
__global__ void __launch_bounds__(192) proj_kernel(const float* __restrict__ wk,
                                                   const float* __restrict__ wv) {
    __shared__ uint32_t As[96][20];   // [m][k] tile, k-tile = 16, pad to 20
    __shared__ uint32_t Bs[32][20];   // [n][k] tile

    int tid  = threadIdx.x;
    int lane = tid & 31;
    int wid  = tid >> 5;              // 0..5 -> m block 16*wid
    int g    = lane >> 2;             // 0..7
    int tg   = lane & 3;              // 0..3
    int n0   = blockIdx.x * 32;

    float acc[4][4];
#pragma unroll
    for (int nr = 0; nr < 4; nr++)
#pragma unroll
        for (int e = 0; e < 4; e++) acc[nr][e] = 0.0f;

    for (int kt = 0; kt < DIN / 16; kt++) {
        int k0 = kt * 16;
        // A tile: 96 rows x 16 k -> 384 float4 loads over 192 threads (x2)
#pragma unroll
        for (int l = 0; l < 2; l++) {
            int idx = tid + l * 192;
            int r = idx >> 2, q = idx & 3;
            float4 f = *(const float4*)&g_X[r * DIN + k0 + 4 * q];
            uint4 u = { f2tf32(f.x), f2tf32(f.y), f2tf32(f.z), f2tf32(f.w) };
            *(uint4*)&As[r][4 * q] = u;
        }
        // B tile: 32 rows x 16 k -> 128 float4 loads
        if (tid < 128) {
            int r = tid >> 2, q = tid & 3;
            int cg = n0 + r;
            uint4 u = {0u, 0u, 0u, 0u};
            if (cg < NCOL) {
                const float* base;
                int p, rr;
                if (cg < KV_OFF) { p = cg / DOUT; rr = cg - p * DOUT; base = wk; }
                else             { int c2 = cg - KV_OFF; p = c2 / DOUT; rr = c2 - p * DOUT; base = wv; }
                float4 f = *(const float4*)&base[rr * (3 * DIN) + p * DIN + k0 + 4 * q];
                u.x = f2tf32(f.x); u.y = f2tf32(f.y); u.z = f2tf32(f.z); u.w = f2tf32(f.w);
            }
            *(uint4*)&Bs[r][4 * q] = u;
        }
        __syncthreads();

#pragma unroll
        for (int kk = 0; kk < 16; kk += 8) {
            uint32_t a[4];
            a[0] = As[wid * 16 + g][kk + tg];
            a[1] = As[wid * 16 + g + 8][kk + tg];
            a[2] = As[wid * 16 + g][kk + tg + 4];
            a[3] = As[wid * 16 + g + 8][kk + tg + 4];
#pragma unroll
            for (int nr = 0; nr < 4; nr++) {
                uint32_t b[2];
                b[0] = Bs[nr * 8 + g][kk + tg];
                b[1] = Bs[nr * 8 + g][kk + tg + 4];
                mma_tf32(acc[nr], a, b);
            }
        }
        __syncthreads();
    }

    // epilogue
#pragma unroll
    for (int nr = 0; nr < 4; nr++) {
#pragma unroll
        for (int e = 0; e < 4; e++) {
            int row = wid * 16 + g + ((e >= 2) ? 8 : 0);
            int cg  = n0 + nr * 8 + 2 * tg + (e & 1);
            if (cg < NCOL) g_Y[row * NCOL + cg] = acc[nr][e];
        }
    }
}

// ---------------------------------------------------------------------------
// Kernel 3: assemble per-tuple K (layernorm) and V.  grid (560, 6)
// ---------------------------------------------------------------------------
__global__ void __launch_bounds__(256) assemble_kernel(const float* __restrict__ bk,
                                                       const float* __restrict__ bv,
                                                       const float* __restrict__ gamma,
                                                       const float* __restrict__ beta) {
    int t   = blockIdx.x;
    int n   = blockIdx.y;
    int tid = threadIdx.x;
    int lane = tid & 31, warp = tid >> 5;

    int i0 = g_tup[t * 3 + 0];
    int i1 = g_tup[t * 3 + 1];
    int i2 = g_tup[t * 3 + 2];
    const float* y0 = g_Y + (n * SEQ + i0) * NCOL;
    const float* y1 = g_Y + (n * SEQ + i1) * NCOL;
    const float* y2 = g_Y + (n * SEQ + i2) * NCOL;

    float kr[5];
    float s1 = 0.0f, s2 = 0.0f;
#pragma unroll
    for (int k = 0; k < 5; k++) {
        int d = tid + k * 256;
        if (k < 4 || tid < (DOUT - 1024)) {
            float v = y0[d] + y1[DOUT + d] + y2[2 * DOUT + d] + bk[d];
            kr[k] = v; s1 += v; s2 += v * v;
            float vv = y0[KV_OFF + d] + y1[KV_OFF + DOUT + d] + y2[KV_OFF + 2 * DOUT + d] + bv[d];
            g_V[(n * NT + t) * DOUT + d] = vv;
        } else kr[k] = 0.0f;
    }
    __shared__ float r1[8], r2[8];
    __shared__ float mu_s, rs_s;
#pragma unroll
    for (int o = 16; o; o >>= 1) {
        s1 += __shfl_xor_sync(0xffffffffu, s1, o);
        s2 += __shfl_xor_sync(0xffffffffu, s2, o);
    }
    if (lane == 0) { r1[warp] = s1; r2[warp] = s2; }
    __syncthreads();
    if (tid == 0) {
        float a = 0.0f, b = 0.0f;
        for (int w = 0; w < 8; w++) { a += r1[w]; b += r2[w]; }
        float mu = a / (float)DOUT;
        float var = b / (float)DOUT - mu * mu;
        mu_s = mu;
        rs_s = rsqrtf(var + LN_EPS);
    }
    __syncthreads();
    float mu = mu_s, rs = rs_s;
#pragma unroll
    for (int k = 0; k < 5; k++) {
        int d = tid + k * 256;
        if (k < 4 || tid < (DOUT - 1024))
            g_K[(n * NT + t) * DOUT + d] = (kr[k] - mu) * rs * gamma[d] + beta[d];
    }
}

// ---------------------------------------------------------------------------
// Kernel 4 (tf32 MMA): S[c][t][s] = Kq[t,:] . Kc[s,:] * scale
// grid (9, 9, 5), block 256 (8 warps 4x2), tile 64x64, K = 1128 (71 k-tiles)
// ---------------------------------------------------------------------------
__global__ void __launch_bounds__(256) score_kernel(const int* __restrict__ labels) {
    __shared__ uint32_t As[64][20];   // [t][k]
    __shared__ uint32_t Bs[64][20];   // [s][k]

    int tid  = threadIdx.x;
    int lane = tid & 31;
    int wid  = tid >> 5;
    int wm   = wid & 3;               // 0..3
    int wn   = wid >> 2;              // 0..1
    int g    = lane >> 2;
    int tg   = lane & 3;

    int c  = blockIdx.z;
    int t0 = blockIdx.x * 64;
    int s0 = blockIdx.y * 64;
    int lab = labels[c];
    if (lab < 0) lab = 0; if (lab >= NSUP) lab = NSUP - 1;

    const float* Aq = g_K + (size_t)NSUP * NT * DOUT;   // query keys
    const float* Bc = g_K + (size_t)lab * NT * DOUT;    // class keys

    float acc[4][4];
#pragma unroll
    for (int nr = 0; nr < 4; nr++)
#pragma unroll
        for (int e = 0; e < 4; e++) acc[nr][e] = 0.0f;

    for (int kt = 0; kt < 71; kt++) {
        int k0 = kt * 16;
        {
            int r = tid >> 2, q = tid & 3;
            int d = k0 + 4 * q;
            uint4 ua = {0u, 0u, 0u, 0u}, ub = {0u, 0u, 0u, 0u};
            if (d < DOUT) {           // DOUT % 4 == 0, so whole float4 valid
                if (t0 + r < NT) {
                    float4 f = *(const float4*)&Aq[(size_t)(t0 + r) * DOUT + d];
                    ua.x = f2tf32(f.x); ua.y = f2tf32(f.y); ua.z = f2tf32(f.z); ua.w = f2tf32(f.w);
                }
                if (s0 + r < NT) {
                    float4 f = *(const float4*)&Bc[(size_t)(s0 + r) * DOUT + d];
                    ub.x = f2tf32(f.x); ub.y = f2tf32(f.y); ub.z = f2tf32(f.z); ub.w = f2tf32(f.w);
                }
            }
            *(uint4*)&As[r][4 * q] = ua;
            *(uint4*)&Bs[r][4 * q] = ub;
        }
        __syncthreads();

#pragma unroll
        for (int kk = 0; kk < 16; kk += 8) {
            uint32_t a[4];
            a[0] = As[wm * 16 + g][kk + tg];
            a[1] = As[wm * 16 + g + 8][kk + tg];
            a[2] = As[wm * 16 + g][kk + tg + 4];
            a[3] = As[wm * 16 + g + 8][kk + tg + 4];
#pragma unroll
            for (int nr = 0; nr < 4; nr++) {
                uint32_t b[2];
                b[0] = Bs[wn * 32 + nr * 8 + g][kk + tg];
                b[1] = Bs[wn * 32 + nr * 8 + g][kk + tg + 4];
                mma_tf32(acc[nr], a, b);
            }
        }
        __syncthreads();
    }

    const float scale = rsqrtf((float)DOUT);
    float* Sc = g_S + (size_t)c * NT * NT;
#pragma unroll
    for (int nr = 0; nr < 4; nr++) {
#pragma unroll
        for (int e = 0; e < 4; e++) {
            int t = t0 + wm * 16 + g + ((e >= 2) ? 8 : 0);
            int s = s0 + wn * 32 + nr * 8 + 2 * tg + (e & 1);
            if (t < NT && s < NT) Sc[(size_t)t * NT + s] = acc[nr][e] * scale;
        }
    }
}

// ---------------------------------------------------------------------------
// Kernel 5: row softmax over s. 2800 rows, one warp per row.
// ---------------------------------------------------------------------------
__global__ void __launch_bounds__(256) softmax_kernel() {
    int lane = threadIdx.x & 31;
    int row  = blockIdx.x * 8 + (threadIdx.x >> 5);
    if (row >= NSUP * NT) return;
    float* r = g_S + (size_t)row * NT;

    float m = -1e30f;
    for (int s = lane; s < NT; s += 32) m = fmaxf(m, r[s]);
#pragma unroll
    for (int o = 16; o; o >>= 1) m = fmaxf(m, __shfl_xor_sync(0xffffffffu, m, o));
    float sum = 0.0f;
    for (int s = lane; s < NT; s += 32) {
        float e = expf(r[s] - m);
        r[s] = e;
        sum += e;
    }
#pragma unroll
    for (int o = 16; o; o >>= 1) sum += __shfl_xor_sync(0xffffffffu, sum, o);
    float inv = 1.0f / sum;
    for (int s = lane; s < NT; s += 32) r[s] *= inv;
}

// ---------------------------------------------------------------------------
// Kernel 6 (tf32 MMA): P[t,d] = attn[t,:] @ Vc[:,d]; accumulate (q_v - P)^2.
// grid (9, 18, 5), block 256 (8 warps 4x2), tile 64(t) x 64(d), K = 560 exact.
// ---------------------------------------------------------------------------
__global__ void __launch_bounds__(256) dist_kernel(const int* __restrict__ labels,
                                                   float* __restrict__ out) {
    __shared__ uint32_t As[64][20];   // [t][k=s]
    __shared__ uint32_t Bs[16][72];   // [k=s][n=d]
    __shared__ float red[8];

    int tid  = threadIdx.x;
    int lane = tid & 31;
    int wid  = tid >> 5;
    int wm   = wid & 3;
    int wn   = wid >> 2;
    int g    = lane >> 2;
    int tg   = lane & 3;

    int c  = blockIdx.z;
    int t0 = blockIdx.x * 64;
    int d0 = blockIdx.y * 64;
    int lab = labels[c];
    if (lab < 0) lab = 0; if (lab >= NSUP) lab = NSUP - 1;

    const float* Ag = g_S + (size_t)c * NT * NT;        // attn [t][s]
    const float* Vc = g_V + (size_t)lab * NT * DOUT;    // class values [s][d]
    const float* Vq = g_V + (size_t)NSUP * NT * DOUT;   // query values [t][d]

    float acc[4][4];
#pragma unroll
    for (int nr = 0; nr < 4; nr++)
#pragma unroll
        for (int e = 0; e < 4; e++) acc[nr][e] = 0.0f;

    for (int kt = 0; kt < NT / 16; kt++) {   // 35 k-tiles, exact
        int k0 = kt * 16;
        {   // A: 64 t-rows x 16 s
            int r = tid >> 2, q = tid & 3;
            uint4 ua = {0u, 0u, 0u, 0u};
            if (t0 + r < NT) {
                float4 f = *(const float4*)&Ag[(size_t)(t0 + r) * NT + k0 + 4 * q];
                ua.x = f2tf32(f.x); ua.y = f2tf32(f.y); ua.z = f2tf32(f.z); ua.w = f2tf32(f.w);
            }
            *(uint4*)&As[r][4 * q] = ua;
        }
        {   // B: 16 s-rows x 64 d
            int r = tid >> 4, q = tid & 15;
            int d = d0 + 4 * q;
            uint4 ub = {0u, 0u, 0u, 0u};
            if (d < DOUT) {          // DOUT % 4 == 0
                float4 f = *(const float4*)&Vc[(size_t)(k0 + r) * DOUT + d];
                ub.x = f2tf32(f.x); ub.y = f2tf32(f.y); ub.z = f2tf32(f.z); ub.w = f2tf32(f.w);
            }
            *(uint4*)&Bs[r][4 * q] = ub;
        }
        __syncthreads();

#pragma unroll
        for (int kk = 0; kk < 16; kk += 8) {
            uint32_t a[4];
            a[0] = As[wm * 16 + g][kk + tg];
            a[1] = As[wm * 16 + g + 8][kk + tg];
            a[2] = As[wm * 16 + g][kk + tg + 4];
            a[3] = As[wm * 16 + g + 8][kk + tg + 4];
#pragma unroll
            for (int nr = 0; nr < 4; nr++) {
                uint32_t b[2];
                b[0] = Bs[kk + tg][wn * 32 + nr * 8 + g];
                b[1] = Bs[kk + tg + 4][wn * 32 + nr * 8 + g];
                mma_tf32(acc[nr], a, b);
            }
        }
        __syncthreads();
    }

    // epilogue: squared distance vs query values
    float loc = 0.0f;
#pragma unroll
    for (int nr = 0; nr < 4; nr++) {
#pragma unroll
        for (int e = 0; e < 4; e++) {
            int t = t0 + wm * 16 + g + ((e >= 2) ? 8 : 0);
            int d = d0 + wn * 32 + nr * 8 + 2 * tg + (e & 1);
            if (t < NT && d < DOUT) {
                float diff = Vq[(size_t)t * DOUT + d] - acc[nr][e];
                loc += diff * diff;
            }
        }
    }
#pragma unroll
    for (int o = 16; o; o >>= 1) loc += __shfl_xor_sync(0xffffffffu, loc, o);
    if (lane == 0) red[wid] = loc;
    __syncthreads();
    if (tid == 0) {
        float tot = 0.0f;
        for (int w = 0; w < 8; w++) tot += red[w];
        atomicAdd(out + c, -tot / (float)NT);
    }
}

// ---------------------------------------------------------------------------
// Launch
// ---------------------------------------------------------------------------
extern "C" void kernel_launch(void* const* d_in, const int* in_sizes, int n_in,
                              void* d_out, int out_size) {
    const float* sup   = (const float*)d_in[0];
    const float* qry   = (const float*)d_in[1];
    const int*   lab   = (const int*)d_in[2];
    const float* wk    = (const float*)d_in[3];
    const float* bk    = (const float*)d_in[4];
    const float* wv    = (const float*)d_in[5];
    const float* bv    = (const float*)d_in[6];
    const float* gamma = (const float*)d_in[7];
    const float* beta  = (const float*)d_in[8];
    float* out = (float*)d_out;

    init_tup_kernel<<<1, 32>>>();
    build_x_kernel<<<NROWS, 256>>>(sup, qry);
    zero_out_kernel<<<1, 32>>>(out);
    proj_kernel<<<(NCOL + 31) / 32, 192>>>(wk, wv);                  // 212 blocks
    assemble_kernel<<<dim3(NT, NSEQ), 256>>>(bk, bv, gamma, beta);
    score_kernel<<<dim3(9, 9, NSUP), 256>>>(lab);
    softmax_kernel<<<(NSUP * NT + 7) / 8, 256>>>();
    dist_kernel<<<dim3(9, 18, NSUP), 256>>>(lab, out);
}

// round 6
// speedup vs baseline: 2.9039x; 1.5061x over previous
#include <cuda_runtime.h>
#include <math.h>
#include <stdint.h>

// ---------------------------------------------------------------------------
// Problem constants
// ---------------------------------------------------------------------------
#define SEQ    16
#define DIN    2048
#define DOUT   1128
#define NT     560          // C(16,3)
#define NSUP   5
#define NSEQ   6            // 5 support + 1 query
#define NROWS  96           // 6 seqs * 16 frames
#define NCOL   6768         // 2 (K,V) * 3 parts * 1128
#define KV_OFF 3384
#define LN_EPS 1e-5f

// ---------------------------------------------------------------------------
// Scratch (device globals -- no allocation allowed)
// ---------------------------------------------------------------------------
__device__ float g_X[NROWS * DIN];
__device__ float g_Y[NROWS * NCOL];
__device__ float g_K[NSEQ * NT * DOUT];
__device__ float g_V[NSEQ * NT * DOUT];
__device__ float g_S[NSUP * NT * NT];
__device__ int   g_tup[NT * 3];

// ---------------------------------------------------------------------------
// helpers: tf32 mma + round-to-nearest fragment load + cp.async
// ---------------------------------------------------------------------------
__device__ __forceinline__ void mma_tf32(float* c, const uint32_t* a, const uint32_t* b) {
    asm volatile(
        "mma.sync.aligned.m16n8k8.row.col.f32.tf32.tf32.f32 "
        "{%0,%1,%2,%3}, {%4,%5,%6,%7}, {%8,%9}, {%0,%1,%2,%3};\n"
        : "+f"(c[0]), "+f"(c[1]), "+f"(c[2]), "+f"(c[3])
        : "r"(a[0]), "r"(a[1]), "r"(a[2]), "r"(a[3]), "r"(b[0]), "r"(b[1]));
}

// load fp32 word from smem and round-to-nearest into tf32 (restores R4 numerics)
__device__ __forceinline__ uint32_t ldcvt(const uint32_t* p) {
    float f = __uint_as_float(*p);
    uint32_t r;
    asm("cvt.rna.tf32.f32 %0, %1;" : "=r"(r) : "f"(f));
    return r;
}

__device__ __forceinline__ void cp16(uint32_t saddr, const float* g, bool p) {
    asm volatile("cp.async.cg.shared.global [%0], [%1], 16, %2;"
                 :: "r"(saddr), "l"(g), "r"(p ? 16 : 0));
}
#define CP_COMMIT()  asm volatile("cp.async.commit_group;")
#define CP_WAIT1()   asm volatile("cp.async.wait_group 1;")
#define CP_WAIT0()   asm volatile("cp.async.wait_group 0;")

// ---------------------------------------------------------------------------
// Kernel 0: tuple table + zero output
// ---------------------------------------------------------------------------
__global__ void init_tup_kernel() {
    if (threadIdx.x == 0) {
        int idx = 0;
        for (int i = 0; i < SEQ; i++)
            for (int j = i + 1; j < SEQ; j++)
                for (int k = j + 1; k < SEQ; k++) {
                    g_tup[idx * 3 + 0] = i;
                    g_tup[idx * 3 + 1] = j;
                    g_tup[idx * 3 + 2] = k;
                    idx++;
                }
    }
}

__global__ void zero_out_kernel(float* out) {
    if (threadIdx.x < NSUP) out[threadIdx.x] = 0.0f;
}

// ---------------------------------------------------------------------------
// Kernel 1: X = input + positional encoding
// ---------------------------------------------------------------------------
__global__ void build_x_kernel(const float* __restrict__ sup,
                               const float* __restrict__ qry) {
    int r   = blockIdx.x;
    int tid = threadIdx.x;
    int f   = (r < 80) ? (r & 15) : (r - 80);
    const float* src = (r < 80) ? (sup + r * DIN) : (qry + (r - 80) * DIN);
    const float cexp = -logf(10000.0f) / (float)DIN;
    for (int j = tid; j < DIN / 2; j += blockDim.x) {
        float div = expf((float)(2 * j) * cexp);
        float ang = (float)f * div;
        g_X[r * DIN + 2 * j]     = src[2 * j]     + 0.1f * sinf(ang);
        g_X[r * DIN + 2 * j + 1] = src[2 * j + 1] + 0.1f * cosf(ang);
    }
}

// ---------------------------------------------------------------------------
// Kernel 2: Y[96,6768] = X[96,2048] @ W^T.  tile 96x32, BK=32, 2-stage cp.async
// 192 threads = 6 warps, each m16 x n32.
// ---------------------------------------------------------------------------
#define PRJ_STAGE_F 4608   // floats per stage
__global__ void __launch_bounds__(192) proj_kernel(const float* __restrict__ wk,
                                                   const float* __restrict__ wv) {
    __shared__ float smem[2 * PRJ_STAGE_F];
    uint32_t sbase = (uint32_t)__cvta_generic_to_shared(smem);
    const uint32_t* S = (const uint32_t*)smem;

    int tid  = threadIdx.x;
    int lane = tid & 31;
    int wid  = tid >> 5;
    int g    = lane >> 2;
    int tg   = lane & 3;
    int n0   = blockIdx.x * 32;

    // slot precompute: 1024 float4 per stage (A 768 + B 256), 6 slots/thread
    const float* gb[6]; uint32_t so[6]; bool ex[6]; bool sok[6];
#pragma unroll
    for (int l = 0; l < 6; l++) {
        int idx = tid + l * 192;
        ex[l] = idx < 1024;
        gb[l] = g_X; so[l] = 0; sok[l] = false;
        if (!ex[l]) continue;
        if (idx < 768) {                       // A region
            int r = idx >> 3, q = idx & 7;
            gb[l]  = g_X + r * DIN + 4 * q;
            so[l]  = r * 144 + q * 16;
            sok[l] = true;
        } else {                               // B region
            int j = idx - 768;
            int r = j >> 3, q = j & 7;
            int cg = n0 + r;
            so[l] = 13824 + r * 144 + q * 16;
            if (cg < NCOL) {
                const float* base; int p, rr;
                if (cg < KV_OFF) { p = cg / DOUT; rr = cg - p * DOUT; base = wk; }
                else             { int c2 = cg - KV_OFF; p = c2 / DOUT; rr = c2 - p * DOUT; base = wv; }
                gb[l]  = base + rr * (3 * DIN) + p * DIN + 4 * q;
                sok[l] = true;
            }
        }
    }

    float acc[4][4];
#pragma unroll
    for (int nr = 0; nr < 4; nr++)
#pragma unroll
        for (int e = 0; e < 4; e++) acc[nr][e] = 0.0f;

    const int NKT = DIN / 32;   // 64
#pragma unroll
    for (int l = 0; l < 6; l++)
        if (ex[l]) cp16(sbase + so[l], gb[l], sok[l]);
    CP_COMMIT();

    for (int kt = 0; kt < NKT; kt++) {
        int buf = kt & 1;
        if (kt + 1 < NKT) {
            int k0 = (kt + 1) * 32;
            uint32_t boff = (buf ^ 1) * (PRJ_STAGE_F * 4);
#pragma unroll
            for (int l = 0; l < 6; l++)
                if (ex[l]) cp16(sbase + boff + so[l], gb[l] + k0, sok[l]);
            CP_COMMIT();
            CP_WAIT1();
        } else {
            CP_WAIT0();
        }
        __syncthreads();

        const uint32_t* As = S + buf * PRJ_STAGE_F;
        const uint32_t* Bs = As + 3456;        // 96*36
#pragma unroll
        for (int kk = 0; kk < 32; kk += 8) {
            uint32_t a[4];
            a[0] = ldcvt(&As[(wid * 16 + g)     * 36 + kk + tg]);
            a[1] = ldcvt(&As[(wid * 16 + g + 8) * 36 + kk + tg]);
            a[2] = ldcvt(&As[(wid * 16 + g)     * 36 + kk + tg + 4]);
            a[3] = ldcvt(&As[(wid * 16 + g + 8) * 36 + kk + tg + 4]);
#pragma unroll
            for (int nr = 0; nr < 4; nr++) {
                uint32_t b[2];
                b[0] = ldcvt(&Bs[(nr * 8 + g) * 36 + kk + tg]);
                b[1] = ldcvt(&Bs[(nr * 8 + g) * 36 + kk + tg + 4]);
                mma_tf32(acc[nr], a, b);
            }
        }
        __syncthreads();
    }

#pragma unroll
    for (int nr = 0; nr < 4; nr++)
#pragma unroll
        for (int e = 0; e < 4; e++) {
            int row = wid * 16 + g + ((e >= 2) ? 8 : 0);
            int cg  = n0 + nr * 8 + 2 * tg + (e & 1);
            if (cg < NCOL) g_Y[row * NCOL + cg] = acc[nr][e];
        }
}

// ---------------------------------------------------------------------------
// Kernel 3: assemble per-tuple K (layernorm) and V.  grid (560, 6)
// ---------------------------------------------------------------------------
__global__ void __launch_bounds__(256) assemble_kernel(const float* __restrict__ bk,
                                                       const float* __restrict__ bv,
                                                       const float* __restrict__ gamma,
                                                       const float* __restrict__ beta) {
    int t   = blockIdx.x;
    int n   = blockIdx.y;
    int tid = threadIdx.x;
    int lane = tid & 31, warp = tid >> 5;

    int i0 = g_tup[t * 3 + 0];
    int i1 = g_tup[t * 3 + 1];
    int i2 = g_tup[t * 3 + 2];
    const float* y0 = g_Y + (n * SEQ + i0) * NCOL;
    const float* y1 = g_Y + (n * SEQ + i1) * NCOL;
    const float* y2 = g_Y + (n * SEQ + i2) * NCOL;

    float kr[5];
    float s1 = 0.0f, s2 = 0.0f;
#pragma unroll
    for (int k = 0; k < 5; k++) {
        int d = tid + k * 256;
        if (k < 4 || tid < (DOUT - 1024)) {
            float v = y0[d] + y1[DOUT + d] + y2[2 * DOUT + d] + bk[d];
            kr[k] = v; s1 += v; s2 += v * v;
            float vv = y0[KV_OFF + d] + y1[KV_OFF + DOUT + d] + y2[KV_OFF + 2 * DOUT + d] + bv[d];
            g_V[(n * NT + t) * DOUT + d] = vv;
        } else kr[k] = 0.0f;
    }
    __shared__ float r1[8], r2[8];
    __shared__ float mu_s, rs_s;
#pragma unroll
    for (int o = 16; o; o >>= 1) {
        s1 += __shfl_xor_sync(0xffffffffu, s1, o);
        s2 += __shfl_xor_sync(0xffffffffu, s2, o);
    }
    if (lane == 0) { r1[warp] = s1; r2[warp] = s2; }
    __syncthreads();
    if (tid == 0) {
        float a = 0.0f, b = 0.0f;
        for (int w = 0; w < 8; w++) { a += r1[w]; b += r2[w]; }
        float mu = a / (float)DOUT;
        float var = b / (float)DOUT - mu * mu;
        mu_s = mu;
        rs_s = rsqrtf(var + LN_EPS);
    }
    __syncthreads();
    float mu = mu_s, rs = rs_s;
#pragma unroll
    for (int k = 0; k < 5; k++) {
        int d = tid + k * 256;
        if (k < 4 || tid < (DOUT - 1024))
            g_K[(n * NT + t) * DOUT + d] = (kr[k] - mu) * rs * gamma[d] + beta[d];
    }
}

// ---------------------------------------------------------------------------
// Kernel 4: S[c][t][s] = Kq[t,:].Kc[s,:] * scale.  tile 64x64, BK=32, 2-stage.
// ---------------------------------------------------------------------------
#define SCR_STAGE_F 4608
__global__ void __launch_bounds__(256) score_kernel(const int* __restrict__ labels) {
    __shared__ float smem[2 * SCR_STAGE_F];
    uint32_t sbase = (uint32_t)__cvta_generic_to_shared(smem);
    const uint32_t* S = (const uint32_t*)smem;

    int tid  = threadIdx.x;
    int lane = tid & 31;
    int wid  = tid >> 5;
    int wm   = wid & 3;
    int wn   = wid >> 2;
    int g    = lane >> 2;
    int tg   = lane & 3;

    int c  = blockIdx.z;
    int t0 = blockIdx.x * 64;
    int s0 = blockIdx.y * 64;
    int lab = labels[c];
    if (lab < 0) lab = 0; if (lab >= NSUP) lab = NSUP - 1;

    const float* Aq = g_K + (size_t)NSUP * NT * DOUT;
    const float* Bc = g_K + (size_t)lab * NT * DOUT;

    const float* gb[4]; uint32_t so[4]; int kthr[4]; bool sok[4];
#pragma unroll
    for (int l = 0; l < 4; l++) {
        int idx = tid + l * 256;
        if (idx < 512) {
            int r = idx >> 3, q = idx & 7;
            int row = t0 + r;
            sok[l]  = row < NT;
            gb[l]   = Aq + (size_t)(sok[l] ? row : 0) * DOUT + 4 * q;
            so[l]   = r * 144 + q * 16;
            kthr[l] = DOUT - 4 * q;
        } else {
            int j = idx - 512;
            int r = j >> 3, q = j & 7;
            int row = s0 + r;
            sok[l]  = row < NT;
            gb[l]   = Bc + (size_t)(sok[l] ? row : 0) * DOUT + 4 * q;
            so[l]   = 9216 + r * 144 + q * 16;
            kthr[l] = DOUT - 4 * q;
        }
    }

    float acc[4][4];
#pragma unroll
    for (int nr = 0; nr < 4; nr++)
#pragma unroll
        for (int e = 0; e < 4; e++) acc[nr][e] = 0.0f;

    const int NKT = (DOUT + 31) / 32;   // 36
#pragma unroll
    for (int l = 0; l < 4; l++)
        cp16(sbase + so[l], gb[l], sok[l] && (0 < kthr[l]));
    CP_COMMIT();

    for (int kt = 0; kt < NKT; kt++) {
        int buf = kt & 1;
        if (kt + 1 < NKT) {
            int k0 = (kt + 1) * 32;
            uint32_t boff = (buf ^ 1) * (SCR_STAGE_F * 4);
#pragma unroll
            for (int l = 0; l < 4; l++)
                cp16(sbase + boff + so[l], gb[l] + k0, sok[l] && (k0 < kthr[l]));
            CP_COMMIT();
            CP_WAIT1();
        } else {
            CP_WAIT0();
        }
        __syncthreads();

        const uint32_t* As = S + buf * SCR_STAGE_F;
        const uint32_t* Bs = As + 2304;   // 64*36
#pragma unroll
        for (int kk = 0; kk < 32; kk += 8) {
            uint32_t a[4];
            a[0] = ldcvt(&As[(wm * 16 + g)     * 36 + kk + tg]);
            a[1] = ldcvt(&As[(wm * 16 + g + 8) * 36 + kk + tg]);
            a[2] = ldcvt(&As[(wm * 16 + g)     * 36 + kk + tg + 4]);
            a[3] = ldcvt(&As[(wm * 16 + g + 8) * 36 + kk + tg + 4]);
#pragma unroll
            for (int nr = 0; nr < 4; nr++) {
                uint32_t b[2];
                b[0] = ldcvt(&Bs[(wn * 32 + nr * 8 + g) * 36 + kk + tg]);
                b[1] = ldcvt(&Bs[(wn * 32 + nr * 8 + g) * 36 + kk + tg + 4]);
                mma_tf32(acc[nr], a, b);
            }
        }
        __syncthreads();
    }

    const float scale = rsqrtf((float)DOUT);
    float* Sc = g_S + (size_t)c * NT * NT;
#pragma unroll
    for (int nr = 0; nr < 4; nr++)
#pragma unroll
        for (int e = 0; e < 4; e++) {
            int t = t0 + wm * 16 + g + ((e >= 2) ? 8 : 0);
            int s = s0 + wn * 32 + nr * 8 + 2 * tg + (e & 1);
            if (t < NT && s < NT) Sc[(size_t)t * NT + s] = acc[nr][e] * scale;
        }
}

// ---------------------------------------------------------------------------
// Kernel 5: row softmax over s.  one warp per row.
// ---------------------------------------------------------------------------
__global__ void __launch_bounds__(256) softmax_kernel() {
    int lane = threadIdx.x & 31;
    int row  = blockIdx.x * 8 + (threadIdx.x >> 5);
    if (row >= NSUP * NT) return;
    float* r = g_S + (size_t)row * NT;

    float m = -1e30f;
    for (int s = lane; s < NT; s += 32) m = fmaxf(m, r[s]);
#pragma unroll
    for (int o = 16; o; o >>= 1) m = fmaxf(m, __shfl_xor_sync(0xffffffffu, m, o));
    float sum = 0.0f;
    for (int s = lane; s < NT; s += 32) {
        float e = expf(r[s] - m);
        r[s] = e;
        sum += e;
    }
#pragma unroll
    for (int o = 16; o; o >>= 1) sum += __shfl_xor_sync(0xffffffffu, sum, o);
    float inv = 1.0f / sum;
    for (int s = lane; s < NT; s += 32) r[s] *= inv;
}

// ---------------------------------------------------------------------------
// Kernel 6: P = attn @ Vc, accumulate (q_v - P)^2.  tile 64(t) x 64(d),
// BK=32 over s (18 tiles), 2-stage cp.async.
// ---------------------------------------------------------------------------
#define DST_STAGE_F 4608
__global__ void __launch_bounds__(256) dist_kernel(const int* __restrict__ labels,
                                                   float* __restrict__ out) {
    __shared__ float smem[2 * DST_STAGE_F];
    __shared__ float red[8];
    uint32_t sbase = (uint32_t)__cvta_generic_to_shared(smem);
    const uint32_t* S = (const uint32_t*)smem;

    int tid  = threadIdx.x;
    int lane = tid & 31;
    int wid  = tid >> 5;
    int wm   = wid & 3;
    int wn   = wid >> 2;
    int g    = lane >> 2;
    int tg   = lane & 3;

    int c  = blockIdx.z;
    int t0 = blockIdx.x * 64;
    int d0 = blockIdx.y * 64;
    int lab = labels[c];
    if (lab < 0) lab = 0; if (lab >= NSUP) lab = NSUP - 1;

    const float* Ag = g_S + (size_t)c * NT * NT;
    const float* Vc = g_V + (size_t)lab * NT * DOUT;
    const float* Vq = g_V + (size_t)NSUP * NT * DOUT;

    const float* gb[4]; uint32_t so[4]; int gstep[4]; int kthr[4]; bool sok[4];
#pragma unroll
    for (int l = 0; l < 4; l++) {
        int idx = tid + l * 256;
        if (idx < 512) {
            int r = idx >> 3, q = idx & 7;
            int row = t0 + r;
            sok[l]   = row < NT;
            gb[l]    = Ag + (size_t)(sok[l] ? row : 0) * NT + 4 * q;
            so[l]    = r * 144 + q * 16;
            gstep[l] = 1;
            kthr[l]  = NT - 4 * q;
        } else {
            int j = idx - 512;
            int r = j >> 4, q = j & 15;
            int d = d0 + 4 * q;
            sok[l]   = d < DOUT;
            gb[l]    = Vc + (size_t)r * DOUT + (sok[l] ? d : 0);
            so[l]    = 9216 + r * 288 + q * 16;
            gstep[l] = DOUT;
            kthr[l]  = NT - r;
        }
    }

    float acc[4][4];
#pragma unroll
    for (int nr = 0; nr < 4; nr++)
#pragma unroll
        for (int e = 0; e < 4; e++) acc[nr][e] = 0.0f;

    const int NKT = (NT + 31) / 32;   // 18
#pragma unroll
    for (int l = 0; l < 4; l++)
        cp16(sbase + so[l], gb[l], sok[l] && (0 < kthr[l]));
    CP_COMMIT();

    for (int kt = 0; kt < NKT; kt++) {
        int buf = kt & 1;
        if (kt + 1 < NKT) {
            int k0 = (kt + 1) * 32;
            uint32_t boff = (buf ^ 1) * (DST_STAGE_F * 4);
#pragma unroll
            for (int l = 0; l < 4; l++)
                cp16(sbase + boff + so[l], gb[l] + (size_t)k0 * gstep[l],
                     sok[l] && (k0 < kthr[l]));
            CP_COMMIT();
            CP_WAIT1();
        } else {
            CP_WAIT0();
        }
        __syncthreads();

        const uint32_t* As = S + buf * DST_STAGE_F;
        const uint32_t* Bs = As + 2304;       // Bs[k][d], stride 72
#pragma unroll
        for (int kk = 0; kk < 32; kk += 8) {
            uint32_t a[4];
            a[0] = ldcvt(&As[(wm * 16 + g)     * 36 + kk + tg]);
            a[1] = ldcvt(&As[(wm * 16 + g + 8) * 36 + kk + tg]);
            a[2] = ldcvt(&As[(wm * 16 + g)     * 36 + kk + tg + 4]);
            a[3] = ldcvt(&As[(wm * 16 + g + 8) * 36 + kk + tg + 4]);
#pragma unroll
            for (int nr = 0; nr < 4; nr++) {
                uint32_t b[2];
                b[0] = ldcvt(&Bs[(kk + tg)     * 72 + wn * 32 + nr * 8 + g]);
                b[1] = ldcvt(&Bs[(kk + tg + 4) * 72 + wn * 32 + nr * 8 + g]);
                mma_tf32(acc[nr], a, b);
            }
        }
        __syncthreads();
    }

    float loc = 0.0f;
#pragma unroll
    for (int nr = 0; nr < 4; nr++)
#pragma unroll
        for (int e = 0; e < 4; e++) {
            int t = t0 + wm * 16 + g + ((e >= 2) ? 8 : 0);
            int d = d0 + wn * 32 + nr * 8 + 2 * tg + (e & 1);
            if (t < NT && d < DOUT) {
                float diff = Vq[(size_t)t * DOUT + d] - acc[nr][e];
                loc += diff * diff;
            }
        }
#pragma unroll
    for (int o = 16; o; o >>= 1) loc += __shfl_xor_sync(0xffffffffu, loc, o);
    if (lane == 0) red[wid] = loc;
    __syncthreads();
    if (tid == 0) {
        float tot = 0.0f;
        for (int w = 0; w < 8; w++) tot += red[w];
        atomicAdd(out + c, -tot / (float)NT);
    }
}

// ---------------------------------------------------------------------------
// Launch
// ---------------------------------------------------------------------------
extern "C" void kernel_launch(void* const* d_in, const int* in_sizes, int n_in,
                              void* d_out, int out_size) {
    const float* sup   = (const float*)d_in[0];
    const float* qry   = (const float*)d_in[1];
    const int*   lab   = (const int*)d_in[2];
    const float* wk    = (const float*)d_in[3];
    const float* bk    = (const float*)d_in[4];
    const float* wv    = (const float*)d_in[5];
    const float* bv    = (const float*)d_in[6];
    const float* gamma = (const float*)d_in[7];
    const float* beta  = (const float*)d_in[8];
    float* out = (float*)d_out;

    init_tup_kernel<<<1, 32>>>();
    build_x_kernel<<<NROWS, 256>>>(sup, qry);
    zero_out_kernel<<<1, 32>>>(out);
    proj_kernel<<<(NCOL + 31) / 32, 192>>>(wk, wv);
    assemble_kernel<<<dim3(NT, NSEQ), 256>>>(bk, bv, gamma, beta);
    score_kernel<<<dim3(9, 9, NSUP), 256>>>(lab);
    softmax_kernel<<<(NSUP * NT + 7) / 8, 256>>>();
    dist_kernel<<<dim3(9, 18, NSUP), 256>>>(lab, out);
}

// round 8
// speedup vs baseline: 3.0469x; 1.0493x over previous
#include <cuda_runtime.h>
#include <math.h>
#include <stdint.h>

// ---------------------------------------------------------------------------
// Problem constants
// ---------------------------------------------------------------------------
#define SEQ    16
#define DIN    2048
#define DOUT   1128
#define NT     560          // C(16,3)
#define NSUP   5
#define NSEQ   6            // 5 support + 1 query
#define NROWS  96           // 6 seqs * 16 frames
#define NCOL   6768         // 2 (K,V) * 3 parts * 1128
#define KV_OFF 3384
#define LN_EPS 1e-5f

#define STAGE_F     4608                 // floats per pipeline stage (all GEMMs)
#define STAGE_B     (STAGE_F * 4)        // bytes per stage
#define SMEM_BYTES  (4 * STAGE_B)        // 73728 B, 4 stages

// ---------------------------------------------------------------------------
// Scratch (device globals -- no allocation allowed)
// ---------------------------------------------------------------------------
__device__ float g_X[NROWS * DIN];       // tf32-pre-rounded
__device__ float g_Y[NROWS * NCOL];      // full fp32
__device__ float g_K[NSEQ * NT * DOUT];  // tf32-pre-rounded (LN output)
__device__ float g_V[NSEQ * NT * DOUT];  // full fp32
__device__ float g_S[NSUP * NT * NT];    // scores fp32 -> attn tf32-pre-rounded
__device__ int   g_tup[NT * 3];

// ---------------------------------------------------------------------------
// helpers
// ---------------------------------------------------------------------------
__device__ __forceinline__ void mma_tf32(float* c, const uint32_t* a, const uint32_t* b) {
    asm volatile(
        "mma.sync.aligned.m16n8k8.row.col.f32.tf32.tf32.f32 "
        "{%0,%1,%2,%3}, {%4,%5,%6,%7}, {%8,%9}, {%0,%1,%2,%3};\n"
        : "+f"(c[0]), "+f"(c[1]), "+f"(c[2]), "+f"(c[3])
        : "r"(a[0]), "r"(a[1]), "r"(a[2]), "r"(a[3]), "r"(b[0]), "r"(b[1]));
}

// round-to-nearest into tf32 bit pattern (low 13 bits zero), returned as float
__device__ __forceinline__ float rnd32(float f) {
    uint32_t r;
    asm("cvt.rna.tf32.f32 %0, %1;" : "=r"(r) : "f"(f));
    return __uint_as_float(r);
}

// fragment load with rna conversion (for raw fp32 operands in smem)
__device__ __forceinline__ uint32_t ldcvt(const uint32_t* p) {
    float f = __uint_as_float(*p);
    uint32_t r;
    asm("cvt.rna.tf32.f32 %0, %1;" : "=r"(r) : "f"(f));
    return r;
}

__device__ __forceinline__ void cp16(uint32_t saddr, const float* g, bool p) {
    asm volatile("cp.async.cg.shared.global [%0], [%1], 16, %2;"
                 :: "r"(saddr), "l"(g), "r"(p ? 16 : 0));
}
#define CP_COMMIT()  asm volatile("cp.async.commit_group;")
#define CP_WAIT2()   asm volatile("cp.async.wait_group 2;")

// ---------------------------------------------------------------------------
// Kernel 1: X = input + positional encoding (tf32 pre-rounded).
// Block 0 also builds the tuple table and zeroes the output.
// ---------------------------------------------------------------------------
__global__ void build_x_kernel(const float* __restrict__ sup,
                               const float* __restrict__ qry,
                               float* __restrict__ out) {
    int r   = blockIdx.x;
    int tid = threadIdx.x;
    if (r == 0) {
        if (tid == 0) {
            int idx = 0;
            for (int i = 0; i < SEQ; i++)
                for (int j = i + 1; j < SEQ; j++)
                    for (int k = j + 1; k < SEQ; k++) {
                        g_tup[idx * 3 + 0] = i;
                        g_tup[idx * 3 + 1] = j;
                        g_tup[idx * 3 + 2] = k;
                        idx++;
                    }
        }
        if (tid < NSUP) out[tid] = 0.0f;
    }
    int f   = (r < 80) ? (r & 15) : (r - 80);
    const float* src = (r < 80) ? (sup + r * DIN) : (qry + (r - 80) * DIN);
    const float cexp = -logf(10000.0f) / (float)DIN;
    for (int j = tid; j < DIN / 2; j += blockDim.x) {
        float div = expf((float)(2 * j) * cexp);
        float ang = (float)f * div;
        g_X[r * DIN + 2 * j]     = rnd32(src[2 * j]     + 0.1f * sinf(ang));
        g_X[r * DIN + 2 * j + 1] = rnd32(src[2 * j + 1] + 0.1f * cosf(ang));
    }
}

// ---------------------------------------------------------------------------
// Kernel 2: Y[96,6768] = X[96,2048] @ W^T.  tile 96x32, BK=32, 4-stage cp.async
// A (g_X) pre-rounded -> plain LDS.  B (weights) raw -> ldcvt.
// ---------------------------------------------------------------------------
__global__ void __launch_bounds__(192) proj_kernel(const float* __restrict__ wk,
                                                   const float* __restrict__ wv) {
    extern __shared__ float smem[];
    uint32_t sbase = (uint32_t)__cvta_generic_to_shared(smem);
    const uint32_t* S = (const uint32_t*)smem;

    int tid  = threadIdx.x;
    int lane = tid & 31;
    int wid  = tid >> 5;
    int g    = lane >> 2;
    int tg   = lane & 3;
    int n0   = blockIdx.x * 32;

    // slots: 1024 float4 per stage (A 768 + B 256), 6 per thread
    const float* gb[6]; uint32_t so[6]; bool ex[6]; bool sok[6];
#pragma unroll
    for (int l = 0; l < 6; l++) {
        int idx = tid + l * 192;
        ex[l] = idx < 1024;
        gb[l] = g_X; so[l] = 0; sok[l] = false;
        if (!ex[l]) continue;
        if (idx < 768) {                       // A region
            int r = idx >> 3, q = idx & 7;
            gb[l]  = g_X + r * DIN + 4 * q;
            so[l]  = r * 144 + q * 16;
            sok[l] = true;
        } else {                               // B region
            int j = idx - 768;
            int r = j >> 3, q = j & 7;
            int cg = n0 + r;
            so[l] = 13824 + r * 144 + q * 16;
            if (cg < NCOL) {
                const float* base; int p, rr;
                if (cg < KV_OFF) { p = cg / DOUT; rr = cg - p * DOUT; base = wk; }
                else             { int c2 = cg - KV_OFF; p = c2 / DOUT; rr = c2 - p * DOUT; base = wv; }
                gb[l]  = base + rr * (3 * DIN) + p * DIN + 4 * q;
                sok[l] = true;
            }
        }
    }

    float acc[4][4];
#pragma unroll
    for (int nr = 0; nr < 4; nr++)
#pragma unroll
        for (int e = 0; e < 4; e++) acc[nr][e] = 0.0f;

    const int NKT = DIN / 32;   // 64
    // prologue: prefetch tiles 0..2
#pragma unroll
    for (int p = 0; p < 3; p++) {
        int k0 = p * 32;
        uint32_t boff = p * STAGE_B;
#pragma unroll
        for (int l = 0; l < 6; l++)
            if (ex[l]) cp16(sbase + boff + so[l], gb[l] + k0, sok[l]);
        CP_COMMIT();
    }

    for (int kt = 0; kt < NKT; kt++) {
        CP_WAIT2();
        __syncthreads();
        int kp = kt + 3;
        if (kp < NKT) {
            int k0 = kp * 32;
            uint32_t boff = (kp & 3) * STAGE_B;
#pragma unroll
            for (int l = 0; l < 6; l++)
                if (ex[l]) cp16(sbase + boff + so[l], gb[l] + k0, sok[l]);
        }
        CP_COMMIT();

        const uint32_t* As = S + (kt & 3) * STAGE_F;
        const uint32_t* Bs = As + 3456;        // 96*36
#pragma unroll
        for (int kk = 0; kk < 32; kk += 8) {
            uint32_t a[4];
            a[0] = As[(wid * 16 + g)     * 36 + kk + tg];
            a[1] = As[(wid * 16 + g + 8) * 36 + kk + tg];
            a[2] = As[(wid * 16 + g)     * 36 + kk + tg + 4];
            a[3] = As[(wid * 16 + g + 8) * 36 + kk + tg + 4];
#pragma unroll
            for (int nr = 0; nr < 4; nr++) {
                uint32_t b[2];
                b[0] = ldcvt(&Bs[(nr * 8 + g) * 36 + kk + tg]);
                b[1] = ldcvt(&Bs[(nr * 8 + g) * 36 + kk + tg + 4]);
                mma_tf32(acc[nr], a, b);
            }
        }
    }

#pragma unroll
    for (int nr = 0; nr < 4; nr++)
#pragma unroll
        for (int e = 0; e < 4; e++) {
            int row = wid * 16 + g + ((e >= 2) ? 8 : 0);
            int cg  = n0 + nr * 8 + 2 * tg + (e & 1);
            if (cg < NCOL) g_Y[row * NCOL + cg] = acc[nr][e];
        }
}

// ---------------------------------------------------------------------------
// Kernel 3: assemble per-tuple K (layernorm, tf32-rounded store) and V.
// ---------------------------------------------------------------------------
__global__ void __launch_bounds__(256) assemble_kernel(const float* __restrict__ bk,
                                                       const float* __restrict__ bv,
                                                       const float* __restrict__ gamma,
                                                       const float* __restrict__ beta) {
    int t   = blockIdx.x;
    int n   = blockIdx.y;
    int tid = threadIdx.x;
    int lane = tid & 31, warp = tid >> 5;

    int i0 = g_tup[t * 3 + 0];
    int i1 = g_tup[t * 3 + 1];
    int i2 = g_tup[t * 3 + 2];
    const float* y0 = g_Y + (n * SEQ + i0) * NCOL;
    const float* y1 = g_Y + (n * SEQ + i1) * NCOL;
    const float* y2 = g_Y + (n * SEQ + i2) * NCOL;

    float kr[5];
    float s1 = 0.0f, s2 = 0.0f;
#pragma unroll
    for (int k = 0; k < 5; k++) {
        int d = tid + k * 256;
        if (k < 4 || tid < (DOUT - 1024)) {
            float v = y0[d] + y1[DOUT + d] + y2[2 * DOUT + d] + bk[d];
            kr[k] = v; s1 += v; s2 += v * v;
            float vv = y0[KV_OFF + d] + y1[KV_OFF + DOUT + d] + y2[KV_OFF + 2 * DOUT + d] + bv[d];
            g_V[(n * NT + t) * DOUT + d] = vv;
        } else kr[k] = 0.0f;
    }
    __shared__ float r1[8], r2[8];
    __shared__ float mu_s, rs_s;
#pragma unroll
    for (int o = 16; o; o >>= 1) {
        s1 += __shfl_xor_sync(0xffffffffu, s1, o);
        s2 += __shfl_xor_sync(0xffffffffu, s2, o);
    }
    if (lane == 0) { r1[warp] = s1; r2[warp] = s2; }
    __syncthreads();
    if (tid == 0) {
        float a = 0.0f, b = 0.0f;
        for (int w = 0; w < 8; w++) { a += r1[w]; b += r2[w]; }
        float mu = a / (float)DOUT;
        float var = b / (float)DOUT - mu * mu;
        mu_s = mu;
        rs_s = rsqrtf(var + LN_EPS);
    }
    __syncthreads();
    float mu = mu_s, rs = rs_s;
#pragma unroll
    for (int k = 0; k < 5; k++) {
        int d = tid + k * 256;
        if (k < 4 || tid < (DOUT - 1024))
            g_K[(n * NT + t) * DOUT + d] = rnd32((kr[k] - mu) * rs * gamma[d] + beta[d]);
    }
}

// ---------------------------------------------------------------------------
// Kernel 4: S = Kq . Kc^T * scale.  tile 64x64, BK=32, 4-stage, all plain LDS.
// ---------------------------------------------------------------------------
__global__ void __launch_bounds__(256) score_kernel(const int* __restrict__ labels) {
    extern __shared__ float smem[];
    uint32_t sbase = (uint32_t)__cvta_generic_to_shared(smem);
    const uint32_t* S = (const uint32_t*)smem;

    int tid  = threadIdx.x;
    int lane = tid & 31;
    int wid  = tid >> 5;
    int wm   = wid & 3;
    int wn   = wid >> 2;
    int g    = lane >> 2;
    int tg   = lane & 3;

    int c  = blockIdx.z;
    int t0 = blockIdx.x * 64;
    int s0 = blockIdx.y * 64;
    int lab = labels[c];
    if (lab < 0) lab = 0; if (lab >= NSUP) lab = NSUP - 1;

    const float* Aq = g_K + (size_t)NSUP * NT * DOUT;
    const float* Bc = g_K + (size_t)lab * NT * DOUT;

    const float* gb[4]; uint32_t so[4]; int kthr[4]; bool sok[4];
#pragma unroll
    for (int l = 0; l < 4; l++) {
        int idx = tid + l * 256;
        if (idx < 512) {
            int r = idx >> 3, q = idx & 7;
            int row = t0 + r;
            sok[l]  = row < NT;
            gb[l]   = Aq + (size_t)(sok[l] ? row : 0) * DOUT + 4 * q;
            so[l]   = r * 144 + q * 16;
            kthr[l] = DOUT - 4 * q;
        } else {
            int j = idx - 512;
            int r = j >> 3, q = j & 7;
            int row = s0 + r;
            sok[l]  = row < NT;
            gb[l]   = Bc + (size_t)(sok[l] ? row : 0) * DOUT + 4 * q;
            so[l]   = 9216 + r * 144 + q * 16;
            kthr[l] = DOUT - 4 * q;
        }
    }

    float acc[4][4];
#pragma unroll
    for (int nr = 0; nr < 4; nr++)
#pragma unroll
        for (int e = 0; e < 4; e++) acc[nr][e] = 0.0f;

    const int NKT = (DOUT + 31) / 32;   // 36
#pragma unroll
    for (int p = 0; p < 3; p++) {
        int k0 = p * 32;
        uint32_t boff = p * STAGE_B;
#pragma unroll
        for (int l = 0; l < 4; l++)
            cp16(sbase + boff + so[l], gb[l] + k0, sok[l] && (k0 < kthr[l]));
        CP_COMMIT();
    }

    for (int kt = 0; kt < NKT; kt++) {
        CP_WAIT2();
        __syncthreads();
        int kp = kt + 3;
        if (kp < NKT) {
            int k0 = kp * 32;
            uint32_t boff = (kp & 3) * STAGE_B;
#pragma unroll
            for (int l = 0; l < 4; l++)
                cp16(sbase + boff + so[l], gb[l] + k0, sok[l] && (k0 < kthr[l]));
        }
        CP_COMMIT();

        const uint32_t* As = S + (kt & 3) * STAGE_F;
        const uint32_t* Bs = As + 2304;   // 64*36
#pragma unroll
        for (int kk = 0; kk < 32; kk += 8) {
            uint32_t a[4];
            a[0] = As[(wm * 16 + g)     * 36 + kk + tg];
            a[1] = As[(wm * 16 + g + 8) * 36 + kk + tg];
            a[2] = As[(wm * 16 + g)     * 36 + kk + tg + 4];
            a[3] = As[(wm * 16 + g + 8) * 36 + kk + tg + 4];
#pragma unroll
            for (int nr = 0; nr < 4; nr++) {
                uint32_t b[2];
                b[0] = Bs[(wn * 32 + nr * 8 + g) * 36 + kk + tg];
                b[1] = Bs[(wn * 32 + nr * 8 + g) * 36 + kk + tg + 4];
                mma_tf32(acc[nr], a, b);
            }
        }
    }

    const float scale = rsqrtf((float)DOUT);
    float* Sc = g_S + (size_t)c * NT * NT;
#pragma unroll
    for (int nr = 0; nr < 4; nr++)
#pragma unroll
        for (int e = 0; e < 4; e++) {
            int t = t0 + wm * 16 + g + ((e >= 2) ? 8 : 0);
            int s = s0 + wn * 32 + nr * 8 + 2 * tg + (e & 1);
            if (t < NT && s < NT) Sc[(size_t)t * NT + s] = acc[nr][e] * scale;
        }
}

// ---------------------------------------------------------------------------
// Kernel 5: row softmax; final attn stored tf32-pre-rounded.
// ---------------------------------------------------------------------------
__global__ void __launch_bounds__(256) softmax_kernel() {
    int lane = threadIdx.x & 31;
    int row  = blockIdx.x * 8 + (threadIdx.x >> 5);
    if (row >= NSUP * NT) return;
    float* r = g_S + (size_t)row * NT;

    float m = -1e30f;
    for (int s = lane; s < NT; s += 32) m = fmaxf(m, r[s]);
#pragma unroll
    for (int o = 16; o; o >>= 1) m = fmaxf(m, __shfl_xor_sync(0xffffffffu, m, o));
    float sum = 0.0f;
    float ev[NT / 32 + 1];
    int cnt = 0;
    for (int s = lane; s < NT; s += 32) {
        float e = expf(r[s] - m);
        ev[cnt++] = e;
        sum += e;
    }
#pragma unroll
    for (int o = 16; o; o >>= 1) sum += __shfl_xor_sync(0xffffffffu, sum, o);
    float inv = 1.0f / sum;
    cnt = 0;
    for (int s = lane; s < NT; s += 32) r[s] = rnd32(ev[cnt++] * inv);
}

// ---------------------------------------------------------------------------
// Kernel 6: P = attn @ Vc, accumulate (q_v - P)^2.  4-stage.
// A (attn) pre-rounded -> plain LDS.  B (Vc) raw fp32 -> ldcvt.
// ---------------------------------------------------------------------------
__global__ void __launch_bounds__(256) dist_kernel(const int* __restrict__ labels,
                                                   float* __restrict__ out) {
    extern __shared__ float smem[];
    __shared__ float red[8];
    uint32_t sbase = (uint32_t)__cvta_generic_to_shared(smem);
    const uint32_t* S = (const uint32_t*)smem;

    int tid  = threadIdx.x;
    int lane = tid & 31;
    int wid  = tid >> 5;
    int wm   = wid & 3;
    int wn   = wid >> 2;
    int g    = lane >> 2;
    int tg   = lane & 3;

    int c  = blockIdx.z;
    int t0 = blockIdx.x * 64;
    int d0 = blockIdx.y * 64;
    int lab = labels[c];
    if (lab < 0) lab = 0; if (lab >= NSUP) lab = NSUP - 1;

    const float* Ag = g_S + (size_t)c * NT * NT;
    const float* Vc = g_V + (size_t)lab * NT * DOUT;
    const float* Vq = g_V + (size_t)NSUP * NT * DOUT;

    const float* gb[4]; uint32_t so[4]; int gstep[4]; int kthr[4]; bool sok[4];
#pragma unroll
    for (int l = 0; l < 4; l++) {
        int idx = tid + l * 256;
        if (idx < 512) {
            int r = idx >> 3, q = idx & 7;
            int row = t0 + r;
            sok[l]   = row < NT;
            gb[l]    = Ag + (size_t)(sok[l] ? row : 0) * NT + 4 * q;
            so[l]    = r * 144 + q * 16;
            gstep[l] = 1;
            kthr[l]  = NT - 4 * q;
        } else {
            int j = idx - 512;
            int r = j >> 4, q = j & 15;
            int d = d0 + 4 * q;
            sok[l]   = d < DOUT;
            gb[l]    = Vc + (size_t)r * DOUT + (sok[l] ? d : 0);
            so[l]    = 9216 + r * 288 + q * 16;
            gstep[l] = DOUT;
            kthr[l]  = NT - r;
        }
    }

    float acc[4][4];
#pragma unroll
    for (int nr = 0; nr < 4; nr++)
#pragma unroll
        for (int e = 0; e < 4; e++) acc[nr][e] = 0.0f;

    const int NKT = (NT + 31) / 32;   // 18
#pragma unroll
    for (int p = 0; p < 3; p++) {
        int k0 = p * 32;
        uint32_t boff = p * STAGE_B;
#pragma unroll
        for (int l = 0; l < 4; l++)
            cp16(sbase + boff + so[l], gb[l] + (size_t)k0 * gstep[l],
                 sok[l] && (k0 < kthr[l]));
        CP_COMMIT();
    }

    for (int kt = 0; kt < NKT; kt++) {
        CP_WAIT2();
        __syncthreads();
        int kp = kt + 3;
        if (kp < NKT) {
            int k0 = kp * 32;
            uint32_t boff = (kp & 3) * STAGE_B;
#pragma unroll
            for (int l = 0; l < 4; l++)
                cp16(sbase + boff + so[l], gb[l] + (size_t)k0 * gstep[l],
                     sok[l] && (k0 < kthr[l]));
        }
        CP_COMMIT();

        const uint32_t* As = S + (kt & 3) * STAGE_F;
        const uint32_t* Bs = As + 2304;       // Bs[k][d], stride 72
#pragma unroll
        for (int kk = 0; kk < 32; kk += 8) {
            uint32_t a[4];
            a[0] = As[(wm * 16 + g)     * 36 + kk + tg];
            a[1] = As[(wm * 16 + g + 8) * 36 + kk + tg];
            a[2] = As[(wm * 16 + g)     * 36 + kk + tg + 4];
            a[3] = As[(wm * 16 + g + 8) * 36 + kk + tg + 4];
#pragma unroll
            for (int nr = 0; nr < 4; nr++) {
                uint32_t b[2];
                b[0] = ldcvt(&Bs[(kk + tg)     * 72 + wn * 32 + nr * 8 + g]);
                b[1] = ldcvt(&Bs[(kk + tg + 4) * 72 + wn * 32 + nr * 8 + g]);
                mma_tf32(acc[nr], a, b);
            }
        }
    }

    float loc = 0.0f;
#pragma unroll
    for (int nr = 0; nr < 4; nr++)
#pragma unroll
        for (int e = 0; e < 4; e++) {
            int t = t0 + wm * 16 + g + ((e >= 2) ? 8 : 0);
            int d = d0 + wn * 32 + nr * 8 + 2 * tg + (e & 1);
            if (t < NT && d < DOUT) {
                float diff = Vq[(size_t)t * DOUT + d] - acc[nr][e];
                loc += diff * diff;
            }
        }
#pragma unroll
    for (int o = 16; o; o >>= 1) loc += __shfl_xor_sync(0xffffffffu, loc, o);
    if (lane == 0) red[wid] = loc;
    __syncthreads();
    if (tid == 0) {
        float tot = 0.0f;
        for (int w = 0; w < 8; w++) tot += red[w];
        atomicAdd(out + c, -tot / (float)NT);
    }
}

// ---------------------------------------------------------------------------
// Launch
// ---------------------------------------------------------------------------
extern "C" void kernel_launch(void* const* d_in, const int* in_sizes, int n_in,
                              void* d_out, int out_size) {
    const float* sup   = (const float*)d_in[0];
    const float* qry   = (const float*)d_in[1];
    const int*   lab   = (const int*)d_in[2];
    const float* wk    = (const float*)d_in[3];
    const float* bk    = (const float*)d_in[4];
    const float* wv    = (const float*)d_in[5];
    const float* bv    = (const float*)d_in[6];
    const float* gamma = (const float*)d_in[7];
    const float* beta  = (const float*)d_in[8];
    float* out = (float*)d_out;

    cudaFuncSetAttribute(proj_kernel,  cudaFuncAttributeMaxDynamicSharedMemorySize, SMEM_BYTES);
    cudaFuncSetAttribute(score_kernel, cudaFuncAttributeMaxDynamicSharedMemorySize, SMEM_BYTES);
    cudaFuncSetAttribute(dist_kernel,  cudaFuncAttributeMaxDynamicSharedMemorySize, SMEM_BYTES);

    build_x_kernel<<<NROWS, 256>>>(sup, qry, out);
    proj_kernel<<<(NCOL + 31) / 32, 192, SMEM_BYTES>>>(wk, wv);
    assemble_kernel<<<dim3(NT, NSEQ), 256>>>(bk, bv, gamma, beta);
    score_kernel<<<dim3(9, 9, NSUP), 256, SMEM_BYTES>>>(lab);
    softmax_kernel<<<(NSUP * NT + 7) / 8, 256>>>();
    dist_kernel<<<dim3(9, 18, NSUP), 256, SMEM_BYTES>>>(lab, out);
}

// round 9
// speedup vs baseline: 3.1902x; 1.0470x over previous
#include <cuda_runtime.h>
#include <math.h>
#include <stdint.h>

// ---------------------------------------------------------------------------
// Problem constants
// ---------------------------------------------------------------------------
#define SEQ    16
#define DIN    2048
#define DOUT   1128
#define NT     560          // C(16,3)
#define NSUP   5
#define NSEQ   6            // 5 support + 1 query
#define NROWS  96           // 6 seqs * 16 frames
#define NCOL   6768         // 2 (K,V) * 3 parts * 1128
#define KV_OFF 3384
#define LN_EPS 1e-5f

// proj pipeline (unchanged from R8)
#define STAGE_F     4608
#define STAGE_B     (STAGE_F * 4)
#define SMEM_BYTES  (4 * STAGE_B)        // 73728 B

// score pipeline: As 128x36 + Bs 128x36 per stage, 3 stages
#define SC_STAGE_F  9216
#define SC_STAGE_B  (SC_STAGE_F * 4)     // 36864
#define SC_SMEM     (3 * SC_STAGE_B)     // 110592

// dist pipeline: As 128x36 + Bs 32x136 per stage, 3 stages
#define DS_STAGE_F  (4608 + 4352)        // 8960
#define DS_STAGE_B  (DS_STAGE_F * 4)     // 35840
#define DS_SMEM     (3 * DS_STAGE_B)     // 107520

// ---------------------------------------------------------------------------
// Scratch (device globals -- no allocation allowed)
// ---------------------------------------------------------------------------
__device__ float g_X[NROWS * DIN];       // tf32-pre-rounded
__device__ float g_Y[NROWS * NCOL];      // full fp32
__device__ float g_K[NSEQ * NT * DOUT];  // tf32-pre-rounded (LN output)
__device__ float g_V[NSEQ * NT * DOUT];  // full fp32
__device__ float g_S[NSUP * NT * NT];    // scores fp32 -> attn tf32-pre-rounded
__device__ int   g_tup[NT * 3];

// ---------------------------------------------------------------------------
// helpers
// ---------------------------------------------------------------------------
__device__ __forceinline__ void mma_tf32(float* c, const uint32_t* a, const uint32_t* b) {
    asm volatile(
        "mma.sync.aligned.m16n8k8.row.col.f32.tf32.tf32.f32 "
        "{%0,%1,%2,%3}, {%4,%5,%6,%7}, {%8,%9}, {%0,%1,%2,%3};\n"
        : "+f"(c[0]), "+f"(c[1]), "+f"(c[2]), "+f"(c[3])
        : "r"(a[0]), "r"(a[1]), "r"(a[2]), "r"(a[3]), "r"(b[0]), "r"(b[1]));
}

__device__ __forceinline__ float rnd32(float f) {
    uint32_t r;
    asm("cvt.rna.tf32.f32 %0, %1;" : "=r"(r) : "f"(f));
    return __uint_as_float(r);
}

__device__ __forceinline__ uint32_t ldcvt(const uint32_t* p) {
    float f = __uint_as_float(*p);
    uint32_t r;
    asm("cvt.rna.tf32.f32 %0, %1;" : "=r"(r) : "f"(f));
    return r;
}

__device__ __forceinline__ void cp16(uint32_t saddr, const float* g, bool p) {
    asm volatile("cp.async.cg.shared.global [%0], [%1], 16, %2;"
                 :: "r"(saddr), "l"(g), "r"(p ? 16 : 0));
}
#define CP_COMMIT()  asm volatile("cp.async.commit_group;")
#define CP_WAIT1()   asm volatile("cp.async.wait_group 1;")
#define CP_WAIT2()   asm volatile("cp.async.wait_group 2;")

// ---------------------------------------------------------------------------
// Kernel 1: X = input + positional encoding (tf32 pre-rounded).
// Block 0 also builds the tuple table and zeroes the output.
// ---------------------------------------------------------------------------
__global__ void build_x_kernel(const float* __restrict__ sup,
                               const float* __restrict__ qry,
                               float* __restrict__ out) {
    int r   = blockIdx.x;
    int tid = threadIdx.x;
    if (r == 0) {
        if (tid == 0) {
            int idx = 0;
            for (int i = 0; i < SEQ; i++)
                for (int j = i + 1; j < SEQ; j++)
                    for (int k = j + 1; k < SEQ; k++) {
                        g_tup[idx * 3 + 0] = i;
                        g_tup[idx * 3 + 1] = j;
                        g_tup[idx * 3 + 2] = k;
                        idx++;
                    }
        }
        if (tid < NSUP) out[tid] = 0.0f;
    }
    int f   = (r < 80) ? (r & 15) : (r - 80);
    const float* src = (r < 80) ? (sup + r * DIN) : (qry + (r - 80) * DIN);
    const float cexp = -logf(10000.0f) / (float)DIN;
    for (int j = tid; j < DIN / 2; j += blockDim.x) {
        float div = expf((float)(2 * j) * cexp);
        float ang = (float)f * div;
        g_X[r * DIN + 2 * j]     = rnd32(src[2 * j]     + 0.1f * sinf(ang));
        g_X[r * DIN + 2 * j + 1] = rnd32(src[2 * j + 1] + 0.1f * cosf(ang));
    }
}

// ---------------------------------------------------------------------------
// Kernel 2: Y[96,6768] = X[96,2048] @ W^T.  (unchanged from R8)
// ---------------------------------------------------------------------------
__global__ void __launch_bounds__(192) proj_kernel(const float* __restrict__ wk,
                                                   const float* __restrict__ wv) {
    extern __shared__ float smem[];
    uint32_t sbase = (uint32_t)__cvta_generic_to_shared(smem);
    const uint32_t* S = (const uint32_t*)smem;

    int tid  = threadIdx.x;
    int lane = tid & 31;
    int wid  = tid >> 5;
    int g    = lane >> 2;
    int tg   = lane & 3;
    int n0   = blockIdx.x * 32;

    const float* gb[6]; uint32_t so[6]; bool ex[6]; bool sok[6];
#pragma unroll
    for (int l = 0; l < 6; l++) {
        int idx = tid + l * 192;
        ex[l] = idx < 1024;
        gb[l] = g_X; so[l] = 0; sok[l] = false;
        if (!ex[l]) continue;
        if (idx < 768) {
            int r = idx >> 3, q = idx & 7;
            gb[l]  = g_X + r * DIN + 4 * q;
            so[l]  = r * 144 + q * 16;
            sok[l] = true;
        } else {
            int j = idx - 768;
            int r = j >> 3, q = j & 7;
            int cg = n0 + r;
            so[l] = 13824 + r * 144 + q * 16;
            if (cg < NCOL) {
                const float* base; int p, rr;
                if (cg < KV_OFF) { p = cg / DOUT; rr = cg - p * DOUT; base = wk; }
                else             { int c2 = cg - KV_OFF; p = c2 / DOUT; rr = c2 - p * DOUT; base = wv; }
                gb[l]  = base + rr * (3 * DIN) + p * DIN + 4 * q;
                sok[l] = true;
            }
        }
    }

    float acc[4][4];
#pragma unroll
    for (int nr = 0; nr < 4; nr++)
#pragma unroll
        for (int e = 0; e < 4; e++) acc[nr][e] = 0.0f;

    const int NKT = DIN / 32;   // 64
#pragma unroll
    for (int p = 0; p < 3; p++) {
        int k0 = p * 32;
        uint32_t boff = p * STAGE_B;
#pragma unroll
        for (int l = 0; l < 6; l++)
            if (ex[l]) cp16(sbase + boff + so[l], gb[l] + k0, sok[l]);
        CP_COMMIT();
    }

    for (int kt = 0; kt < NKT; kt++) {
        CP_WAIT2();
        __syncthreads();
        int kp = kt + 3;
        if (kp < NKT) {
            int k0 = kp * 32;
            uint32_t boff = (kp & 3) * STAGE_B;
#pragma unroll
            for (int l = 0; l < 6; l++)
                if (ex[l]) cp16(sbase + boff + so[l], gb[l] + k0, sok[l]);
        }
        CP_COMMIT();

        const uint32_t* As = S + (kt & 3) * STAGE_F;
        const uint32_t* Bs = As + 3456;
#pragma unroll
        for (int kk = 0; kk < 32; kk += 8) {
            uint32_t a[4];
            a[0] = As[(wid * 16 + g)     * 36 + kk + tg];
            a[1] = As[(wid * 16 + g + 8) * 36 + kk + tg];
            a[2] = As[(wid * 16 + g)     * 36 + kk + tg + 4];
            a[3] = As[(wid * 16 + g + 8) * 36 + kk + tg + 4];
#pragma unroll
            for (int nr = 0; nr < 4; nr++) {
                uint32_t b[2];
                b[0] = ldcvt(&Bs[(nr * 8 + g) * 36 + kk + tg]);
                b[1] = ldcvt(&Bs[(nr * 8 + g) * 36 + kk + tg + 4]);
                mma_tf32(acc[nr], a, b);
            }
        }
    }

#pragma unroll
    for (int nr = 0; nr < 4; nr++)
#pragma unroll
        for (int e = 0; e < 4; e++) {
            int row = wid * 16 + g + ((e >= 2) ? 8 : 0);
            int cg  = n0 + nr * 8 + 2 * tg + (e & 1);
            if (cg < NCOL) g_Y[row * NCOL + cg] = acc[nr][e];
        }
}

// ---------------------------------------------------------------------------
// Kernel 3: assemble per-tuple K (layernorm, tf32-rounded store) and V.
// ---------------------------------------------------------------------------
__global__ void __launch_bounds__(256) assemble_kernel(const float* __restrict__ bk,
                                                       const float* __restrict__ bv,
                                                       const float* __restrict__ gamma,
                                                       const float* __restrict__ beta) {
    int t   = blockIdx.x;
    int n   = blockIdx.y;
    int tid = threadIdx.x;
    int lane = tid & 31, warp = tid >> 5;

    int i0 = g_tup[t * 3 + 0];
    int i1 = g_tup[t * 3 + 1];
    int i2 = g_tup[t * 3 + 2];
    const float* y0 = g_Y + (n * SEQ + i0) * NCOL;
    const float* y1 = g_Y + (n * SEQ + i1) * NCOL;
    const float* y2 = g_Y + (n * SEQ + i2) * NCOL;

    float kr[5];
    float s1 = 0.0f, s2 = 0.0f;
#pragma unroll
    for (int k = 0; k < 5; k++) {
        int d = tid + k * 256;
        if (k < 4 || tid < (DOUT - 1024)) {
            float v = y0[d] + y1[DOUT + d] + y2[2 * DOUT + d] + bk[d];
            kr[k] = v; s1 += v; s2 += v * v;
            float vv = y0[KV_OFF + d] + y1[KV_OFF + DOUT + d] + y2[KV_OFF + 2 * DOUT + d] + bv[d];
            g_V[(n * NT + t) * DOUT + d] = vv;
        } else kr[k] = 0.0f;
    }
    __shared__ float r1[8], r2[8];
    __shared__ float mu_s, rs_s;
#pragma unroll
    for (int o = 16; o; o >>= 1) {
        s1 += __shfl_xor_sync(0xffffffffu, s1, o);
        s2 += __shfl_xor_sync(0xffffffffu, s2, o);
    }
    if (lane == 0) { r1[warp] = s1; r2[warp] = s2; }
    __syncthreads();
    if (tid == 0) {
        float a = 0.0f, b = 0.0f;
        for (int w = 0; w < 8; w++) { a += r1[w]; b += r2[w]; }
        float mu = a / (float)DOUT;
        float var = b / (float)DOUT - mu * mu;
        mu_s = mu;
        rs_s = rsqrtf(var + LN_EPS);
    }
    __syncthreads();
    float mu = mu_s, rs = rs_s;
#pragma unroll
    for (int k = 0; k < 5; k++) {
        int d = tid + k * 256;
        if (k < 4 || tid < (DOUT - 1024))
            g_K[(n * NT + t) * DOUT + d] = rnd32((kr[k] - mu) * rs * gamma[d] + beta[d]);
    }
}

// ---------------------------------------------------------------------------
// Kernel 4: S = Kq . Kc^T * scale.  Block tile 128x128, warp 32x64, BK=32,
// 3-stage cp.async.  All operands tf32-pre-rounded -> plain LDS.
// ---------------------------------------------------------------------------
__global__ void __launch_bounds__(256) score_kernel(const int* __restrict__ labels) {
    extern __shared__ float smem[];
    uint32_t sbase = (uint32_t)__cvta_generic_to_shared(smem);
    const uint32_t* S = (const uint32_t*)smem;

    int tid  = threadIdx.x;
    int lane = tid & 31;
    int wid  = tid >> 5;
    int wm   = wid & 3;               // 0..3 -> m block 32*wm
    int wn   = wid >> 2;              // 0..1 -> n block 64*wn
    int g    = lane >> 2;
    int tg   = lane & 3;

    int c  = blockIdx.z;
    int t0 = blockIdx.x * 128;
    int s0 = blockIdx.y * 128;
    int lab = labels[c];
    if (lab < 0) lab = 0; if (lab >= NSUP) lab = NSUP - 1;

    const float* Aq = g_K + (size_t)NSUP * NT * DOUT;
    const float* Bc = g_K + (size_t)lab * NT * DOUT;

    // loader slots: 2048 float4 per stage (A 1024 + B 1024), 8 per thread
    const float* gb[8]; uint32_t so[8]; int kthr[8]; bool sok[8];
#pragma unroll
    for (int l = 0; l < 8; l++) {
        int idx = tid + l * 256;
        if (idx < 1024) {
            int r = idx >> 3, q = idx & 7;
            int row = t0 + r;
            sok[l]  = row < NT;
            gb[l]   = Aq + (size_t)(sok[l] ? row : 0) * DOUT + 4 * q;
            so[l]   = r * 144 + q * 16;
            kthr[l] = DOUT - 4 * q;
        } else {
            int j = idx - 1024;
            int r = j >> 3, q = j & 7;
            int row = s0 + r;
            sok[l]  = row < NT;
            gb[l]   = Bc + (size_t)(sok[l] ? row : 0) * DOUT + 4 * q;
            so[l]   = 18432 + r * 144 + q * 16;   // after A = 128*36*4
            kthr[l] = DOUT - 4 * q;
        }
    }

    float acc[2][8][4];
#pragma unroll
    for (int mi = 0; mi < 2; mi++)
#pragma unroll
        for (int ni = 0; ni < 8; ni++)
#pragma unroll
            for (int e = 0; e < 4; e++) acc[mi][ni][e] = 0.0f;

    const int NKT = (DOUT + 31) / 32;   // 36
#pragma unroll
    for (int p = 0; p < 2; p++) {
        int k0 = p * 32;
        uint32_t boff = p * SC_STAGE_B;
#pragma unroll
        for (int l = 0; l < 8; l++)
            cp16(sbase + boff + so[l], gb[l] + k0, sok[l] && (k0 < kthr[l]));
        CP_COMMIT();
    }

    for (int kt = 0; kt < NKT; kt++) {
        CP_WAIT1();
        __syncthreads();
        int kp = kt + 2;
        if (kp < NKT) {
            int k0 = kp * 32;
            uint32_t boff = (kp % 3) * SC_STAGE_B;
#pragma unroll
            for (int l = 0; l < 8; l++)
                cp16(sbase + boff + so[l], gb[l] + k0, sok[l] && (k0 < kthr[l]));
        }
        CP_COMMIT();

        const uint32_t* As = S + (kt % 3) * SC_STAGE_F;
        const uint32_t* Bs = As + 4608;   // 128*36
#pragma unroll
        for (int kk = 0; kk < 32; kk += 8) {
            uint32_t a[2][4];
#pragma unroll
            for (int mi = 0; mi < 2; mi++) {
                int row = wm * 32 + mi * 16 + g;
                a[mi][0] = As[row       * 36 + kk + tg];
                a[mi][1] = As[(row + 8) * 36 + kk + tg];
                a[mi][2] = As[row       * 36 + kk + tg + 4];
                a[mi][3] = As[(row + 8) * 36 + kk + tg + 4];
            }
            uint32_t b[8][2];
#pragma unroll
            for (int ni = 0; ni < 8; ni++) {
                int nrow = wn * 64 + ni * 8 + g;
                b[ni][0] = Bs[nrow * 36 + kk + tg];
                b[ni][1] = Bs[nrow * 36 + kk + tg + 4];
            }
#pragma unroll
            for (int mi = 0; mi < 2; mi++)
#pragma unroll
                for (int ni = 0; ni < 8; ni++)
                    mma_tf32(acc[mi][ni], a[mi], b[ni]);
        }
    }

    const float scale = rsqrtf((float)DOUT);
    float* Sc = g_S + (size_t)c * NT * NT;
#pragma unroll
    for (int mi = 0; mi < 2; mi++)
#pragma unroll
        for (int ni = 0; ni < 8; ni++)
#pragma unroll
            for (int e = 0; e < 4; e++) {
                int t = t0 + wm * 32 + mi * 16 + g + ((e >= 2) ? 8 : 0);
                int s = s0 + wn * 64 + ni * 8 + 2 * tg + (e & 1);
                if (t < NT && s < NT) Sc[(size_t)t * NT + s] = acc[mi][ni][e] * scale;
            }
}

// ---------------------------------------------------------------------------
// Kernel 5: row softmax; final attn stored tf32-pre-rounded.
// ---------------------------------------------------------------------------
__global__ void __launch_bounds__(256) softmax_kernel() {
    int lane = threadIdx.x & 31;
    int row  = blockIdx.x * 8 + (threadIdx.x >> 5);
    if (row >= NSUP * NT) return;
    float* r = g_S + (size_t)row * NT;

    float m = -1e30f;
    for (int s = lane; s < NT; s += 32) m = fmaxf(m, r[s]);
#pragma unroll
    for (int o = 16; o; o >>= 1) m = fmaxf(m, __shfl_xor_sync(0xffffffffu, m, o));
    float sum = 0.0f;
    float ev[NT / 32 + 1];
    int cnt = 0;
    for (int s = lane; s < NT; s += 32) {
        float e = expf(r[s] - m);
        ev[cnt++] = e;
        sum += e;
    }
#pragma unroll
    for (int o = 16; o; o >>= 1) sum += __shfl_xor_sync(0xffffffffu, sum, o);
    float inv = 1.0f / sum;
    cnt = 0;
    for (int s = lane; s < NT; s += 32) r[s] = rnd32(ev[cnt++] * inv);
}

// ---------------------------------------------------------------------------
// Kernel 6: P = attn @ Vc, accumulate (q_v - P)^2.  Block tile 128(t)x128(d),
// warp 32x64, BK=32 over s (18 tiles), 3-stage cp.async.
// A (attn) pre-rounded -> plain LDS.  B (Vc) raw fp32 -> ldcvt.
// ---------------------------------------------------------------------------
__global__ void __launch_bounds__(256) dist_kernel(const int* __restrict__ labels,
                                                   float* __restrict__ out) {
    extern __shared__ float smem[];
    __shared__ float red[8];
    uint32_t sbase = (uint32_t)__cvta_generic_to_shared(smem);
    const uint32_t* S = (const uint32_t*)smem;

    int tid  = threadIdx.x;
    int lane = tid & 31;
    int wid  = tid >> 5;
    int wm   = wid & 3;
    int wn   = wid >> 2;
    int g    = lane >> 2;
    int tg   = lane & 3;

    int c  = blockIdx.z;
    int t0 = blockIdx.x * 128;
    int d0 = blockIdx.y * 128;
    int lab = labels[c];
    if (lab < 0) lab = 0; if (lab >= NSUP) lab = NSUP - 1;

    const float* Ag = g_S + (size_t)c * NT * NT;
    const float* Vc = g_V + (size_t)lab * NT * DOUT;
    const float* Vq = g_V + (size_t)NSUP * NT * DOUT;

    // slots: A 1024 f4 (128 t-rows x 8), B 1024 f4 (32 s-rows x 32)
    const float* gb[8]; uint32_t so[8]; int gstep[8]; int kthr[8]; bool sok[8];
#pragma unroll
    for (int l = 0; l < 8; l++) {
        int idx = tid + l * 256;
        if (idx < 1024) {
            int r = idx >> 3, q = idx & 7;
            int row = t0 + r;
            sok[l]   = row < NT;
            gb[l]    = Ag + (size_t)(sok[l] ? row : 0) * NT + 4 * q;
            so[l]    = r * 144 + q * 16;
            gstep[l] = 1;
            kthr[l]  = NT - 4 * q;
        } else {
            int j = idx - 1024;
            int r = j >> 5, q = j & 31;
            int d = d0 + 4 * q;
            sok[l]   = d < DOUT;
            gb[l]    = Vc + (size_t)r * DOUT + (sok[l] ? d : 0);
            so[l]    = 18432 + r * 544 + q * 16;   // B row stride 136 floats
            gstep[l] = DOUT;
            kthr[l]  = NT - r;
        }
    }

    float acc[2][8][4];
#pragma unroll
    for (int mi = 0; mi < 2; mi++)
#pragma unroll
        for (int ni = 0; ni < 8; ni++)
#pragma unroll
            for (int e = 0; e < 4; e++) acc[mi][ni][e] = 0.0f;

    const int NKT = (NT + 31) / 32;   // 18
#pragma unroll
    for (int p = 0; p < 2; p++) {
        int k0 = p * 32;
        uint32_t boff = p * DS_STAGE_B;
#pragma unroll
        for (int l = 0; l < 8; l++)
            cp16(sbase + boff + so[l], gb[l] + (size_t)k0 * gstep[l],
                 sok[l] && (k0 < kthr[l]));
        CP_COMMIT();
    }

    for (int kt = 0; kt < NKT; kt++) {
        CP_WAIT1();
        __syncthreads();
        int kp = kt + 2;
        if (kp < NKT) {
            int k0 = kp * 32;
            uint32_t boff = (kp % 3) * DS_STAGE_B;
#pragma unroll
            for (int l = 0; l < 8; l++)
                cp16(sbase + boff + so[l], gb[l] + (size_t)k0 * gstep[l],
                     sok[l] && (k0 < kthr[l]));
        }
        CP_COMMIT();

        const uint32_t* As = S + (kt % 3) * DS_STAGE_F;
        const uint32_t* Bs = As + 4608;       // Bs[k][d], stride 136
#pragma unroll
        for (int kk = 0; kk < 32; kk += 8) {
            uint32_t a[2][4];
#pragma unroll
            for (int mi = 0; mi < 2; mi++) {
                int row = wm * 32 + mi * 16 + g;
                a[mi][0] = As[row       * 36 + kk + tg];
                a[mi][1] = As[(row + 8) * 36 + kk + tg];
                a[mi][2] = As[row       * 36 + kk + tg + 4];
                a[mi][3] = As[(row + 8) * 36 + kk + tg + 4];
            }
            uint32_t b[8][2];
#pragma unroll
            for (int ni = 0; ni < 8; ni++) {
                int ncol = wn * 64 + ni * 8 + g;
                b[ni][0] = ldcvt(&Bs[(kk + tg)     * 136 + ncol]);
                b[ni][1] = ldcvt(&Bs[(kk + tg + 4) * 136 + ncol]);
            }
#pragma unroll
            for (int mi = 0; mi < 2; mi++)
#pragma unroll
                for (int ni = 0; ni < 8; ni++)
                    mma_tf32(acc[mi][ni], a[mi], b[ni]);
        }
    }

    float loc = 0.0f;
#pragma unroll
    for (int mi = 0; mi < 2; mi++)
#pragma unroll
        for (int ni = 0; ni < 8; ni++)
#pragma unroll
            for (int e = 0; e < 4; e++) {
                int t = t0 + wm * 32 + mi * 16 + g + ((e >= 2) ? 8 : 0);
                int d = d0 + wn * 64 + ni * 8 + 2 * tg + (e & 1);
                if (t < NT && d < DOUT) {
                    float diff = Vq[(size_t)t * DOUT + d] - acc[mi][ni][e];
                    loc += diff * diff;
                }
            }
#pragma unroll
    for (int o = 16; o; o >>= 1) loc += __shfl_xor_sync(0xffffffffu, loc, o);
    if (lane == 0) red[wid] = loc;
    __syncthreads();
    if (tid == 0) {
        float tot = 0.0f;
        for (int w = 0; w < 8; w++) tot += red[w];
        atomicAdd(out + c, -tot / (float)NT);
    }
}

// ---------------------------------------------------------------------------
// Launch
// ---------------------------------------------------------------------------
extern "C" void kernel_launch(void* const* d_in, const int* in_sizes, int n_in,
                              void* d_out, int out_size) {
    const float* sup   = (const float*)d_in[0];
    const float* qry   = (const float*)d_in[1];
    const int*   lab   = (const int*)d_in[2];
    const float* wk    = (const float*)d_in[3];
    const float* bk    = (const float*)d_in[4];
    const float* wv    = (const float*)d_in[5];
    const float* bv    = (const float*)d_in[6];
    const float* gamma = (const float*)d_in[7];
    const float* beta  = (const float*)d_in[8];
    float* out = (float*)d_out;

    cudaFuncSetAttribute(proj_kernel,  cudaFuncAttributeMaxDynamicSharedMemorySize, SMEM_BYTES);
    cudaFuncSetAttribute(score_kernel, cudaFuncAttributeMaxDynamicSharedMemorySize, SC_SMEM);
    cudaFuncSetAttribute(dist_kernel,  cudaFuncAttributeMaxDynamicSharedMemorySize, DS_SMEM);

    build_x_kernel<<<NROWS, 256>>>(sup, qry, out);
    proj_kernel<<<(NCOL + 31) / 32, 192, SMEM_BYTES>>>(wk, wv);
    assemble_kernel<<<dim3(NT, NSEQ), 256>>>(bk, bv, gamma, beta);
    score_kernel<<<dim3(5, 5, NSUP), 256, SC_SMEM>>>(lab);
    softmax_kernel<<<(NSUP * NT + 7) / 8, 256>>>();
    dist_kernel<<<dim3(5, 9, NSUP), 256, DS_SMEM>>>(lab, out);
}

// round 11
// speedup vs baseline: 3.2201x; 1.0094x over previous
#include <cuda_runtime.h>
#include <math.h>
#include <stdint.h>

// ---------------------------------------------------------------------------
// Problem constants
// ---------------------------------------------------------------------------
#define SEQ    16
#define DIN    2048
#define DOUT   1128
#define NT     560          // C(16,3)
#define NSUP   5
#define NSEQ   6            // 5 support + 1 query
#define NROWS  96           // 6 seqs * 16 frames
#define NCOL   6768         // 2 (K,V) * 3 parts * 1128
#define KV_OFF 3384
#define LN_EPS 1e-5f

// proj pipeline
#define STAGE_F     4608
#define STAGE_B     (STAGE_F * 4)
#define SMEM_BYTES  (4 * STAGE_B)        // 73728 B

// score pipeline: As 128x36 + Bs 128x36 per stage, 3 stages
#define SC_STAGE_F  9216
#define SC_STAGE_B  (SC_STAGE_F * 4)     // 36864
#define SC_SMEM     (3 * SC_STAGE_B)     // 110592
#define SC_BOFF     18432                // byte offset of B region in stage

// dist pipeline: As 128x36 + Bs 32x136 per stage, 3 stages
#define DS_STAGE_F  (4608 + 4352)        // 8960
#define DS_STAGE_B  (DS_STAGE_F * 4)     // 35840
#define DS_SMEM     (3 * DS_STAGE_B)     // 107520
#define DS_BOFF     18432

// ---------------------------------------------------------------------------
// Scratch (device globals -- no allocation allowed)
// ---------------------------------------------------------------------------
__device__ float g_X[NROWS * DIN];       // tf32-pre-rounded
__device__ float g_Y[NROWS * NCOL];      // full fp32
__device__ float g_K[NSEQ * NT * DOUT];  // tf32-pre-rounded (LN output)
__device__ float g_V[NSEQ * NT * DOUT];  // tf32-pre-rounded
__device__ float g_S[NSUP * NT * NT];    // scores fp32 -> attn tf32-pre-rounded
__device__ int   g_tup[NT * 3];

// ---------------------------------------------------------------------------
// helpers
// ---------------------------------------------------------------------------
__device__ __forceinline__ void mma_tf32(float* c, const uint32_t* a, const uint32_t* b) {
    asm volatile(
        "mma.sync.aligned.m16n8k8.row.col.f32.tf32.tf32.f32 "
        "{%0,%1,%2,%3}, {%4,%5,%6,%7}, {%8,%9}, {%0,%1,%2,%3};\n"
        : "+f"(c[0]), "+f"(c[1]), "+f"(c[2]), "+f"(c[3])
        : "r"(a[0]), "r"(a[1]), "r"(a[2]), "r"(a[3]), "r"(b[0]), "r"(b[1]));
}

__device__ __forceinline__ float rnd32(float f) {
    uint32_t r;
    asm("cvt.rna.tf32.f32 %0, %1;" : "=r"(r) : "f"(f));
    return __uint_as_float(r);
}

__device__ __forceinline__ uint32_t ldcvt(const uint32_t* p) {
    float f = __uint_as_float(*p);
    uint32_t r;
    asm("cvt.rna.tf32.f32 %0, %1;" : "=r"(r) : "f"(f));
    return r;
}

// ldmatrix x4: loads four 8x4-tf32 tiles (viewed as 8x8 b16) in one op
__device__ __forceinline__ void ldsm4(uint32_t addr, uint32_t& r0, uint32_t& r1,
                                      uint32_t& r2, uint32_t& r3) {
    asm volatile("ldmatrix.sync.aligned.m8n8.x4.shared.b16 {%0,%1,%2,%3}, [%4];"
                 : "=r"(r0), "=r"(r1), "=r"(r2), "=r"(r3) : "r"(addr));
}

__device__ __forceinline__ void cp16(uint32_t saddr, const float* g, bool p) {
    asm volatile("cp.async.cg.shared.global [%0], [%1], 16, %2;"
                 :: "r"(saddr), "l"(g), "r"(p ? 16 : 0));
}
#define CP_COMMIT()  asm volatile("cp.async.commit_group;")
#define CP_WAIT1()   asm volatile("cp.async.wait_group 1;")
#define CP_WAIT2()   asm volatile("cp.async.wait_group 2;")

// ---------------------------------------------------------------------------
// Kernel 1: X = input + positional encoding (tf32 pre-rounded).
// ---------------------------------------------------------------------------
__global__ void build_x_kernel(const float* __restrict__ sup,
                               const float* __restrict__ qry,
                               float* __restrict__ out) {
    int r   = blockIdx.x;
    int tid = threadIdx.x;
    if (r == 0) {
        if (tid == 0) {
            int idx = 0;
            for (int i = 0; i < SEQ; i++)
                for (int j = i + 1; j < SEQ; j++)
                    for (int k = j + 1; k < SEQ; k++) {
                        g_tup[idx * 3 + 0] = i;
                        g_tup[idx * 3 + 1] = j;
                        g_tup[idx * 3 + 2] = k;
                        idx++;
                    }
        }
        if (tid < NSUP) out[tid] = 0.0f;
    }
    int f   = (r < 80) ? (r & 15) : (r - 80);
    const float* src = (r < 80) ? (sup + r * DIN) : (qry + (r - 80) * DIN);
    const float cexp = -logf(10000.0f) / (float)DIN;
    for (int j = tid; j < DIN / 2; j += blockDim.x) {
        float div = expf((float)(2 * j) * cexp);
        float ang = (float)f * div;
        g_X[r * DIN + 2 * j]     = rnd32(src[2 * j]     + 0.1f * sinf(ang));
        g_X[r * DIN + 2 * j + 1] = rnd32(src[2 * j + 1] + 0.1f * cosf(ang));
    }
}

// ---------------------------------------------------------------------------
// Kernel 2: Y[96,6768] = X[96,2048] @ W^T.  (unchanged)
// ---------------------------------------------------------------------------
__global__ void __launch_bounds__(192) proj_kernel(const float* __restrict__ wk,
                                                   const float* __restrict__ wv) {
    extern __shared__ float smem[];
    uint32_t sbase = (uint32_t)__cvta_generic_to_shared(smem);
    const uint32_t* S = (const uint32_t*)smem;

    int tid  = threadIdx.x;
    int lane = tid & 31;
    int wid  = tid >> 5;
    int g    = lane >> 2;
    int tg   = lane & 3;
    int n0   = blockIdx.x * 32;

    const float* gb[6]; uint32_t so[6]; bool ex[6]; bool sok[6];
#pragma unroll
    for (int l = 0; l < 6; l++) {
        int idx = tid + l * 192;
        ex[l] = idx < 1024;
        gb[l] = g_X; so[l] = 0; sok[l] = false;
        if (!ex[l]) continue;
        if (idx < 768) {
            int r = idx >> 3, q = idx & 7;
            gb[l]  = g_X + r * DIN + 4 * q;
            so[l]  = r * 144 + q * 16;
            sok[l] = true;
        } else {
            int j = idx - 768;
            int r = j >> 3, q = j & 7;
            int cg = n0 + r;
            so[l] = 13824 + r * 144 + q * 16;
            if (cg < NCOL) {
                const float* base; int p, rr;
                if (cg < KV_OFF) { p = cg / DOUT; rr = cg - p * DOUT; base = wk; }
                else             { int c2 = cg - KV_OFF; p = c2 / DOUT; rr = c2 - p * DOUT; base = wv; }
                gb[l]  = base + rr * (3 * DIN) + p * DIN + 4 * q;
                sok[l] = true;
            }
        }
    }

    float acc[4][4];
#pragma unroll
    for (int nr = 0; nr < 4; nr++)
#pragma unroll
        for (int e = 0; e < 4; e++) acc[nr][e] = 0.0f;

    const int NKT = DIN / 32;   // 64
#pragma unroll
    for (int p = 0; p < 3; p++) {
        int k0 = p * 32;
        uint32_t boff = p * STAGE_B;
#pragma unroll
        for (int l = 0; l < 6; l++)
            if (ex[l]) cp16(sbase + boff + so[l], gb[l] + k0, sok[l]);
        CP_COMMIT();
    }

    for (int kt = 0; kt < NKT; kt++) {
        CP_WAIT2();
        __syncthreads();
        int kp = kt + 3;
        if (kp < NKT) {
            int k0 = kp * 32;
            uint32_t boff = (kp & 3) * STAGE_B;
#pragma unroll
            for (int l = 0; l < 6; l++)
                if (ex[l]) cp16(sbase + boff + so[l], gb[l] + k0, sok[l]);
        }
        CP_COMMIT();

        const uint32_t* As = S + (kt & 3) * STAGE_F;
        const uint32_t* Bs = As + 3456;
#pragma unroll
        for (int kk = 0; kk < 32; kk += 8) {
            uint32_t a[4];
            a[0] = As[(wid * 16 + g)     * 36 + kk + tg];
            a[1] = As[(wid * 16 + g + 8) * 36 + kk + tg];
            a[2] = As[(wid * 16 + g)     * 36 + kk + tg + 4];
            a[3] = As[(wid * 16 + g + 8) * 36 + kk + tg + 4];
#pragma unroll
            for (int nr = 0; nr < 4; nr++) {
                uint32_t b[2];
                b[0] = ldcvt(&Bs[(nr * 8 + g) * 36 + kk + tg]);
                b[1] = ldcvt(&Bs[(nr * 8 + g) * 36 + kk + tg + 4]);
                mma_tf32(acc[nr], a, b);
            }
        }
    }

#pragma unroll
    for (int nr = 0; nr < 4; nr++)
#pragma unroll
        for (int e = 0; e < 4; e++) {
            int row = wid * 16 + g + ((e >= 2) ? 8 : 0);
            int cg  = n0 + nr * 8 + 2 * tg + (e & 1);
            if (cg < NCOL) g_Y[row * NCOL + cg] = acc[nr][e];
        }
}

// ---------------------------------------------------------------------------
// Kernel 3: assemble per-tuple K (LN) and V, both tf32-pre-rounded stores.
// ---------------------------------------------------------------------------
__global__ void __launch_bounds__(256) assemble_kernel(const float* __restrict__ bk,
                                                       const float* __restrict__ bv,
                                                       const float* __restrict__ gamma,
                                                       const float* __restrict__ beta) {
    int t   = blockIdx.x;
    int n   = blockIdx.y;
    int tid = threadIdx.x;
    int lane = tid & 31, warp = tid >> 5;

    int i0 = g_tup[t * 3 + 0];
    int i1 = g_tup[t * 3 + 1];
    int i2 = g_tup[t * 3 + 2];
    const float* y0 = g_Y + (n * SEQ + i0) * NCOL;
    const float* y1 = g_Y + (n * SEQ + i1) * NCOL;
    const float* y2 = g_Y + (n * SEQ + i2) * NCOL;

    float kr[5];
    float s1 = 0.0f, s2 = 0.0f;
#pragma unroll
    for (int k = 0; k < 5; k++) {
        int d = tid + k * 256;
        if (k < 4 || tid < (DOUT - 1024)) {
            float v = y0[d] + y1[DOUT + d] + y2[2 * DOUT + d] + bk[d];
            kr[k] = v; s1 += v; s2 += v * v;
            float vv = y0[KV_OFF + d] + y1[KV_OFF + DOUT + d] + y2[KV_OFF + 2 * DOUT + d] + bv[d];
            g_V[(n * NT + t) * DOUT + d] = rnd32(vv);
        } else kr[k] = 0.0f;
    }
    __shared__ float r1[8], r2[8];
    __shared__ float mu_s, rs_s;
#pragma unroll
    for (int o = 16; o; o >>= 1) {
        s1 += __shfl_xor_sync(0xffffffffu, s1, o);
        s2 += __shfl_xor_sync(0xffffffffu, s2, o);
    }
    if (lane == 0) { r1[warp] = s1; r2[warp] = s2; }
    __syncthreads();
    if (tid == 0) {
        float a = 0.0f, b = 0.0f;
        for (int w = 0; w < 8; w++) { a += r1[w]; b += r2[w]; }
        float mu = a / (float)DOUT;
        float var = b / (float)DOUT - mu * mu;
        mu_s = mu;
        rs_s = rsqrtf(var + LN_EPS);
    }
    __syncthreads();
    float mu = mu_s, rs = rs_s;
#pragma unroll
    for (int k = 0; k < 5; k++) {
        int d = tid + k * 256;
        if (k < 4 || tid < (DOUT - 1024))
            g_K[(n * NT + t) * DOUT + d] = rnd32((kr[k] - mu) * rs * gamma[d] + beta[d]);
    }
}

// ---------------------------------------------------------------------------
// Kernel 4: S = Kq . Kc^T * scale.  128x128 tile, warp 32x64, BK=32,
// 3-stage cp.async, fragments via ldmatrix.x4.
// ---------------------------------------------------------------------------
__global__ void __launch_bounds__(256) score_kernel(const int* __restrict__ labels) {
    extern __shared__ float smem[];
    uint32_t sbase = (uint32_t)__cvta_generic_to_shared(smem);

    int tid  = threadIdx.x;
    int lane = tid & 31;
    int wid  = tid >> 5;
    int wm   = wid & 3;
    int wn   = wid >> 2;
    int g    = lane >> 2;
    int tg   = lane & 3;

    int c  = blockIdx.z;
    int t0 = blockIdx.x * 128;
    int s0 = blockIdx.y * 128;
    int lab = labels[c];
    if (lab < 0) lab = 0; if (lab >= NSUP) lab = NSUP - 1;

    const float* Aq = g_K + (size_t)NSUP * NT * DOUT;
    const float* Bc = g_K + (size_t)lab * NT * DOUT;

    const float* gb[8]; uint32_t so[8]; int kthr[8]; bool sok[8];
#pragma unroll
    for (int l = 0; l < 8; l++) {
        int idx = tid + l * 256;
        if (idx < 1024) {
            int r = idx >> 3, q = idx & 7;
            int row = t0 + r;
            sok[l]  = row < NT;
            gb[l]   = Aq + (size_t)(sok[l] ? row : 0) * DOUT + 4 * q;
            so[l]   = r * 144 + q * 16;
            kthr[l] = DOUT - 4 * q;
        } else {
            int j = idx - 1024;
            int r = j >> 3, q = j & 7;
            int row = s0 + r;
            sok[l]  = row < NT;
            gb[l]   = Bc + (size_t)(sok[l] ? row : 0) * DOUT + 4 * q;
            so[l]   = SC_BOFF + r * 144 + q * 16;
            kthr[l] = DOUT - 4 * q;
        }
    }

    // ldmatrix per-lane address components (bytes within stage)
    uint32_t aoff0 = (uint32_t)((wm * 32 + (lane & 15)) * 144 + ((lane >> 4) * 4) * 4);
    uint32_t aoff1 = aoff0 + 16 * 144;
    uint32_t boffL = (uint32_t)(SC_BOFF + (wn * 64 + ((lane >> 3) & 3) * 8 + (lane & 7)) * 144);

    float acc[2][8][4];
#pragma unroll
    for (int mi = 0; mi < 2; mi++)
#pragma unroll
        for (int ni = 0; ni < 8; ni++)
#pragma unroll
            for (int e = 0; e < 4; e++) acc[mi][ni][e] = 0.0f;

    const int NKT = (DOUT + 31) / 32;   // 36
#pragma unroll
    for (int p = 0; p < 2; p++) {
        int k0 = p * 32;
        uint32_t boff = p * SC_STAGE_B;
#pragma unroll
        for (int l = 0; l < 8; l++)
            cp16(sbase + boff + so[l], gb[l] + k0, sok[l] && (k0 < kthr[l]));
        CP_COMMIT();
    }

    for (int kt = 0; kt < NKT; kt++) {
        CP_WAIT1();
        __syncthreads();
        int kp = kt + 2;
        if (kp < NKT) {
            int k0 = kp * 32;
            uint32_t boff = (kp % 3) * SC_STAGE_B;
#pragma unroll
            for (int l = 0; l < 8; l++)
                cp16(sbase + boff + so[l], gb[l] + k0, sok[l] && (k0 < kthr[l]));
        }
        CP_COMMIT();

        uint32_t stg = sbase + (kt % 3) * SC_STAGE_B;
#pragma unroll
        for (int kk = 0; kk < 32; kk += 8) {
            uint32_t a[2][4];
            ldsm4(stg + aoff0 + kk * 4, a[0][0], a[0][1], a[0][2], a[0][3]);
            ldsm4(stg + aoff1 + kk * 4, a[1][0], a[1][1], a[1][2], a[1][3]);
            uint32_t b[8][2];
#pragma unroll
            for (int nb = 0; nb < 2; nb++)
#pragma unroll
                for (int kg = 0; kg < 2; kg++) {
                    uint32_t r0, r1, r2, r3;
                    ldsm4(stg + boffL + nb * (32 * 144) + (kk + kg * 4) * 4,
                          r0, r1, r2, r3);
                    b[nb * 4 + 0][kg] = r0; b[nb * 4 + 1][kg] = r1;
                    b[nb * 4 + 2][kg] = r2; b[nb * 4 + 3][kg] = r3;
                }
#pragma unroll
            for (int mi = 0; mi < 2; mi++)
#pragma unroll
                for (int ni = 0; ni < 8; ni++)
                    mma_tf32(acc[mi][ni], a[mi], b[ni]);
        }
    }

    const float scale = rsqrtf((float)DOUT);
    float* Sc = g_S + (size_t)c * NT * NT;
#pragma unroll
    for (int mi = 0; mi < 2; mi++)
#pragma unroll
        for (int ni = 0; ni < 8; ni++)
#pragma unroll
            for (int e = 0; e < 4; e++) {
                int t = t0 + wm * 32 + mi * 16 + g + ((e >= 2) ? 8 : 0);
                int s = s0 + wn * 64 + ni * 8 + 2 * tg + (e & 1);
                if (t < NT && s < NT) Sc[(size_t)t * NT + s] = acc[mi][ni][e] * scale;
            }
}

// ---------------------------------------------------------------------------
// Kernel 5: row softmax; attn stored tf32-pre-rounded.
// ---------------------------------------------------------------------------
__global__ void __launch_bounds__(256) softmax_kernel() {
    int lane = threadIdx.x & 31;
    int row  = blockIdx.x * 8 + (threadIdx.x >> 5);
    if (row >= NSUP * NT) return;
    float* r = g_S + (size_t)row * NT;

    float m = -1e30f;
    for (int s = lane; s < NT; s += 32) m = fmaxf(m, r[s]);
#pragma unroll
    for (int o = 16; o; o >>= 1) m = fmaxf(m, __shfl_xor_sync(0xffffffffu, m, o));
    float sum = 0.0f;
    float ev[NT / 32 + 1];
    int cnt = 0;
    for (int s = lane; s < NT; s += 32) {
        float e = expf(r[s] - m);
        ev[cnt++] = e;
        sum += e;
    }
#pragma unroll
    for (int o = 16; o; o >>= 1) sum += __shfl_xor_sync(0xffffffffu, sum, o);
    float inv = 1.0f / sum;
    cnt = 0;
    for (int s = lane; s < NT; s += 32) r[s] = rnd32(ev[cnt++] * inv);
}

// ---------------------------------------------------------------------------
// Kernel 6: P = attn @ Vc, accumulate (q_v - P)^2.  128x128 tile, BK=32,
// 3-stage.  A via ldmatrix; B plain LDS (g_V pre-rounded).
// ---------------------------------------------------------------------------
__global__ void __launch_bounds__(256) dist_kernel(const int* __restrict__ labels,
                                                   float* __restrict__ out) {
    extern __shared__ float smem[];
    __shared__ float red[8];
    uint32_t sbase = (uint32_t)__cvta_generic_to_shared(smem);
    const uint32_t* S = (const uint32_t*)smem;

    int tid  = threadIdx.x;
    int lane = tid & 31;
    int wid  = tid >> 5;
    int wm   = wid & 3;
    int wn   = wid >> 2;
    int g    = lane >> 2;
    int tg   = lane & 3;

    int c  = blockIdx.z;
    int t0 = blockIdx.x * 128;
    int d0 = blockIdx.y * 128;
    int lab = labels[c];
    if (lab < 0) lab = 0; if (lab >= NSUP) lab = NSUP - 1;

    const float* Ag = g_S + (size_t)c * NT * NT;
    const float* Vc = g_V + (size_t)lab * NT * DOUT;
    const float* Vq = g_V + (size_t)NSUP * NT * DOUT;

    const float* gb[8]; uint32_t so[8]; int gstep[8]; int kthr[8]; bool sok[8];
#pragma unroll
    for (int l = 0; l < 8; l++) {
        int idx = tid + l * 256;
        if (idx < 1024) {
            int r = idx >> 3, q = idx & 7;
            int row = t0 + r;
            sok[l]   = row < NT;
            gb[l]    = Ag + (size_t)(sok[l] ? row : 0) * NT + 4 * q;
            so[l]    = r * 144 + q * 16;
            gstep[l] = 1;
            kthr[l]  = NT - 4 * q;
        } else {
            int j = idx - 1024;
            int r = j >> 5, q = j & 31;
            int d = d0 + 4 * q;
            sok[l]   = d < DOUT;
            gb[l]    = Vc + (size_t)r * DOUT + (sok[l] ? d : 0);
            so[l]    = DS_BOFF + r * 544 + q * 16;
            gstep[l] = DOUT;
            kthr[l]  = NT - r;
        }
    }

    uint32_t aoff0 = (uint32_t)((wm * 32 + (lane & 15)) * 144 + ((lane >> 4) * 4) * 4);
    uint32_t aoff1 = aoff0 + 16 * 144;

    float acc[2][8][4];
#pragma unroll
    for (int mi = 0; mi < 2; mi++)
#pragma unroll
        for (int ni = 0; ni < 8; ni++)
#pragma unroll
            for (int e = 0; e < 4; e++) acc[mi][ni][e] = 0.0f;

    const int NKT = (NT + 31) / 32;   // 18
#pragma unroll
    for (int p = 0; p < 2; p++) {
        int k0 = p * 32;
        uint32_t boff = p * DS_STAGE_B;
#pragma unroll
        for (int l = 0; l < 8; l++)
            cp16(sbase + boff + so[l], gb[l] + (size_t)k0 * gstep[l],
                 sok[l] && (k0 < kthr[l]));
        CP_COMMIT();
    }

    for (int kt = 0; kt < NKT; kt++) {
        CP_WAIT1();
        __syncthreads();
        int kp = kt + 2;
        if (kp < NKT) {
            int k0 = kp * 32;
            uint32_t boff = (kp % 3) * DS_STAGE_B;
#pragma unroll
            for (int l = 0; l < 8; l++)
                cp16(sbase + boff + so[l], gb[l] + (size_t)k0 * gstep[l],
                     sok[l] && (k0 < kthr[l]));
        }
        CP_COMMIT();

        uint32_t stg = sbase + (kt % 3) * DS_STAGE_B;
        const uint32_t* Bs = S + (kt % 3) * DS_STAGE_F + 4608;   // [k][d], stride 136
#pragma unroll
        for (int kk = 0; kk < 32; kk += 8) {
            uint32_t a[2][4];
            ldsm4(stg + aoff0 + kk * 4, a[0][0], a[0][1], a[0][2], a[0][3]);
            ldsm4(stg + aoff1 + kk * 4, a[1][0], a[1][1], a[1][2], a[1][3]);
            uint32_t b[8][2];
#pragma unroll
            for (int ni = 0; ni < 8; ni++) {
                int ncol = wn * 64 + ni * 8 + g;
                b[ni][0] = Bs[(kk + tg)     * 136 + ncol];
                b[ni][1] = Bs[(kk + tg + 4) * 136 + ncol];
            }
#pragma unroll
            for (int mi = 0; mi < 2; mi++)
#pragma unroll
                for (int ni = 0; ni < 8; ni++)
                    mma_tf32(acc[mi][ni], a[mi], b[ni]);
        }
    }

    float loc = 0.0f;
#pragma unroll
    for (int mi = 0; mi < 2; mi++)
#pragma unroll
        for (int ni = 0; ni < 8; ni++)
#pragma unroll
            for (int e = 0; e < 4; e++) {
                int t = t0 + wm * 32 + mi * 16 + g + ((e >= 2) ? 8 : 0);
                int d = d0 + wn * 64 + ni * 8 + 2 * tg + (e & 1);
                if (t < NT && d < DOUT) {
                    float diff = Vq[(size_t)t * DOUT + d] - acc[mi][ni][e];
                    loc += diff * diff;
                }
            }
#pragma unroll
    for (int o = 16; o; o >>= 1) loc += __shfl_xor_sync(0xffffffffu, loc, o);
    if (lane == 0) red[wid] = loc;
    __syncthreads();
    if (tid == 0) {
        float tot = 0.0f;
        for (int w = 0; w < 8; w++) tot += red[w];
        atomicAdd(out + c, -tot / (float)NT);
    }
}

// ---------------------------------------------------------------------------
// Launch
// ---------------------------------------------------------------------------
extern "C" void kernel_launch(void* const* d_in, const int* in_sizes, int n_in,
                              void* d_out, int out_size) {
    const float* sup   = (const float*)d_in[0];
    const float* qry   = (const float*)d_in[1];
    const int*   lab   = (const int*)d_in[2];
    const float* wk    = (const float*)d_in[3];
    const float* bk    = (const float*)d_in[4];
    const float* wv    = (const float*)d_in[5];
    const float* bv    = (const float*)d_in[6];
    const float* gamma = (const float*)d_in[7];
    const float* beta  = (const float*)d_in[8];
    float* out = (float*)d_out;

    cudaFuncSetAttribute(proj_kernel,  cudaFuncAttributeMaxDynamicSharedMemorySize, SMEM_BYTES);
    cudaFuncSetAttribute(score_kernel, cudaFuncAttributeMaxDynamicSharedMemorySize, SC_SMEM);
    cudaFuncSetAttribute(dist_kernel,  cudaFuncAttributeMaxDynamicSharedMemorySize, DS_SMEM);

    build_x_kernel<<<NROWS, 256>>>(sup, qry, out);
    proj_kernel<<<(NCOL + 31) / 32, 192, SMEM_BYTES>>>(wk, wv);
    assemble_kernel<<<dim3(NT, NSEQ), 256>>>(bk, bv, gamma, beta);
    score_kernel<<<dim3(5, 5, NSUP), 256, SC_SMEM>>>(lab);
    softmax_kernel<<<(NSUP * NT + 7) / 8, 256>>>();
    dist_kernel<<<dim3(5, 9, NSUP), 256, DS_SMEM>>>(lab, out);
}

// round 13
// speedup vs baseline: 4.0079x; 1.2447x over previous
#include <cuda_runtime.h>
#include <cuda_bf16.h>
#include <math.h>
#include <stdint.h>

// ---------------------------------------------------------------------------
// Problem constants
// ---------------------------------------------------------------------------
#define SEQ    16
#define DIN    2048
#define DOUT   1128
#define NT     560          // C(16,3)
#define NSUP   5
#define NSEQ   6            // 5 support + 1 query
#define NROWS  96           // 6 seqs * 16 frames
#define NCOL   6768         // 2 (K,V) * 3 parts * 1128
#define KV_OFF 3384
#define LN_EPS 1e-5f

// proj pipeline (tf32, unchanged)
#define STAGE_F     4608
#define STAGE_B     (STAGE_F * 4)
#define SMEM_BYTES  (4 * STAGE_B)        // 73728 B

// score pipeline (bf16): A 128 rows x 80 B + B 128 rows x 80 B per stage
#define SC_STAGE_B  20480
#define SC_SMEM     (3 * SC_STAGE_B)     // 61440
#define SC_BOFF     10240

// dist pipeline (bf16): A 128 x 80 B + B 32 x 272 B per stage
#define DS_STAGE_B  18944
#define DS_SMEM     (3 * DS_STAGE_B)     // 56832
#define DS_BOFF     10240

// ---------------------------------------------------------------------------
// Scratch (device globals -- no allocation allowed)
// ---------------------------------------------------------------------------
__device__ float          g_X[NROWS * DIN];        // tf32-pre-rounded
__device__ float          g_Y[NROWS * NCOL];       // full fp32
__device__ __nv_bfloat16  g_Kb[NSEQ * NT * DOUT];  // bf16 keys (LN output)
__device__ float          g_V[NSEQ * NT * DOUT];   // fp32 values (epilogue)
__device__ __nv_bfloat16  g_Vb[NSEQ * NT * DOUT];  // bf16 values (MMA operand)
__device__ float          g_S[NSUP * NT * NT];     // fp32 scores
__device__ __nv_bfloat16  g_A[NSUP * NT * NT];     // bf16 attention weights
__device__ int            g_tup[NT * 3];

// ---------------------------------------------------------------------------
// helpers
// ---------------------------------------------------------------------------
__device__ __forceinline__ void mma_tf32(float* c, const uint32_t* a, const uint32_t* b) {
    asm volatile(
        "mma.sync.aligned.m16n8k8.row.col.f32.tf32.tf32.f32 "
        "{%0,%1,%2,%3}, {%4,%5,%6,%7}, {%8,%9}, {%0,%1,%2,%3};\n"
        : "+f"(c[0]), "+f"(c[1]), "+f"(c[2]), "+f"(c[3])
        : "r"(a[0]), "r"(a[1]), "r"(a[2]), "r"(a[3]), "r"(b[0]), "r"(b[1]));
}

__device__ __forceinline__ void mma_bf16(float* c, const uint32_t* a, const uint32_t* b) {
    asm volatile(
        "mma.sync.aligned.m16n8k16.row.col.f32.bf16.bf16.f32 "
        "{%0,%1,%2,%3}, {%4,%5,%6,%7}, {%8,%9}, {%0,%1,%2,%3};\n"
        : "+f"(c[0]), "+f"(c[1]), "+f"(c[2]), "+f"(c[3])
        : "r"(a[0]), "r"(a[1]), "r"(a[2]), "r"(a[3]), "r"(b[0]), "r"(b[1]));
}

__device__ __forceinline__ float rnd32(float f) {
    uint32_t r;
    asm("cvt.rna.tf32.f32 %0, %1;" : "=r"(r) : "f"(f));
    return __uint_as_float(r);
}

__device__ __forceinline__ uint32_t ldcvt(const uint32_t* p) {
    float f = __uint_as_float(*p);
    uint32_t r;
    asm("cvt.rna.tf32.f32 %0, %1;" : "=r"(r) : "f"(f));
    return r;
}

__device__ __forceinline__ void ldsm4(uint32_t addr, uint32_t& r0, uint32_t& r1,
                                      uint32_t& r2, uint32_t& r3) {
    asm volatile("ldmatrix.sync.aligned.m8n8.x4.shared.b16 {%0,%1,%2,%3}, [%4];"
                 : "=r"(r0), "=r"(r1), "=r"(r2), "=r"(r3) : "r"(addr));
}

__device__ __forceinline__ void ldsm4t(uint32_t addr, uint32_t& r0, uint32_t& r1,
                                       uint32_t& r2, uint32_t& r3) {
    asm volatile("ldmatrix.sync.aligned.m8n8.x4.trans.shared.b16 {%0,%1,%2,%3}, [%4];"
                 : "=r"(r0), "=r"(r1), "=r"(r2), "=r"(r3) : "r"(addr));
}

__device__ __forceinline__ void cp16(uint32_t saddr, const void* g, bool p) {
    asm volatile("cp.async.cg.shared.global [%0], [%1], 16, %2;"
                 :: "r"(saddr), "l"(g), "r"(p ? 16 : 0));
}
#define CP_COMMIT()  asm volatile("cp.async.commit_group;")
#define CP_WAIT1()   asm volatile("cp.async.wait_group 1;")
#define CP_WAIT2()   asm volatile("cp.async.wait_group 2;")

// ---------------------------------------------------------------------------
// Kernel 1: X = input + positional encoding (tf32 pre-rounded).
// ---------------------------------------------------------------------------
__global__ void build_x_kernel(const float* __restrict__ sup,
                               const float* __restrict__ qry,
                               float* __restrict__ out) {
    int r   = blockIdx.x;
    int tid = threadIdx.x;
    if (r == 0) {
        if (tid == 0) {
            int idx = 0;
            for (int i = 0; i < SEQ; i++)
                for (int j = i + 1; j < SEQ; j++)
                    for (int k = j + 1; k < SEQ; k++) {
                        g_tup[idx * 3 + 0] = i;
                        g_tup[idx * 3 + 1] = j;
                        g_tup[idx * 3 + 2] = k;
                        idx++;
                    }
        }
        if (tid < NSUP) out[tid] = 0.0f;
    }
    int f   = (r < 80) ? (r & 15) : (r - 80);
    const float* src = (r < 80) ? (sup + r * DIN) : (qry + (r - 80) * DIN);
    const float cexp = -logf(10000.0f) / (float)DIN;
    for (int j = tid; j < DIN / 2; j += blockDim.x) {
        float div = expf((float)(2 * j) * cexp);
        float ang = (float)f * div;
        g_X[r * DIN + 2 * j]     = rnd32(src[2 * j]     + 0.1f * sinf(ang));
        g_X[r * DIN + 2 * j + 1] = rnd32(src[2 * j + 1] + 0.1f * cosf(ang));
    }
}

// ---------------------------------------------------------------------------
// Kernel 2: Y[96,6768] = X[96,2048] @ W^T.  tf32 MMA (unchanged).
// ---------------------------------------------------------------------------
__global__ void __launch_bounds__(192) proj_kernel(const float* __restrict__ wk,
                                                   const float* __restrict__ wv) {
    extern __shared__ float smem[];
    uint32_t sbase = (uint32_t)__cvta_generic_to_shared(smem);
    const uint32_t* S = (const uint32_t*)smem;

    int tid  = threadIdx.x;
    int lane = tid & 31;
    int wid  = tid >> 5;
    int g    = lane >> 2;
    int tg   = lane & 3;
    int n0   = blockIdx.x * 32;

    const float* gb[6]; uint32_t so[6]; bool ex[6]; bool sok[6];
#pragma unroll
    for (int l = 0; l < 6; l++) {
        int idx = tid + l * 192;
        ex[l] = idx < 1024;
        gb[l] = g_X; so[l] = 0; sok[l] = false;
        if (!ex[l]) continue;
        if (idx < 768) {
            int r = idx >> 3, q = idx & 7;
            gb[l]  = g_X + r * DIN + 4 * q;
            so[l]  = r * 144 + q * 16;
            sok[l] = true;
        } else {
            int j = idx - 768;
            int r = j >> 3, q = j & 7;
            int cg = n0 + r;
            so[l] = 13824 + r * 144 + q * 16;
            if (cg < NCOL) {
                const float* base; int p, rr;
                if (cg < KV_OFF) { p = cg / DOUT; rr = cg - p * DOUT; base = wk; }
                else             { int c2 = cg - KV_OFF; p = c2 / DOUT; rr = c2 - p * DOUT; base = wv; }
                gb[l]  = base + rr * (3 * DIN) + p * DIN + 4 * q;
                sok[l] = true;
            }
        }
    }

    float acc[4][4];
#pragma unroll
    for (int nr = 0; nr < 4; nr++)
#pragma unroll
        for (int e = 0; e < 4; e++) acc[nr][e] = 0.0f;

    const int NKT = DIN / 32;   // 64
#pragma unroll
    for (int p = 0; p < 3; p++) {
        int k0 = p * 32;
        uint32_t boff = p * STAGE_B;
#pragma unroll
        for (int l = 0; l < 6; l++)
            if (ex[l]) cp16(sbase + boff + so[l], gb[l] + k0, sok[l]);
        CP_COMMIT();
    }

    for (int kt = 0; kt < NKT; kt++) {
        CP_WAIT2();
        __syncthreads();
        int kp = kt + 3;
        if (kp < NKT) {
            int k0 = kp * 32;
            uint32_t boff = (kp & 3) * STAGE_B;
#pragma unroll
            for (int l = 0; l < 6; l++)
                if (ex[l]) cp16(sbase + boff + so[l], gb[l] + k0, sok[l]);
        }
        CP_COMMIT();

        const uint32_t* As = S + (kt & 3) * STAGE_F;
        const uint32_t* Bs = As + 3456;
#pragma unroll
        for (int kk = 0; kk < 32; kk += 8) {
            uint32_t a[4];
            a[0] = As[(wid * 16 + g)     * 36 + kk + tg];
            a[1] = As[(wid * 16 + g + 8) * 36 + kk + tg];
            a[2] = As[(wid * 16 + g)     * 36 + kk + tg + 4];
            a[3] = As[(wid * 16 + g + 8) * 36 + kk + tg + 4];
#pragma unroll
            for (int nr = 0; nr < 4; nr++) {
                uint32_t b[2];
                b[0] = ldcvt(&Bs[(nr * 8 + g) * 36 + kk + tg]);
                b[1] = ldcvt(&Bs[(nr * 8 + g) * 36 + kk + tg + 4]);
                mma_tf32(acc[nr], a, b);
            }
        }
    }

#pragma unroll
    for (int nr = 0; nr < 4; nr++)
#pragma unroll
        for (int e = 0; e < 4; e++) {
            int row = wid * 16 + g + ((e >= 2) ? 8 : 0);
            int cg  = n0 + nr * 8 + 2 * tg + (e & 1);
            if (cg < NCOL) g_Y[row * NCOL + cg] = acc[nr][e];
        }
}

// ---------------------------------------------------------------------------
// Kernel 3: assemble per-tuple K (LN -> bf16) and V (fp32 + bf16).
// ---------------------------------------------------------------------------
__global__ void __launch_bounds__(256) assemble_kernel(const float* __restrict__ bk,
                                                       const float* __restrict__ bv,
                                                       const float* __restrict__ gamma,
                                                       const float* __restrict__ beta) {
    int t   = blockIdx.x;
    int n   = blockIdx.y;
    int tid = threadIdx.x;
    int lane = tid & 31, warp = tid >> 5;

    int i0 = g_tup[t * 3 + 0];
    int i1 = g_tup[t * 3 + 1];
    int i2 = g_tup[t * 3 + 2];
    const float* y0 = g_Y + (n * SEQ + i0) * NCOL;
    const float* y1 = g_Y + (n * SEQ + i1) * NCOL;
    const float* y2 = g_Y + (n * SEQ + i2) * NCOL;

    float kr[5];
    float s1 = 0.0f, s2 = 0.0f;
#pragma unroll
    for (int k = 0; k < 5; k++) {
        int d = tid + k * 256;
        if (k < 4 || tid < (DOUT - 1024)) {
            float v = y0[d] + y1[DOUT + d] + y2[2 * DOUT + d] + bk[d];
            kr[k] = v; s1 += v; s2 += v * v;
            float vv = y0[KV_OFF + d] + y1[KV_OFF + DOUT + d] + y2[KV_OFF + 2 * DOUT + d] + bv[d];
            g_V[(n * NT + t) * DOUT + d]  = vv;
            g_Vb[(n * NT + t) * DOUT + d] = __float2bfloat16_rn(vv);
        } else kr[k] = 0.0f;
    }
    __shared__ float r1[8], r2[8];
    __shared__ float mu_s, rs_s;
#pragma unroll
    for (int o = 16; o; o >>= 1) {
        s1 += __shfl_xor_sync(0xffffffffu, s1, o);
        s2 += __shfl_xor_sync(0xffffffffu, s2, o);
    }
    if (lane == 0) { r1[warp] = s1; r2[warp] = s2; }
    __syncthreads();
    if (tid == 0) {
        float a = 0.0f, b = 0.0f;
        for (int w = 0; w < 8; w++) { a += r1[w]; b += r2[w]; }
        float mu = a / (float)DOUT;
        float var = b / (float)DOUT - mu * mu;
        mu_s = mu;
        rs_s = rsqrtf(var + LN_EPS);
    }
    __syncthreads();
    float mu = mu_s, rs = rs_s;
#pragma unroll
    for (int k = 0; k < 5; k++) {
        int d = tid + k * 256;
        if (k < 4 || tid < (DOUT - 1024))
            g_Kb[(n * NT + t) * DOUT + d] =
                __float2bfloat16_rn((kr[k] - mu) * rs * gamma[d] + beta[d]);
    }
}

// ---------------------------------------------------------------------------
// Kernel 4: S = Kq . Kc^T * scale.  bf16 m16n8k16.  128x128 tile, warp 32x64,
// BK=32 halves, 3-stage cp.async, ldmatrix fragments.
// Row stride 80 B (40 halves) -- LDSM conflict-free.
// ---------------------------------------------------------------------------
__global__ void __launch_bounds__(256) score_kernel(const int* __restrict__ labels) {
    extern __shared__ float smem[];
    uint32_t sbase = (uint32_t)__cvta_generic_to_shared(smem);

    int tid  = threadIdx.x;
    int lane = tid & 31;
    int wid  = tid >> 5;
    int wm   = wid & 3;
    int wn   = wid >> 2;
    int g    = lane >> 2;
    int tg   = lane & 3;

    int c  = blockIdx.z;
    int t0 = blockIdx.x * 128;
    int s0 = blockIdx.y * 128;
    int lab = labels[c];
    if (lab < 0) lab = 0; if (lab >= NSUP) lab = NSUP - 1;

    const __nv_bfloat16* Aq = g_Kb + (size_t)NSUP * NT * DOUT;
    const __nv_bfloat16* Bc = g_Kb + (size_t)lab * NT * DOUT;

    // loader: 512 A granules (128 rows x 4) + 512 B granules; 4 slots/thread
    const __nv_bfloat16* gb[4]; uint32_t so[4]; int kthr[4]; bool sok[4];
#pragma unroll
    for (int l = 0; l < 4; l++) {
        int idx = tid + l * 256;
        if (idx < 512) {
            int r = idx >> 2, q = idx & 3;
            int row = t0 + r;
            sok[l]  = row < NT;
            gb[l]   = Aq + (size_t)(sok[l] ? row : 0) * DOUT + 8 * q;
            so[l]   = r * 80 + q * 16;
            kthr[l] = DOUT - 8 * q;
        } else {
            int j = idx - 512;
            int r = j >> 2, q = j & 3;
            int row = s0 + r;
            sok[l]  = row < NT;
            gb[l]   = Bc + (size_t)(sok[l] ? row : 0) * DOUT + 8 * q;
            so[l]   = SC_BOFF + r * 80 + q * 16;
            kthr[l] = DOUT - 8 * q;
        }
    }

    // ldmatrix lane addresses (bytes within stage)
    uint32_t aoff0 = (uint32_t)((wm * 32 + (lane & 15)) * 80 + (lane >> 4) * 16);
    uint32_t aoff1 = aoff0 + 16 * 80;
    uint32_t boffL = (uint32_t)(SC_BOFF + (wn * 64 + (lane >> 4) * 8 + (lane & 7)) * 80
                                + ((lane >> 3) & 1) * 16);

    float acc[2][8][4];
#pragma unroll
    for (int mi = 0; mi < 2; mi++)
#pragma unroll
        for (int ni = 0; ni < 8; ni++)
#pragma unroll
            for (int e = 0; e < 4; e++) acc[mi][ni][e] = 0.0f;

    const int NKT = (DOUT + 31) / 32;   // 36
#pragma unroll
    for (int p = 0; p < 2; p++) {
        int k0 = p * 32;
        uint32_t boff = p * SC_STAGE_B;
#pragma unroll
        for (int l = 0; l < 4; l++)
            cp16(sbase + boff + so[l], gb[l] + k0, sok[l] && (k0 < kthr[l]));
        CP_COMMIT();
    }

    for (int kt = 0; kt < NKT; kt++) {
        CP_WAIT1();
        __syncthreads();
        int kp = kt + 2;
        if (kp < NKT) {
            int k0 = kp * 32;
            uint32_t boff = (kp % 3) * SC_STAGE_B;
#pragma unroll
            for (int l = 0; l < 4; l++)
                cp16(sbase + boff + so[l], gb[l] + k0, sok[l] && (k0 < kthr[l]));
        }
        CP_COMMIT();

        uint32_t stg = sbase + (kt % 3) * SC_STAGE_B;
#pragma unroll
        for (int kq = 0; kq < 2; kq++) {          // two k16 groups, +32 B each
            uint32_t koff = kq * 32;
            uint32_t a[2][4];
            ldsm4(stg + aoff0 + koff, a[0][0], a[0][1], a[0][2], a[0][3]);
            ldsm4(stg + aoff1 + koff, a[1][0], a[1][1], a[1][2], a[1][3]);
            uint32_t b[8][2];
#pragma unroll
            for (int nb = 0; nb < 4; nb++) {      // each covers 2 n8-tiles
                uint32_t r0, r1, r2, r3;
                ldsm4(stg + boffL + nb * (16 * 80) + koff, r0, r1, r2, r3);
                b[nb * 2 + 0][0] = r0; b[nb * 2 + 0][1] = r1;
                b[nb * 2 + 1][0] = r2; b[nb * 2 + 1][1] = r3;
            }
#pragma unroll
            for (int mi = 0; mi < 2; mi++)
#pragma unroll
                for (int ni = 0; ni < 8; ni++)
                    mma_bf16(acc[mi][ni], a[mi], b[ni]);
        }
    }

    const float scale = rsqrtf((float)DOUT);
    float* Sc = g_S + (size_t)c * NT * NT;
#pragma unroll
    for (int mi = 0; mi < 2; mi++)
#pragma unroll
        for (int ni = 0; ni < 8; ni++)
#pragma unroll
            for (int e = 0; e < 4; e++) {
                int t = t0 + wm * 32 + mi * 16 + g + ((e >= 2) ? 8 : 0);
                int s = s0 + wn * 64 + ni * 8 + 2 * tg + (e & 1);
                if (t < NT && s < NT) Sc[(size_t)t * NT + s] = acc[mi][ni][e] * scale;
            }
}

// ---------------------------------------------------------------------------
// Kernel 5: row softmax; attn written to g_A as bf16.
// ---------------------------------------------------------------------------
__global__ void __launch_bounds__(256) softmax_kernel() {
    int lane = threadIdx.x & 31;
    int row  = blockIdx.x * 8 + (threadIdx.x >> 5);
    if (row >= NSUP * NT) return;
    const float* r = g_S + (size_t)row * NT;
    __nv_bfloat16* a = g_A + (size_t)row * NT;

    float m = -1e30f;
    for (int s = lane; s < NT; s += 32) m = fmaxf(m, r[s]);
#pragma unroll
    for (int o = 16; o; o >>= 1) m = fmaxf(m, __shfl_xor_sync(0xffffffffu, m, o));
    float sum = 0.0f;
    float ev[NT / 32 + 1];
    int cnt = 0;
    for (int s = lane; s < NT; s += 32) {
        float e = expf(r[s] - m);
        ev[cnt++] = e;
        sum += e;
    }
#pragma unroll
    for (int o = 16; o; o >>= 1) sum += __shfl_xor_sync(0xffffffffu, sum, o);
    float inv = 1.0f / sum;
    cnt = 0;
    for (int s = lane; s < NT; s += 32) a[s] = __float2bfloat16_rn(ev[cnt++] * inv);
}

// ---------------------------------------------------------------------------
// Kernel 6: P = attn @ Vc (bf16 MMA), accumulate (q_v - P)^2 with fp32 Vq.
// 128(t) x 128(d) tile, BK=32 over s, 3-stage.  A ldmatrix, B ldmatrix.trans.
// ---------------------------------------------------------------------------
__global__ void __launch_bounds__(256) dist_kernel(const int* __restrict__ labels,
                                                   float* __restrict__ out) {
    extern __shared__ float smem[];
    __shared__ float red[8];
    uint32_t sbase = (uint32_t)__cvta_generic_to_shared(smem);

    int tid  = threadIdx.x;
    int lane = tid & 31;
    int wid  = tid >> 5;
    int wm   = wid & 3;
    int wn   = wid >> 2;
    int g    = lane >> 2;
    int tg   = lane & 3;

    int c  = blockIdx.z;
    int t0 = blockIdx.x * 128;
    int d0 = blockIdx.y * 128;
    int lab = labels[c];
    if (lab < 0) lab = 0; if (lab >= NSUP) lab = NSUP - 1;

    const __nv_bfloat16* Ag = g_A + (size_t)c * NT * NT;
    const __nv_bfloat16* Vc = g_Vb + (size_t)lab * NT * DOUT;
    const float*         Vq = g_V + (size_t)NSUP * NT * DOUT;

    // loader: A 512 granules (128 t-rows x 4), B 512 (32 s-rows x 16)
    const __nv_bfloat16* gb[4]; uint32_t so[4]; int gstep[4]; int kthr[4]; bool sok[4];
#pragma unroll
    for (int l = 0; l < 4; l++) {
        int idx = tid + l * 256;
        if (idx < 512) {
            int r = idx >> 2, q = idx & 3;
            int row = t0 + r;
            sok[l]   = row < NT;
            gb[l]    = Ag + (size_t)(sok[l] ? row : 0) * NT + 8 * q;
            so[l]    = r * 80 + q * 16;
            gstep[l] = 1;
            kthr[l]  = NT - 8 * q;
        } else {
            int j = idx - 512;
            int r = j >> 4, q = j & 15;
            int d = d0 + 8 * q;
            sok[l]   = d < DOUT;
            gb[l]    = Vc + (size_t)r * DOUT + (sok[l] ? d : 0);
            so[l]    = DS_BOFF + r * 272 + q * 16;
            gstep[l] = DOUT;
            kthr[l]  = NT - r;
        }
    }

    uint32_t aoff0 = (uint32_t)((wm * 32 + (lane & 15)) * 80 + (lane >> 4) * 16);
    uint32_t aoff1 = aoff0 + 16 * 80;
    // B trans: lane addresses k-rows of [k][n] tile
    uint32_t boffL = (uint32_t)(DS_BOFF + (((lane >> 3) & 1) * 8 + (lane & 7)) * 272
                                + (wn * 64 + (lane >> 4) * 8) * 2);

    float acc[2][8][4];
#pragma unroll
    for (int mi = 0; mi < 2; mi++)
#pragma unroll
        for (int ni = 0; ni < 8; ni++)
#pragma unroll
            for (int e = 0; e < 4; e++) acc[mi][ni][e] = 0.0f;

    const int NKT = (NT + 31) / 32;   // 18
#pragma unroll
    for (int p = 0; p < 2; p++) {
        int k0 = p * 32;
        uint32_t boff = p * DS_STAGE_B;
#pragma unroll
        for (int l = 0; l < 4; l++)
            cp16(sbase + boff + so[l], gb[l] + (size_t)k0 * gstep[l],
                 sok[l] && (k0 < kthr[l]));
        CP_COMMIT();
    }

    for (int kt = 0; kt < NKT; kt++) {
        CP_WAIT1();
        __syncthreads();
        int kp = kt + 2;
        if (kp < NKT) {
            int k0 = kp * 32;
            uint32_t boff = (kp % 3) * DS_STAGE_B;
#pragma unroll
            for (int l = 0; l < 4; l++)
                cp16(sbase + boff + so[l], gb[l] + (size_t)k0 * gstep[l],
                     sok[l] && (k0 < kthr[l]));
        }
        CP_COMMIT();

        uint32_t stg = sbase + (kt % 3) * DS_STAGE_B;
#pragma unroll
        for (int kq = 0; kq < 2; kq++) {
            uint32_t koff  = kq * 32;          // A: +32 B along s
            uint32_t krow  = kq * 16 * 272;    // B: +16 k-rows
            uint32_t a[2][4];
            ldsm4(stg + aoff0 + koff, a[0][0], a[0][1], a[0][2], a[0][3]);
            ldsm4(stg + aoff1 + koff, a[1][0], a[1][1], a[1][2], a[1][3]);
            uint32_t b[8][2];
#pragma unroll
            for (int nb = 0; nb < 4; nb++) {
                uint32_t r0, r1, r2, r3;
                ldsm4t(stg + boffL + krow + nb * 32, r0, r1, r2, r3);
                b[nb * 2 + 0][0] = r0; b[nb * 2 + 0][1] = r1;
                b[nb * 2 + 1][0] = r2; b[nb * 2 + 1][1] = r3;
            }
#pragma unroll
            for (int mi = 0; mi < 2; mi++)
#pragma unroll
                for (int ni = 0; ni < 8; ni++)
                    mma_bf16(acc[mi][ni], a[mi], b[ni]);
        }
    }

    float loc = 0.0f;
#pragma unroll
    for (int mi = 0; mi < 2; mi++)
#pragma unroll
        for (int ni = 0; ni < 8; ni++)
#pragma unroll
            for (int e = 0; e < 4; e++) {
                int t = t0 + wm * 32 + mi * 16 + g + ((e >= 2) ? 8 : 0);
                int d = d0 + wn * 64 + ni * 8 + 2 * tg + (e & 1);
                if (t < NT && d < DOUT) {
                    float diff = Vq[(size_t)t * DOUT + d] - acc[mi][ni][e];
                    loc += diff * diff;
                }
            }
#pragma unroll
    for (int o = 16; o; o >>= 1) loc += __shfl_xor_sync(0xffffffffu, loc, o);
    if (lane == 0) red[wid] = loc;
    __syncthreads();
    if (tid == 0) {
        float tot = 0.0f;
        for (int w = 0; w < 8; w++) tot += red[w];
        atomicAdd(out + c, -tot / (float)NT);
    }
}

// ---------------------------------------------------------------------------
// Launch
// ---------------------------------------------------------------------------
extern "C" void kernel_launch(void* const* d_in, const int* in_sizes, int n_in,
                              void* d_out, int out_size) {
    const float* sup   = (const float*)d_in[0];
    const float* qry   = (const float*)d_in[1];
    const int*   lab   = (const int*)d_in[2];
    const float* wk    = (const float*)d_in[3];
    const float* bk    = (const float*)d_in[4];
    const float* wv    = (const float*)d_in[5];
    const float* bv    = (const float*)d_in[6];
    const float* gamma = (const float*)d_in[7];
    const float* beta  = (const float*)d_in[8];
    float* out = (float*)d_out;

    cudaFuncSetAttribute(proj_kernel,  cudaFuncAttributeMaxDynamicSharedMemorySize, SMEM_BYTES);
    cudaFuncSetAttribute(score_kernel, cudaFuncAttributeMaxDynamicSharedMemorySize, SC_SMEM);
    cudaFuncSetAttribute(dist_kernel,  cudaFuncAttributeMaxDynamicSharedMemorySize, DS_SMEM);

    build_x_kernel<<<NROWS, 256>>>(sup, qry, out);
    proj_kernel<<<(NCOL + 31) / 32, 192, SMEM_BYTES>>>(wk, wv);
    assemble_kernel<<<dim3(NT, NSEQ), 256>>>(bk, bv, gamma, beta);
    score_kernel<<<dim3(5, 5, NSUP), 256, SC_SMEM>>>(lab);
    softmax_kernel<<<(NSUP * NT + 7) / 8, 256>>>();
    dist_kernel<<<dim3(5, 9, NSUP), 256, DS_SMEM>>>(lab, out);
}

// round 14
// speedup vs baseline: 4.0454x; 1.0093x over previous
#include <cuda_runtime.h>
#include <cuda_bf16.h>
#include <math.h>
#include <stdint.h>

// ---------------------------------------------------------------------------
// Problem constants
// ---------------------------------------------------------------------------
#define SEQ    16
#define DIN    2048
#define DOUT   1128
#define NT     560          // C(16,3)
#define NSUP   5
#define NSEQ   6            // 5 support + 1 query
#define NROWS  96           // 6 seqs * 16 frames
#define NCOL   6768         // 2 (K,V) * 3 parts * 1128
#define KV_OFF 3384
#define LN_EPS 1e-5f

// proj pipeline (tf32, unchanged)
#define STAGE_F     4608
#define STAGE_B     (STAGE_F * 4)
#define SMEM_BYTES  (4 * STAGE_B)        // 73728 B

// score pipeline (bf16): A 128 rows x 80 B + B 128 rows x 80 B per stage
#define SC_STAGE_B  20480
#define SC_SMEM     (3 * SC_STAGE_B)     // 61440
#define SC_BOFF     10240

// dist pipeline (bf16): A 128 x 80 B + B 32 x 272 B per stage
#define DS_STAGE_B  18944
#define DS_SMEM     (3 * DS_STAGE_B)     // 56832
#define DS_BOFF     10240

// ---------------------------------------------------------------------------
// Scratch (device globals -- no allocation allowed)
// ---------------------------------------------------------------------------
__device__ float          g_X[NROWS * DIN];        // tf32-pre-rounded
__device__ float          g_Y[NROWS * NCOL];       // full fp32
__device__ __nv_bfloat16  g_Kb[NSEQ * NT * DOUT];  // bf16 keys (LN output)
__device__ float          g_V[NSEQ * NT * DOUT];   // fp32 values (epilogue)
__device__ __nv_bfloat16  g_Vb[NSEQ * NT * DOUT];  // bf16 values (MMA operand)
__device__ float          g_S[NSUP * NT * NT];     // fp32 scores
__device__ __nv_bfloat16  g_A[NSUP * NT * NT];     // bf16 attention weights
__device__ int            g_tup[NT * 3];

// ---------------------------------------------------------------------------
// helpers
// ---------------------------------------------------------------------------
__device__ __forceinline__ void mma_tf32(float* c, const uint32_t* a, const uint32_t* b) {
    asm volatile(
        "mma.sync.aligned.m16n8k8.row.col.f32.tf32.tf32.f32 "
        "{%0,%1,%2,%3}, {%4,%5,%6,%7}, {%8,%9}, {%0,%1,%2,%3};\n"
        : "+f"(c[0]), "+f"(c[1]), "+f"(c[2]), "+f"(c[3])
        : "r"(a[0]), "r"(a[1]), "r"(a[2]), "r"(a[3]), "r"(b[0]), "r"(b[1]));
}

__device__ __forceinline__ void mma_bf16(float* c, const uint32_t* a, const uint32_t* b) {
    asm volatile(
        "mma.sync.aligned.m16n8k16.row.col.f32.bf16.bf16.f32 "
        "{%0,%1,%2,%3}, {%4,%5,%6,%7}, {%8,%9}, {%0,%1,%2,%3};\n"
        : "+f"(c[0]), "+f"(c[1]), "+f"(c[2]), "+f"(c[3])
        : "r"(a[0]), "r"(a[1]), "r"(a[2]), "r"(a[3]), "r"(b[0]), "r"(b[1]));
}

__device__ __forceinline__ float rnd32(float f) {
    uint32_t r;
    asm("cvt.rna.tf32.f32 %0, %1;" : "=r"(r) : "f"(f));
    return __uint_as_float(r);
}

__device__ __forceinline__ uint32_t ldcvt(const uint32_t* p) {
    float f = __uint_as_float(*p);
    uint32_t r;
    asm("cvt.rna.tf32.f32 %0, %1;" : "=r"(r) : "f"(f));
    return r;
}

__device__ __forceinline__ void ldsm4(uint32_t addr, uint32_t& r0, uint32_t& r1,
                                      uint32_t& r2, uint32_t& r3) {
    asm volatile("ldmatrix.sync.aligned.m8n8.x4.shared.b16 {%0,%1,%2,%3}, [%4];"
                 : "=r"(r0), "=r"(r1), "=r"(r2), "=r"(r3) : "r"(addr));
}

__device__ __forceinline__ void ldsm4t(uint32_t addr, uint32_t& r0, uint32_t& r1,
                                       uint32_t& r2, uint32_t& r3) {
    asm volatile("ldmatrix.sync.aligned.m8n8.x4.trans.shared.b16 {%0,%1,%2,%3}, [%4];"
                 : "=r"(r0), "=r"(r1), "=r"(r2), "=r"(r3) : "r"(addr));
}

__device__ __forceinline__ void cp16(uint32_t saddr, const void* g, bool p) {
    asm volatile("cp.async.cg.shared.global [%0], [%1], 16, %2;"
                 :: "r"(saddr), "l"(g), "r"(p ? 16 : 0));
}
#define CP_COMMIT()  asm volatile("cp.async.commit_group;")
#define CP_WAIT1()   asm volatile("cp.async.wait_group 1;")
#define CP_WAIT2()   asm volatile("cp.async.wait_group 2;")

// ---------------------------------------------------------------------------
// Kernel 1: X = input + positional encoding (tf32 pre-rounded).
// ---------------------------------------------------------------------------
__global__ void build_x_kernel(const float* __restrict__ sup,
                               const float* __restrict__ qry,
                               float* __restrict__ out) {
    int r   = blockIdx.x;
    int tid = threadIdx.x;
    if (r == 0) {
        if (tid == 0) {
            int idx = 0;
            for (int i = 0; i < SEQ; i++)
                for (int j = i + 1; j < SEQ; j++)
                    for (int k = j + 1; k < SEQ; k++) {
                        g_tup[idx * 3 + 0] = i;
                        g_tup[idx * 3 + 1] = j;
                        g_tup[idx * 3 + 2] = k;
                        idx++;
                    }
        }
        if (tid < NSUP) out[tid] = 0.0f;
    }
    int f   = (r < 80) ? (r & 15) : (r - 80);
    const float* src = (r < 80) ? (sup + r * DIN) : (qry + (r - 80) * DIN);
    const float cexp = -logf(10000.0f) / (float)DIN;
    for (int j = tid; j < DIN / 2; j += blockDim.x) {
        float div = expf((float)(2 * j) * cexp);
        float ang = (float)f * div;
        g_X[r * DIN + 2 * j]     = rnd32(src[2 * j]     + 0.1f * sinf(ang));
        g_X[r * DIN + 2 * j + 1] = rnd32(src[2 * j + 1] + 0.1f * cosf(ang));
    }
}

// ---------------------------------------------------------------------------
// Kernel 2: Y[96,6768] = X[96,2048] @ W^T.  tf32 MMA (unchanged).
// ---------------------------------------------------------------------------
__global__ void __launch_bounds__(192) proj_kernel(const float* __restrict__ wk,
                                                   const float* __restrict__ wv) {
    extern __shared__ float smem[];
    uint32_t sbase = (uint32_t)__cvta_generic_to_shared(smem);
    const uint32_t* S = (const uint32_t*)smem;

    int tid  = threadIdx.x;
    int lane = tid & 31;
    int wid  = tid >> 5;
    int g    = lane >> 2;
    int tg   = lane & 3;
    int n0   = blockIdx.x * 32;

    const float* gb[6]; uint32_t so[6]; bool ex[6]; bool sok[6];
#pragma unroll
    for (int l = 0; l < 6; l++) {
        int idx = tid + l * 192;
        ex[l] = idx < 1024;
        gb[l] = g_X; so[l] = 0; sok[l] = false;
        if (!ex[l]) continue;
        if (idx < 768) {
            int r = idx >> 3, q = idx & 7;
            gb[l]  = g_X + r * DIN + 4 * q;
            so[l]  = r * 144 + q * 16;
            sok[l] = true;
        } else {
            int j = idx - 768;
            int r = j >> 3, q = j & 7;
            int cg = n0 + r;
            so[l] = 13824 + r * 144 + q * 16;
            if (cg < NCOL) {
                const float* base; int p, rr;
                if (cg < KV_OFF) { p = cg / DOUT; rr = cg - p * DOUT; base = wk; }
                else             { int c2 = cg - KV_OFF; p = c2 / DOUT; rr = c2 - p * DOUT; base = wv; }
                gb[l]  = base + rr * (3 * DIN) + p * DIN + 4 * q;
                sok[l] = true;
            }
        }
    }

    float acc[4][4];
#pragma unroll
    for (int nr = 0; nr < 4; nr++)
#pragma unroll
        for (int e = 0; e < 4; e++) acc[nr][e] = 0.0f;

    const int NKT = DIN / 32;   // 64
#pragma unroll
    for (int p = 0; p < 3; p++) {
        int k0 = p * 32;
        uint32_t boff = p * STAGE_B;
#pragma unroll
        for (int l = 0; l < 6; l++)
            if (ex[l]) cp16(sbase + boff + so[l], gb[l] + k0, sok[l]);
        CP_COMMIT();
    }

    for (int kt = 0; kt < NKT; kt++) {
        CP_WAIT2();
        __syncthreads();
        int kp = kt + 3;
        if (kp < NKT) {
            int k0 = kp * 32;
            uint32_t boff = (kp & 3) * STAGE_B;
#pragma unroll
            for (int l = 0; l < 6; l++)
                if (ex[l]) cp16(sbase + boff + so[l], gb[l] + k0, sok[l]);
        }
        CP_COMMIT();

        const uint32_t* As = S + (kt & 3) * STAGE_F;
        const uint32_t* Bs = As + 3456;
#pragma unroll
        for (int kk = 0; kk < 32; kk += 8) {
            uint32_t a[4];
            a[0] = As[(wid * 16 + g)     * 36 + kk + tg];
            a[1] = As[(wid * 16 + g + 8) * 36 + kk + tg];
            a[2] = As[(wid * 16 + g)     * 36 + kk + tg + 4];
            a[3] = As[(wid * 16 + g + 8) * 36 + kk + tg + 4];
#pragma unroll
            for (int nr = 0; nr < 4; nr++) {
                uint32_t b[2];
                b[0] = ldcvt(&Bs[(nr * 8 + g) * 36 + kk + tg]);
                b[1] = ldcvt(&Bs[(nr * 8 + g) * 36 + kk + tg + 4]);
                mma_tf32(acc[nr], a, b);
            }
        }
    }

#pragma unroll
    for (int nr = 0; nr < 4; nr++)
#pragma unroll
        for (int e = 0; e < 4; e++) {
            int row = wid * 16 + g + ((e >= 2) ? 8 : 0);
            int cg  = n0 + nr * 8 + 2 * tg + (e & 1);
            if (cg < NCOL) g_Y[row * NCOL + cg] = acc[nr][e];
        }
}

// ---------------------------------------------------------------------------
// Kernel 3: assemble per-tuple K (LN -> bf16) and V (fp32 + bf16).
// ---------------------------------------------------------------------------
__global__ void __launch_bounds__(256) assemble_kernel(const float* __restrict__ bk,
                                                       const float* __restrict__ bv,
                                                       const float* __restrict__ gamma,
                                                       const float* __restrict__ beta) {
    int t   = blockIdx.x;
    int n   = blockIdx.y;
    int tid = threadIdx.x;
    int lane = tid & 31, warp = tid >> 5;

    int i0 = g_tup[t * 3 + 0];
    int i1 = g_tup[t * 3 + 1];
    int i2 = g_tup[t * 3 + 2];
    const float* y0 = g_Y + (n * SEQ + i0) * NCOL;
    const float* y1 = g_Y + (n * SEQ + i1) * NCOL;
    const float* y2 = g_Y + (n * SEQ + i2) * NCOL;

    float kr[5];
    float s1 = 0.0f, s2 = 0.0f;
#pragma unroll
    for (int k = 0; k < 5; k++) {
        int d = tid + k * 256;
        if (k < 4 || tid < (DOUT - 1024)) {
            float v = y0[d] + y1[DOUT + d] + y2[2 * DOUT + d] + bk[d];
            kr[k] = v; s1 += v; s2 += v * v;
            float vv = y0[KV_OFF + d] + y1[KV_OFF + DOUT + d] + y2[KV_OFF + 2 * DOUT + d] + bv[d];
            g_V[(n * NT + t) * DOUT + d]  = vv;
            g_Vb[(n * NT + t) * DOUT + d] = __float2bfloat16_rn(vv);
        } else kr[k] = 0.0f;
    }
    __shared__ float r1[8], r2[8];
    __shared__ float mu_s, rs_s;
#pragma unroll
    for (int o = 16; o; o >>= 1) {
        s1 += __shfl_xor_sync(0xffffffffu, s1, o);
        s2 += __shfl_xor_sync(0xffffffffu, s2, o);
    }
    if (lane == 0) { r1[warp] = s1; r2[warp] = s2; }
    __syncthreads();
    if (tid == 0) {
        float a = 0.0f, b = 0.0f;
        for (int w = 0; w < 8; w++) { a += r1[w]; b += r2[w]; }
        float mu = a / (float)DOUT;
        float var = b / (float)DOUT - mu * mu;
        mu_s = mu;
        rs_s = rsqrtf(var + LN_EPS);
    }
    __syncthreads();
    float mu = mu_s, rs = rs_s;
#pragma unroll
    for (int k = 0; k < 5; k++) {
        int d = tid + k * 256;
        if (k < 4 || tid < (DOUT - 1024))
            g_Kb[(n * NT + t) * DOUT + d] =
                __float2bfloat16_rn((kr[k] - mu) * rs * gamma[d] + beta[d]);
    }
}

// ---------------------------------------------------------------------------
// Kernel 4: S = Kq . Kc^T * scale.  bf16 m16n8k16.  128x128 block tile,
// 512 threads (16 warps, 4x4), warp tile 32x32, BK=32, 3-stage cp.async.
// ---------------------------------------------------------------------------
__global__ void __launch_bounds__(512) score_kernel(const int* __restrict__ labels) {
    extern __shared__ float smem[];
    uint32_t sbase = (uint32_t)__cvta_generic_to_shared(smem);

    int tid  = threadIdx.x;
    int lane = tid & 31;
    int wid  = tid >> 5;
    int wm   = wid & 3;               // m block 32*wm
    int wn   = wid >> 2;              // n block 32*wn (0..3)
    int g    = lane >> 2;
    int tg   = lane & 3;

    int c  = blockIdx.z;
    int t0 = blockIdx.x * 128;
    int s0 = blockIdx.y * 128;
    int lab = labels[c];
    if (lab < 0) lab = 0; if (lab >= NSUP) lab = NSUP - 1;

    const __nv_bfloat16* Aq = g_Kb + (size_t)NSUP * NT * DOUT;
    const __nv_bfloat16* Bc = g_Kb + (size_t)lab * NT * DOUT;

    // loader: 1024 granules per stage (A 512 + B 512), 2 slots/thread
    const __nv_bfloat16* gb[2]; uint32_t so[2]; int kthr[2]; bool sok[2];
#pragma unroll
    for (int l = 0; l < 2; l++) {
        int idx = tid + l * 512;
        if (idx < 512) {
            int r = idx >> 2, q = idx & 3;
            int row = t0 + r;
            sok[l]  = row < NT;
            gb[l]   = Aq + (size_t)(sok[l] ? row : 0) * DOUT + 8 * q;
            so[l]   = r * 80 + q * 16;
            kthr[l] = DOUT - 8 * q;
        } else {
            int j = idx - 512;
            int r = j >> 2, q = j & 3;
            int row = s0 + r;
            sok[l]  = row < NT;
            gb[l]   = Bc + (size_t)(sok[l] ? row : 0) * DOUT + 8 * q;
            so[l]   = SC_BOFF + r * 80 + q * 16;
            kthr[l] = DOUT - 8 * q;
        }
    }

    uint32_t aoff0 = (uint32_t)((wm * 32 + (lane & 15)) * 80 + (lane >> 4) * 16);
    uint32_t aoff1 = aoff0 + 16 * 80;
    uint32_t boffL = (uint32_t)(SC_BOFF + (wn * 32 + (lane >> 4) * 8 + (lane & 7)) * 80
                                + ((lane >> 3) & 1) * 16);

    float acc[2][4][4];
#pragma unroll
    for (int mi = 0; mi < 2; mi++)
#pragma unroll
        for (int ni = 0; ni < 4; ni++)
#pragma unroll
            for (int e = 0; e < 4; e++) acc[mi][ni][e] = 0.0f;

    const int NKT = (DOUT + 31) / 32;   // 36
#pragma unroll
    for (int p = 0; p < 2; p++) {
        int k0 = p * 32;
        uint32_t boff = p * SC_STAGE_B;
#pragma unroll
        for (int l = 0; l < 2; l++)
            cp16(sbase + boff + so[l], gb[l] + k0, sok[l] && (k0 < kthr[l]));
        CP_COMMIT();
    }

    for (int kt = 0; kt < NKT; kt++) {
        CP_WAIT1();
        __syncthreads();
        int kp = kt + 2;
        if (kp < NKT) {
            int k0 = kp * 32;
            uint32_t boff = (kp % 3) * SC_STAGE_B;
#pragma unroll
            for (int l = 0; l < 2; l++)
                cp16(sbase + boff + so[l], gb[l] + k0, sok[l] && (k0 < kthr[l]));
        }
        CP_COMMIT();

        uint32_t stg = sbase + (kt % 3) * SC_STAGE_B;
#pragma unroll
        for (int kq = 0; kq < 2; kq++) {          // two k16 groups, +32 B each
            uint32_t koff = kq * 32;
            uint32_t a[2][4];
            ldsm4(stg + aoff0 + koff, a[0][0], a[0][1], a[0][2], a[0][3]);
            ldsm4(stg + aoff1 + koff, a[1][0], a[1][1], a[1][2], a[1][3]);
            uint32_t b[4][2];
#pragma unroll
            for (int nb = 0; nb < 2; nb++) {      // each ldsm4 covers 2 n8-tiles
                uint32_t r0, r1, r2, r3;
                ldsm4(stg + boffL + nb * (16 * 80) + koff, r0, r1, r2, r3);
                b[nb * 2 + 0][0] = r0; b[nb * 2 + 0][1] = r1;
                b[nb * 2 + 1][0] = r2; b[nb * 2 + 1][1] = r3;
            }
#pragma unroll
            for (int mi = 0; mi < 2; mi++)
#pragma unroll
                for (int ni = 0; ni < 4; ni++)
                    mma_bf16(acc[mi][ni], a[mi], b[ni]);
        }
    }

    const float scale = rsqrtf((float)DOUT);
    float* Sc = g_S + (size_t)c * NT * NT;
#pragma unroll
    for (int mi = 0; mi < 2; mi++)
#pragma unroll
        for (int ni = 0; ni < 4; ni++)
#pragma unroll
            for (int e = 0; e < 4; e++) {
                int t = t0 + wm * 32 + mi * 16 + g + ((e >= 2) ? 8 : 0);
                int s = s0 + wn * 32 + ni * 8 + 2 * tg + (e & 1);
                if (t < NT && s < NT) Sc[(size_t)t * NT + s] = acc[mi][ni][e] * scale;
            }
}

// ---------------------------------------------------------------------------
// Kernel 5: row softmax; attn written to g_A as bf16.
// ---------------------------------------------------------------------------
__global__ void __launch_bounds__(256) softmax_kernel() {
    int lane = threadIdx.x & 31;
    int row  = blockIdx.x * 8 + (threadIdx.x >> 5);
    if (row >= NSUP * NT) return;
    const float* r = g_S + (size_t)row * NT;
    __nv_bfloat16* a = g_A + (size_t)row * NT;

    float m = -1e30f;
    for (int s = lane; s < NT; s += 32) m = fmaxf(m, r[s]);
#pragma unroll
    for (int o = 16; o; o >>= 1) m = fmaxf(m, __shfl_xor_sync(0xffffffffu, m, o));
    float sum = 0.0f;
    float ev[NT / 32 + 1];
    int cnt = 0;
    for (int s = lane; s < NT; s += 32) {
        float e = expf(r[s] - m);
        ev[cnt++] = e;
        sum += e;
    }
#pragma unroll
    for (int o = 16; o; o >>= 1) sum += __shfl_xor_sync(0xffffffffu, sum, o);
    float inv = 1.0f / sum;
    cnt = 0;
    for (int s = lane; s < NT; s += 32) a[s] = __float2bfloat16_rn(ev[cnt++] * inv);
}

// ---------------------------------------------------------------------------
// Kernel 6: P = attn @ Vc (bf16), accumulate (q_v - P)^2 with fp32 Vq.
// 128(t) x 128(d) block tile, 512 threads (16 warps, 4x4), warp 32x32,
// BK=32 over s, 3-stage.  A ldmatrix, B ldmatrix.trans.
// ---------------------------------------------------------------------------
__global__ void __launch_bounds__(512) dist_kernel(const int* __restrict__ labels,
                                                   float* __restrict__ out) {
    extern __shared__ float smem[];
    __shared__ float red[16];
    uint32_t sbase = (uint32_t)__cvta_generic_to_shared(smem);

    int tid  = threadIdx.x;
    int lane = tid & 31;
    int wid  = tid >> 5;
    int wm   = wid & 3;
    int wn   = wid >> 2;              // 0..3 -> d block 32*wn
    int g    = lane >> 2;
    int tg   = lane & 3;

    int c  = blockIdx.z;
    int t0 = blockIdx.x * 128;
    int d0 = blockIdx.y * 128;
    int lab = labels[c];
    if (lab < 0) lab = 0; if (lab >= NSUP) lab = NSUP - 1;

    const __nv_bfloat16* Ag = g_A + (size_t)c * NT * NT;
    const __nv_bfloat16* Vc = g_Vb + (size_t)lab * NT * DOUT;
    const float*         Vq = g_V + (size_t)NSUP * NT * DOUT;

    // loader: A 512 granules (128 t-rows x 4), B 512 (32 s-rows x 16); 2/thread
    const __nv_bfloat16* gb[2]; uint32_t so[2]; int gstep[2]; int kthr[2]; bool sok[2];
#pragma unroll
    for (int l = 0; l < 2; l++) {
        int idx = tid + l * 512;
        if (idx < 512) {
            int r = idx >> 2, q = idx & 3;
            int row = t0 + r;
            sok[l]   = row < NT;
            gb[l]    = Ag + (size_t)(sok[l] ? row : 0) * NT + 8 * q;
            so[l]    = r * 80 + q * 16;
            gstep[l] = 1;
            kthr[l]  = NT - 8 * q;
        } else {
            int j = idx - 512;
            int r = j >> 4, q = j & 15;
            int d = d0 + 8 * q;
            sok[l]   = d < DOUT;
            gb[l]    = Vc + (size_t)r * DOUT + (sok[l] ? d : 0);
            so[l]    = DS_BOFF + r * 272 + q * 16;
            gstep[l] = DOUT;
            kthr[l]  = NT - r;
        }
    }

    uint32_t aoff0 = (uint32_t)((wm * 32 + (lane & 15)) * 80 + (lane >> 4) * 16);
    uint32_t aoff1 = aoff0 + 16 * 80;
    uint32_t boffL = (uint32_t)(DS_BOFF + (((lane >> 3) & 1) * 8 + (lane & 7)) * 272
                                + (wn * 32 + (lane >> 4) * 8) * 2);

    float acc[2][4][4];
#pragma unroll
    for (int mi = 0; mi < 2; mi++)
#pragma unroll
        for (int ni = 0; ni < 4; ni++)
#pragma unroll
            for (int e = 0; e < 4; e++) acc[mi][ni][e] = 0.0f;

    const int NKT = (NT + 31) / 32;   // 18
#pragma unroll
    for (int p = 0; p < 2; p++) {
        int k0 = p * 32;
        uint32_t boff = p * DS_STAGE_B;
#pragma unroll
        for (int l = 0; l < 2; l++)
            cp16(sbase + boff + so[l], gb[l] + (size_t)k0 * gstep[l],
                 sok[l] && (k0 < kthr[l]));
        CP_COMMIT();
    }

    for (int kt = 0; kt < NKT; kt++) {
        CP_WAIT1();
        __syncthreads();
        int kp = kt + 2;
        if (kp < NKT) {
            int k0 = kp * 32;
            uint32_t boff = (kp % 3) * DS_STAGE_B;
#pragma unroll
            for (int l = 0; l < 2; l++)
                cp16(sbase + boff + so[l], gb[l] + (size_t)k0 * gstep[l],
                     sok[l] && (k0 < kthr[l]));
        }
        CP_COMMIT();

        uint32_t stg = sbase + (kt % 3) * DS_STAGE_B;
#pragma unroll
        for (int kq = 0; kq < 2; kq++) {
            uint32_t koff  = kq * 32;          // A: +32 B along s
            uint32_t krow  = kq * 16 * 272;    // B: +16 k-rows
            uint32_t a[2][4];
            ldsm4(stg + aoff0 + koff, a[0][0], a[0][1], a[0][2], a[0][3]);
            ldsm4(stg + aoff1 + koff, a[1][0], a[1][1], a[1][2], a[1][3]);
            uint32_t b[4][2];
#pragma unroll
            for (int nb = 0; nb < 2; nb++) {
                uint32_t r0, r1, r2, r3;
                ldsm4t(stg + boffL + krow + nb * 32, r0, r1, r2, r3);
                b[nb * 2 + 0][0] = r0; b[nb * 2 + 0][1] = r1;
                b[nb * 2 + 1][0] = r2; b[nb * 2 + 1][1] = r3;
            }
#pragma unroll
            for (int mi = 0; mi < 2; mi++)
#pragma unroll
                for (int ni = 0; ni < 4; ni++)
                    mma_bf16(acc[mi][ni], a[mi], b[ni]);
        }
    }

    float loc = 0.0f;
#pragma unroll
    for (int mi = 0; mi < 2; mi++)
#pragma unroll
        for (int ni = 0; ni < 4; ni++)
#pragma unroll
            for (int e = 0; e < 4; e++) {
                int t = t0 + wm * 32 + mi * 16 + g + ((e >= 2) ? 8 : 0);
                int d = d0 + wn * 32 + ni * 8 + 2 * tg + (e & 1);
                if (t < NT && d < DOUT) {
                    float diff = Vq[(size_t)t * DOUT + d] - acc[mi][ni][e];
                    loc += diff * diff;
                }
            }
#pragma unroll
    for (int o = 16; o; o >>= 1) loc += __shfl_xor_sync(0xffffffffu, loc, o);
    if (lane == 0) red[wid] = loc;
    __syncthreads();
    if (tid == 0) {
        float tot = 0.0f;
        for (int w = 0; w < 16; w++) tot += red[w];
        atomicAdd(out + c, -tot / (float)NT);
    }
}

// ---------------------------------------------------------------------------
// Launch
// ---------------------------------------------------------------------------
extern "C" void kernel_launch(void* const* d_in, const int* in_sizes, int n_in,
                              void* d_out, int out_size) {
    const float* sup   = (const float*)d_in[0];
    const float* qry   = (const float*)d_in[1];
    const int*   lab   = (const int*)d_in[2];
    const float* wk    = (const float*)d_in[3];
    const float* bk    = (const float*)d_in[4];
    const float* wv    = (const float*)d_in[5];
    const float* bv    = (const float*)d_in[6];
    const float* gamma = (const float*)d_in[7];
    const float* beta  = (const float*)d_in[8];
    float* out = (float*)d_out;

    cudaFuncSetAttribute(proj_kernel,  cudaFuncAttributeMaxDynamicSharedMemorySize, SMEM_BYTES);
    cudaFuncSetAttribute(score_kernel, cudaFuncAttributeMaxDynamicSharedMemorySize, SC_SMEM);
    cudaFuncSetAttribute(dist_kernel,  cudaFuncAttributeMaxDynamicSharedMemorySize, DS_SMEM);

    build_x_kernel<<<NROWS, 256>>>(sup, qry, out);
    proj_kernel<<<(NCOL + 31) / 32, 192, SMEM_BYTES>>>(wk, wv);
    assemble_kernel<<<dim3(NT, NSEQ), 256>>>(bk, bv, gamma, beta);
    score_kernel<<<dim3(5, 5, NSUP), 512, SC_SMEM>>>(lab);
    softmax_kernel<<<(NSUP * NT + 7) / 8, 256>>>();
    dist_kernel<<<dim3(5, 9, NSUP), 512, DS_SMEM>>>(lab, out);
}

// round 15
// speedup vs baseline: 4.2180x; 1.0427x over previous
#include <cuda_runtime.h>
#include <cuda_bf16.h>
#include <math.h>
#include <stdint.h>

// ---------------------------------------------------------------------------
// Problem constants
// ---------------------------------------------------------------------------
#define SEQ    16
#define DIN    2048
#define DOUT   1128
#define NT     560          // C(16,3)
#define NSUP   5
#define NSEQ   6            // 5 support + 1 query
#define NROWS  96           // 6 seqs * 16 frames
#define NCOL   6768         // 2 (K,V) * 3 parts * 1128
#define KV_OFF 3384
#define LN_EPS 1e-5f

// proj pipeline (tf32, unchanged)
#define STAGE_F     4608
#define STAGE_B     (STAGE_F * 4)
#define SMEM_BYTES  (4 * STAGE_B)        // 73728 B

// score pipeline (bf16, BK=64): A 128 rows x 144 B + B 128 rows x 144 B
#define SC_STAGE_B  36864
#define SC_SMEM     (3 * SC_STAGE_B)     // 110592
#define SC_BOFF     18432

// dist pipeline (bf16, BK=64): A 128 x 144 B + B 64 x 272 B
#define DS_STAGE_B  35840
#define DS_SMEM     (3 * DS_STAGE_B)     // 107520
#define DS_BOFF     18432

// ---------------------------------------------------------------------------
// Scratch (device globals -- no allocation allowed)
// ---------------------------------------------------------------------------
__device__ float          g_X[NROWS * DIN];        // tf32-pre-rounded
__device__ float          g_Y[NROWS * NCOL];       // full fp32
__device__ __nv_bfloat16  g_Kb[NSEQ * NT * DOUT];  // bf16 keys (LN output)
__device__ float          g_V[NSEQ * NT * DOUT];   // fp32 values (epilogue)
__device__ __nv_bfloat16  g_Vb[NSEQ * NT * DOUT];  // bf16 values (MMA operand)
__device__ float          g_S[NSUP * NT * NT];     // fp32 scores
__device__ __nv_bfloat16  g_A[NSUP * NT * NT];     // bf16 attention weights
__device__ int            g_tup[NT * 3];

// ---------------------------------------------------------------------------
// helpers
// ---------------------------------------------------------------------------
__device__ __forceinline__ void mma_tf32(float* c, const uint32_t* a, const uint32_t* b) {
    asm volatile(
        "mma.sync.aligned.m16n8k8.row.col.f32.tf32.tf32.f32 "
        "{%0,%1,%2,%3}, {%4,%5,%6,%7}, {%8,%9}, {%0,%1,%2,%3};\n"
        : "+f"(c[0]), "+f"(c[1]), "+f"(c[2]), "+f"(c[3])
        : "r"(a[0]), "r"(a[1]), "r"(a[2]), "r"(a[3]), "r"(b[0]), "r"(b[1]));
}

__device__ __forceinline__ void mma_bf16(float* c, const uint32_t* a, const uint32_t* b) {
    asm volatile(
        "mma.sync.aligned.m16n8k16.row.col.f32.bf16.bf16.f32 "
        "{%0,%1,%2,%3}, {%4,%5,%6,%7}, {%8,%9}, {%0,%1,%2,%3};\n"
        : "+f"(c[0]), "+f"(c[1]), "+f"(c[2]), "+f"(c[3])
        : "r"(a[0]), "r"(a[1]), "r"(a[2]), "r"(a[3]), "r"(b[0]), "r"(b[1]));
}

__device__ __forceinline__ float rnd32(float f) {
    uint32_t r;
    asm("cvt.rna.tf32.f32 %0, %1;" : "=r"(r) : "f"(f));
    return __uint_as_float(r);
}

__device__ __forceinline__ uint32_t ldcvt(const uint32_t* p) {
    float f = __uint_as_float(*p);
    uint32_t r;
    asm("cvt.rna.tf32.f32 %0, %1;" : "=r"(r) : "f"(f));
    return r;
}

__device__ __forceinline__ void ldsm4(uint32_t addr, uint32_t& r0, uint32_t& r1,
                                      uint32_t& r2, uint32_t& r3) {
    asm volatile("ldmatrix.sync.aligned.m8n8.x4.shared.b16 {%0,%1,%2,%3}, [%4];"
                 : "=r"(r0), "=r"(r1), "=r"(r2), "=r"(r3) : "r"(addr));
}

__device__ __forceinline__ void ldsm4t(uint32_t addr, uint32_t& r0, uint32_t& r1,
                                       uint32_t& r2, uint32_t& r3) {
    asm volatile("ldmatrix.sync.aligned.m8n8.x4.trans.shared.b16 {%0,%1,%2,%3}, [%4];"
                 : "=r"(r0), "=r"(r1), "=r"(r2), "=r"(r3) : "r"(addr));
}

__device__ __forceinline__ void cp16(uint32_t saddr, const void* g, bool p) {
    asm volatile("cp.async.cg.shared.global [%0], [%1], 16, %2;"
                 :: "r"(saddr), "l"(g), "r"(p ? 16 : 0));
}
#define CP_COMMIT()  asm volatile("cp.async.commit_group;")
#define CP_WAIT1()   asm volatile("cp.async.wait_group 1;")
#define CP_WAIT2()   asm volatile("cp.async.wait_group 2;")

// ---------------------------------------------------------------------------
// Kernel 1: X = input + positional encoding (tf32 pre-rounded).
// ---------------------------------------------------------------------------
__global__ void build_x_kernel(const float* __restrict__ sup,
                               const float* __restrict__ qry,
                               float* __restrict__ out) {
    int r   = blockIdx.x;
    int tid = threadIdx.x;
    if (r == 0) {
        if (tid == 0) {
            int idx = 0;
            for (int i = 0; i < SEQ; i++)
                for (int j = i + 1; j < SEQ; j++)
                    for (int k = j + 1; k < SEQ; k++) {
                        g_tup[idx * 3 + 0] = i;
                        g_tup[idx * 3 + 1] = j;
                        g_tup[idx * 3 + 2] = k;
                        idx++;
                    }
        }
        if (tid < NSUP) out[tid] = 0.0f;
    }
    int f   = (r < 80) ? (r & 15) : (r - 80);
    const float* src = (r < 80) ? (sup + r * DIN) : (qry + (r - 80) * DIN);
    const float cexp = -logf(10000.0f) / (float)DIN;
    for (int j = tid; j < DIN / 2; j += blockDim.x) {
        float div = expf((float)(2 * j) * cexp);
        float ang = (float)f * div;
        g_X[r * DIN + 2 * j]     = rnd32(src[2 * j]     + 0.1f * sinf(ang));
        g_X[r * DIN + 2 * j + 1] = rnd32(src[2 * j + 1] + 0.1f * cosf(ang));
    }
}

// ---------------------------------------------------------------------------
// Kernel 2: Y[96,6768] = X[96,2048] @ W^T.  tf32 MMA (unchanged).
// ---------------------------------------------------------------------------
__global__ void __launch_bounds__(192) proj_kernel(const float* __restrict__ wk,
                                                   const float* __restrict__ wv) {
    extern __shared__ float smem[];
    uint32_t sbase = (uint32_t)__cvta_generic_to_shared(smem);
    const uint32_t* S = (const uint32_t*)smem;

    int tid  = threadIdx.x;
    int lane = tid & 31;
    int wid  = tid >> 5;
    int g    = lane >> 2;
    int tg   = lane & 3;
    int n0   = blockIdx.x * 32;

    const float* gb[6]; uint32_t so[6]; bool ex[6]; bool sok[6];
#pragma unroll
    for (int l = 0; l < 6; l++) {
        int idx = tid + l * 192;
        ex[l] = idx < 1024;
        gb[l] = g_X; so[l] = 0; sok[l] = false;
        if (!ex[l]) continue;
        if (idx < 768) {
            int r = idx >> 3, q = idx & 7;
            gb[l]  = g_X + r * DIN + 4 * q;
            so[l]  = r * 144 + q * 16;
            sok[l] = true;
        } else {
            int j = idx - 768;
            int r = j >> 3, q = j & 7;
            int cg = n0 + r;
            so[l] = 13824 + r * 144 + q * 16;
            if (cg < NCOL) {
                const float* base; int p, rr;
                if (cg < KV_OFF) { p = cg / DOUT; rr = cg - p * DOUT; base = wk; }
                else             { int c2 = cg - KV_OFF; p = c2 / DOUT; rr = c2 - p * DOUT; base = wv; }
                gb[l]  = base + rr * (3 * DIN) + p * DIN + 4 * q;
                sok[l] = true;
            }
        }
    }

    float acc[4][4];
#pragma unroll
    for (int nr = 0; nr < 4; nr++)
#pragma unroll
        for (int e = 0; e < 4; e++) acc[nr][e] = 0.0f;

    const int NKT = DIN / 32;   // 64
#pragma unroll
    for (int p = 0; p < 3; p++) {
        int k0 = p * 32;
        uint32_t boff = p * STAGE_B;
#pragma unroll
        for (int l = 0; l < 6; l++)
            if (ex[l]) cp16(sbase + boff + so[l], gb[l] + k0, sok[l]);
        CP_COMMIT();
    }

    for (int kt = 0; kt < NKT; kt++) {
        CP_WAIT2();
        __syncthreads();
        int kp = kt + 3;
        if (kp < NKT) {
            int k0 = kp * 32;
            uint32_t boff = (kp & 3) * STAGE_B;
#pragma unroll
            for (int l = 0; l < 6; l++)
                if (ex[l]) cp16(sbase + boff + so[l], gb[l] + k0, sok[l]);
        }
        CP_COMMIT();

        const uint32_t* As = S + (kt & 3) * STAGE_F;
        const uint32_t* Bs = As + 3456;
#pragma unroll
        for (int kk = 0; kk < 32; kk += 8) {
            uint32_t a[4];
            a[0] = As[(wid * 16 + g)     * 36 + kk + tg];
            a[1] = As[(wid * 16 + g + 8) * 36 + kk + tg];
            a[2] = As[(wid * 16 + g)     * 36 + kk + tg + 4];
            a[3] = As[(wid * 16 + g + 8) * 36 + kk + tg + 4];
#pragma unroll
            for (int nr = 0; nr < 4; nr++) {
                uint32_t b[2];
                b[0] = ldcvt(&Bs[(nr * 8 + g) * 36 + kk + tg]);
                b[1] = ldcvt(&Bs[(nr * 8 + g) * 36 + kk + tg + 4]);
                mma_tf32(acc[nr], a, b);
            }
        }
    }

#pragma unroll
    for (int nr = 0; nr < 4; nr++)
#pragma unroll
        for (int e = 0; e < 4; e++) {
            int row = wid * 16 + g + ((e >= 2) ? 8 : 0);
            int cg  = n0 + nr * 8 + 2 * tg + (e & 1);
            if (cg < NCOL) g_Y[row * NCOL + cg] = acc[nr][e];
        }
}

// ---------------------------------------------------------------------------
// Kernel 3: assemble per-tuple K (LN -> bf16) and V (fp32 + bf16).
// ---------------------------------------------------------------------------
__global__ void __launch_bounds__(256) assemble_kernel(const float* __restrict__ bk,
                                                       const float* __restrict__ bv,
                                                       const float* __restrict__ gamma,
                                                       const float* __restrict__ beta) {
    int t   = blockIdx.x;
    int n   = blockIdx.y;
    int tid = threadIdx.x;
    int lane = tid & 31, warp = tid >> 5;

    int i0 = g_tup[t * 3 + 0];
    int i1 = g_tup[t * 3 + 1];
    int i2 = g_tup[t * 3 + 2];
    const float* y0 = g_Y + (n * SEQ + i0) * NCOL;
    const float* y1 = g_Y + (n * SEQ + i1) * NCOL;
    const float* y2 = g_Y + (n * SEQ + i2) * NCOL;

    float kr[5];
    float s1 = 0.0f, s2 = 0.0f;
#pragma unroll
    for (int k = 0; k < 5; k++) {
        int d = tid + k * 256;
        if (k < 4 || tid < (DOUT - 1024)) {
            float v = y0[d] + y1[DOUT + d] + y2[2 * DOUT + d] + bk[d];
            kr[k] = v; s1 += v; s2 += v * v;
            float vv = y0[KV_OFF + d] + y1[KV_OFF + DOUT + d] + y2[KV_OFF + 2 * DOUT + d] + bv[d];
            g_V[(n * NT + t) * DOUT + d]  = vv;
            g_Vb[(n * NT + t) * DOUT + d] = __float2bfloat16_rn(vv);
        } else kr[k] = 0.0f;
    }
    __shared__ float r1[8], r2[8];
    __shared__ float mu_s, rs_s;
#pragma unroll
    for (int o = 16; o; o >>= 1) {
        s1 += __shfl_xor_sync(0xffffffffu, s1, o);
        s2 += __shfl_xor_sync(0xffffffffu, s2, o);
    }
    if (lane == 0) { r1[warp] = s1; r2[warp] = s2; }
    __syncthreads();
    if (tid == 0) {
        float a = 0.0f, b = 0.0f;
        for (int w = 0; w < 8; w++) { a += r1[w]; b += r2[w]; }
        float mu = a / (float)DOUT;
        float var = b / (float)DOUT - mu * mu;
        mu_s = mu;
        rs_s = rsqrtf(var + LN_EPS);
    }
    __syncthreads();
    float mu = mu_s, rs = rs_s;
#pragma unroll
    for (int k = 0; k < 5; k++) {
        int d = tid + k * 256;
        if (k < 4 || tid < (DOUT - 1024))
            g_Kb[(n * NT + t) * DOUT + d] =
                __float2bfloat16_rn((kr[k] - mu) * rs * gamma[d] + beta[d]);
    }
}

// ---------------------------------------------------------------------------
// Kernel 4: S = Kq . Kc^T * scale.  bf16 m16n8k16.  128x128 block tile,
// 512 threads (16 warps, 4x4), warp tile 32x32, BK=64, 3-stage cp.async.
// Row stride 144 B -- LDSM conflict-free (144/4 mod 32 = 4).
// ---------------------------------------------------------------------------
__global__ void __launch_bounds__(512) score_kernel(const int* __restrict__ labels) {
    extern __shared__ float smem[];
    uint32_t sbase = (uint32_t)__cvta_generic_to_shared(smem);

    int tid  = threadIdx.x;
    int lane = tid & 31;
    int wid  = tid >> 5;
    int wm   = wid & 3;               // m block 32*wm
    int wn   = wid >> 2;              // n block 32*wn (0..3)
    int g    = lane >> 2;
    int tg   = lane & 3;

    int c  = blockIdx.z;
    int t0 = blockIdx.x * 128;
    int s0 = blockIdx.y * 128;
    int lab = labels[c];
    if (lab < 0) lab = 0; if (lab >= NSUP) lab = NSUP - 1;

    const __nv_bfloat16* Aq = g_Kb + (size_t)NSUP * NT * DOUT;
    const __nv_bfloat16* Bc = g_Kb + (size_t)lab * NT * DOUT;

    // loader: 2048 granules per stage (A 1024 + B 1024), 4 slots/thread
    const __nv_bfloat16* gb[4]; uint32_t so[4]; int kthr[4]; bool sok[4];
#pragma unroll
    for (int l = 0; l < 4; l++) {
        int idx = tid + l * 512;
        if (idx < 1024) {
            int r = idx >> 3, q = idx & 7;
            int row = t0 + r;
            sok[l]  = row < NT;
            gb[l]   = Aq + (size_t)(sok[l] ? row : 0) * DOUT + 8 * q;
            so[l]   = r * 144 + q * 16;
            kthr[l] = DOUT - 8 * q;
        } else {
            int j = idx - 1024;
            int r = j >> 3, q = j & 7;
            int row = s0 + r;
            sok[l]  = row < NT;
            gb[l]   = Bc + (size_t)(sok[l] ? row : 0) * DOUT + 8 * q;
            so[l]   = SC_BOFF + r * 144 + q * 16;
            kthr[l] = DOUT - 8 * q;
        }
    }

    uint32_t aoff0 = (uint32_t)((wm * 32 + (lane & 15)) * 144 + (lane >> 4) * 16);
    uint32_t aoff1 = aoff0 + 16 * 144;
    uint32_t boffL = (uint32_t)(SC_BOFF + (wn * 32 + (lane >> 4) * 8 + (lane & 7)) * 144
                                + ((lane >> 3) & 1) * 16);

    float acc[2][4][4];
#pragma unroll
    for (int mi = 0; mi < 2; mi++)
#pragma unroll
        for (int ni = 0; ni < 4; ni++)
#pragma unroll
            for (int e = 0; e < 4; e++) acc[mi][ni][e] = 0.0f;

    const int NKT = (DOUT + 63) / 64;   // 18
#pragma unroll
    for (int p = 0; p < 2; p++) {
        int k0 = p * 64;
        uint32_t boff = p * SC_STAGE_B;
#pragma unroll
        for (int l = 0; l < 4; l++)
            cp16(sbase + boff + so[l], gb[l] + k0, sok[l] && (k0 < kthr[l]));
        CP_COMMIT();
    }

    for (int kt = 0; kt < NKT; kt++) {
        CP_WAIT1();
        __syncthreads();
        int kp = kt + 2;
        if (kp < NKT) {
            int k0 = kp * 64;
            uint32_t boff = (kp % 3) * SC_STAGE_B;
#pragma unroll
            for (int l = 0; l < 4; l++)
                cp16(sbase + boff + so[l], gb[l] + k0, sok[l] && (k0 < kthr[l]));
        }
        CP_COMMIT();

        uint32_t stg = sbase + (kt % 3) * SC_STAGE_B;
#pragma unroll
        for (int kq = 0; kq < 4; kq++) {          // four k16 groups, +32 B each
            uint32_t koff = kq * 32;
            uint32_t a[2][4];
            ldsm4(stg + aoff0 + koff, a[0][0], a[0][1], a[0][2], a[0][3]);
            ldsm4(stg + aoff1 + koff, a[1][0], a[1][1], a[1][2], a[1][3]);
            uint32_t b[4][2];
#pragma unroll
            for (int nb = 0; nb < 2; nb++) {      // each ldsm4 covers 2 n8-tiles
                uint32_t r0, r1, r2, r3;
                ldsm4(stg + boffL + nb * (16 * 144) + koff, r0, r1, r2, r3);
                b[nb * 2 + 0][0] = r0; b[nb * 2 + 0][1] = r1;
                b[nb * 2 + 1][0] = r2; b[nb * 2 + 1][1] = r3;
            }
#pragma unroll
            for (int mi = 0; mi < 2; mi++)
#pragma unroll
                for (int ni = 0; ni < 4; ni++)
                    mma_bf16(acc[mi][ni], a[mi], b[ni]);
        }
    }

    const float scale = rsqrtf((float)DOUT);
    float* Sc = g_S + (size_t)c * NT * NT;
#pragma unroll
    for (int mi = 0; mi < 2; mi++)
#pragma unroll
        for (int ni = 0; ni < 4; ni++)
#pragma unroll
            for (int e = 0; e < 4; e++) {
                int t = t0 + wm * 32 + mi * 16 + g + ((e >= 2) ? 8 : 0);
                int s = s0 + wn * 32 + ni * 8 + 2 * tg + (e & 1);
                if (t < NT && s < NT) Sc[(size_t)t * NT + s] = acc[mi][ni][e] * scale;
            }
}

// ---------------------------------------------------------------------------
// Kernel 5: row softmax; attn written to g_A as bf16.
// ---------------------------------------------------------------------------
__global__ void __launch_bounds__(256) softmax_kernel() {
    int lane = threadIdx.x & 31;
    int row  = blockIdx.x * 8 + (threadIdx.x >> 5);
    if (row >= NSUP * NT) return;
    const float* r = g_S + (size_t)row * NT;
    __nv_bfloat16* a = g_A + (size_t)row * NT;

    float m = -1e30f;
    for (int s = lane; s < NT; s += 32) m = fmaxf(m, r[s]);
#pragma unroll
    for (int o = 16; o; o >>= 1) m = fmaxf(m, __shfl_xor_sync(0xffffffffu, m, o));
    float sum = 0.0f;
    float ev[NT / 32 + 1];
    int cnt = 0;
    for (int s = lane; s < NT; s += 32) {
        float e = expf(r[s] - m);
        ev[cnt++] = e;
        sum += e;
    }
#pragma unroll
    for (int o = 16; o; o >>= 1) sum += __shfl_xor_sync(0xffffffffu, sum, o);
    float inv = 1.0f / sum;
    cnt = 0;
    for (int s = lane; s < NT; s += 32) a[s] = __float2bfloat16_rn(ev[cnt++] * inv);
}

// ---------------------------------------------------------------------------
// Kernel 6: P = attn @ Vc (bf16), accumulate (q_v - P)^2 with fp32 Vq.
// 128(t) x 128(d) block tile, 512 threads, warp 32x32, BK=64 over s,
// 3-stage.  A ldmatrix, B ldmatrix.trans.
// ---------------------------------------------------------------------------
__global__ void __launch_bounds__(512) dist_kernel(const int* __restrict__ labels,
                                                   float* __restrict__ out) {
    extern __shared__ float smem[];
    __shared__ float red[16];
    uint32_t sbase = (uint32_t)__cvta_generic_to_shared(smem);

    int tid  = threadIdx.x;
    int lane = tid & 31;
    int wid  = tid >> 5;
    int wm   = wid & 3;
    int wn   = wid >> 2;              // 0..3 -> d block 32*wn
    int g    = lane >> 2;
    int tg   = lane & 3;

    int c  = blockIdx.z;
    int t0 = blockIdx.x * 128;
    int d0 = blockIdx.y * 128;
    int lab = labels[c];
    if (lab < 0) lab = 0; if (lab >= NSUP) lab = NSUP - 1;

    const __nv_bfloat16* Ag = g_A + (size_t)c * NT * NT;
    const __nv_bfloat16* Vc = g_Vb + (size_t)lab * NT * DOUT;
    const float*         Vq = g_V + (size_t)NSUP * NT * DOUT;

    // loader: A 1024 granules (128 t-rows x 8), B 1024 (64 s-rows x 16); 4/thread
    const __nv_bfloat16* gb[4]; uint32_t so[4]; int gstep[4]; int kthr[4]; bool sok[4];
#pragma unroll
    for (int l = 0; l < 4; l++) {
        int idx = tid + l * 512;
        if (idx < 1024) {
            int r = idx >> 3, q = idx & 7;
            int row = t0 + r;
            sok[l]   = row < NT;
            gb[l]    = Ag + (size_t)(sok[l] ? row : 0) * NT + 8 * q;
            so[l]    = r * 144 + q * 16;
            gstep[l] = 1;
            kthr[l]  = NT - 8 * q;
        } else {
            int j = idx - 1024;
            int r = j >> 4, q = j & 15;
            int d = d0 + 8 * q;
            sok[l]   = d < DOUT;
            gb[l]    = Vc + (size_t)r * DOUT + (sok[l] ? d : 0);
            so[l]    = DS_BOFF + r * 272 + q * 16;
            gstep[l] = DOUT;
            kthr[l]  = NT - r;
        }
    }

    uint32_t aoff0 = (uint32_t)((wm * 32 + (lane & 15)) * 144 + (lane >> 4) * 16);
    uint32_t aoff1 = aoff0 + 16 * 144;
    uint32_t boffL = (uint32_t)(DS_BOFF + (((lane >> 3) & 1) * 8 + (lane & 7)) * 272
                                + (wn * 32 + (lane >> 4) * 8) * 2);

    float acc[2][4][4];
#pragma unroll
    for (int mi = 0; mi < 2; mi++)
#pragma unroll
        for (int ni = 0; ni < 4; ni++)
#pragma unroll
            for (int e = 0; e < 4; e++) acc[mi][ni][e] = 0.0f;

    const int NKT = (NT + 63) / 64;   // 9
#pragma unroll
    for (int p = 0; p < 2; p++) {
        int k0 = p * 64;
        uint32_t boff = p * DS_STAGE_B;
#pragma unroll
        for (int l = 0; l < 4; l++)
            cp16(sbase + boff + so[l], gb[l] + (size_t)k0 * gstep[l],
                 sok[l] && (k0 < kthr[l]));
        CP_COMMIT();
    }

    for (int kt = 0; kt < NKT; kt++) {
        CP_WAIT1();
        __syncthreads();
        int kp = kt + 2;
        if (kp < NKT) {
            int k0 = kp * 64;
            uint32_t boff = (kp % 3) * DS_STAGE_B;
#pragma unroll
            for (int l = 0; l < 4; l++)
                cp16(sbase + boff + so[l], gb[l] + (size_t)k0 * gstep[l],
                     sok[l] && (k0 < kthr[l]));
        }
        CP_COMMIT();

        uint32_t stg = sbase + (kt % 3) * DS_STAGE_B;
#pragma unroll
        for (int kq = 0; kq < 4; kq++) {
            uint32_t koff  = kq * 32;          // A: +32 B along s
            uint32_t krow  = kq * 16 * 272;    // B: +16 k-rows
            uint32_t a[2][4];
            ldsm4(stg + aoff0 + koff, a[0][0], a[0][1], a[0][2], a[0][3]);
            ldsm4(stg + aoff1 + koff, a[1][0], a[1][1], a[1][2], a[1][3]);
            uint32_t b[4][2];
#pragma unroll
            for (int nb = 0; nb < 2; nb++) {
                uint32_t r0, r1, r2, r3;
                ldsm4t(stg + boffL + krow + nb * 32, r0, r1, r2, r3);
                b[nb * 2 + 0][0] = r0; b[nb * 2 + 0][1] = r1;
                b[nb * 2 + 1][0] = r2; b[nb * 2 + 1][1] = r3;
            }
#pragma unroll
            for (int mi = 0; mi < 2; mi++)
#pragma unroll
                for (int ni = 0; ni < 4; ni++)
                    mma_bf16(acc[mi][ni], a[mi], b[ni]);
        }
    }

    float loc = 0.0f;
#pragma unroll
    for (int mi = 0; mi < 2; mi++)
#pragma unroll
        for (int ni = 0; ni < 4; ni++)
#pragma unroll
            for (int e = 0; e < 4; e++) {
                int t = t0 + wm * 32 + mi * 16 + g + ((e >= 2) ? 8 : 0);
                int d = d0 + wn * 32 + ni * 8 + 2 * tg + (e & 1);
                if (t < NT && d < DOUT) {
                    float diff = Vq[(size_t)t * DOUT + d] - acc[mi][ni][e];
                    loc += diff * diff;
                }
            }
#pragma unroll
    for (int o = 16; o; o >>= 1) loc += __shfl_xor_sync(0xffffffffu, loc, o);
    if (lane == 0) red[wid] = loc;
    __syncthreads();
    if (tid == 0) {
        float tot = 0.0f;
        for (int w = 0; w < 16; w++) tot += red[w];
        atomicAdd(out + c, -tot / (float)NT);
    }
}

// ---------------------------------------------------------------------------
// Launch
// ---------------------------------------------------------------------------
extern "C" void kernel_launch(void* const* d_in, const int* in_sizes, int n_in,
                              void* d_out, int out_size) {
    const float* sup   = (const float*)d_in[0];
    const float* qry   = (const float*)d_in[1];
    const int*   lab   = (const int*)d_in[2];
    const float* wk    = (const float*)d_in[3];
    const float* bk    = (const float*)d_in[4];
    const float* wv    = (const float*)d_in[5];
    const float* bv    = (const float*)d_in[6];
    const float* gamma = (const float*)d_in[7];
    const float* beta  = (const float*)d_in[8];
    float* out = (float*)d_out;

    cudaFuncSetAttribute(proj_kernel,  cudaFuncAttributeMaxDynamicSharedMemorySize, SMEM_BYTES);
    cudaFuncSetAttribute(score_kernel, cudaFuncAttributeMaxDynamicSharedMemorySize, SC_SMEM);
    cudaFuncSetAttribute(dist_kernel,  cudaFuncAttributeMaxDynamicSharedMemorySize, DS_SMEM);

    build_x_kernel<<<NROWS, 256>>>(sup, qry, out);
    proj_kernel<<<(NCOL + 31) / 32, 192, SMEM_BYTES>>>(wk, wv);
    assemble_kernel<<<dim3(NT, NSEQ), 256>>>(bk, bv, gamma, beta);
    score_kernel<<<dim3(5, 5, NSUP), 512, SC_SMEM>>>(lab);
    softmax_kernel<<<(NSUP * NT + 7) / 8, 256>>>();
    dist_kernel<<<dim3(5, 9, NSUP), 512, DS_SMEM>>>(lab, out);
}